// round 1
// baseline (speedup 1.0000x reference)
#include <cuda_runtime.h>
#include <math.h>
#include <stdint.h>

#define Nn 100000
#define Ee 300000
#define Hh 256
#define Cc 40
#define Ll 6
#define FIN 128
#define BN_EPS 1e-5f

// ---------------- device scratch (no allocations allowed) ----------------
__device__ float g_h[Nn * Hh];      // current h (also "prev")
__device__ float g_hw[Nn * Hh];     // h @ W
__device__ float g_agg[Nn * Hh];    // aggregated messages + bias
__device__ float g_xin[Nn * Hh];    // x_input (h after input fc)
__device__ float g_mix[Nn * Hh];    // weighted layer mix
__device__ float g_dinv[Nn];
__device__ int   g_deg[Nn];
__device__ int   g_cursor[Nn];
__device__ int   g_rowoff[Nn + 1];
__device__ int   g_csr_src[Ee];
__device__ float g_csr_nrm[Ee];
__device__ double g_bsum[Hh];
__device__ double g_bsq[Hh];
__device__ float g_mean[Hh];
__device__ float g_rstd[Hh];
__device__ float g_wsoft[Ll];
__device__ int   g_bsums_scan[256];   // per-block scan partials (196 used)

// ---------------- setup kernels ----------------
__global__ void k_zero_deg() {
    int i = blockIdx.x * blockDim.x + threadIdx.x;
    if (i < Nn) { g_deg[i] = 0; g_cursor[i] = 0; }
}

__global__ void k_count(const int* __restrict__ ei) {
    int e = blockIdx.x * blockDim.x + threadIdx.x;
    if (e < Ee) atomicAdd(&g_deg[ei[Ee + e]], 1);
}

__global__ void k_dinv() {
    int i = blockIdx.x * blockDim.x + threadIdx.x;
    if (i < Nn) g_dinv[i] = rsqrtf((float)(g_deg[i] + 1));  // +1 self loop
}

// exclusive scan of g_deg -> g_rowoff, 512 elems per block
__global__ void k_scan1() {
    __shared__ int s[512];
    int i = blockIdx.x * 512 + threadIdx.x;
    int v = (i < Nn) ? g_deg[i] : 0;
    s[threadIdx.x] = v;
    __syncthreads();
    int x = v;
#pragma unroll
    for (int off = 1; off < 512; off <<= 1) {
        int t = (threadIdx.x >= off) ? s[threadIdx.x - off] : 0;
        __syncthreads();
        x += t;
        s[threadIdx.x] = x;
        __syncthreads();
    }
    if (i < Nn) g_rowoff[i] = x - v;   // exclusive (pre block offset)
    if (threadIdx.x == 511) g_bsums_scan[blockIdx.x] = x;
}

__global__ void k_scan2(int nb) {
    int acc = 0;
    for (int b = 0; b < nb; b++) { int t = g_bsums_scan[b]; g_bsums_scan[b] = acc; acc += t; }
    g_rowoff[Nn] = acc;   // == Ee
}

__global__ void k_scan3() {
    int i = blockIdx.x * 512 + threadIdx.x;
    if (i < Nn) g_rowoff[i] += g_bsums_scan[blockIdx.x];
}

__global__ void k_scatter(const int* __restrict__ ei) {
    int e = blockIdx.x * blockDim.x + threadIdx.x;
    if (e < Ee) {
        int s = ei[e];
        int d = ei[Ee + e];
        int pos = g_rowoff[d] + atomicAdd(&g_cursor[d], 1);
        g_csr_src[pos] = s;
        g_csr_nrm[pos] = g_dinv[s] * g_dinv[d];
    }
}

__global__ void k_softmax_w(const float* __restrict__ rw) {
    // single thread: softmax over L=6 values
    float mx = -1e30f;
    for (int l = 0; l < Ll; l++) mx = fmaxf(mx, rw[l]);
    float s = 0.f;
    float e[Ll];
    for (int l = 0; l < Ll; l++) { e[l] = expf(rw[l] - mx); s += e[l]; }
    for (int l = 0; l < Ll; l++) g_wsoft[l] = e[l] / s;
}

__global__ void k_zero_stats() {
    int t = threadIdx.x;
    if (t < Hh) { g_bsum[t] = 0.0; g_bsq[t] = 0.0; }
}

// ---------------- fp32 tiled GEMM: C[M,Ncols] = A[M,K] @ B[K,Ncols] (+bias) ----------------
// BM=128 BN=128 BK=16, 256 threads, 8x8 microtile
__global__ void __launch_bounds__(256)
k_sgemm(const float* __restrict__ A, const float* __restrict__ B,
        const float* __restrict__ bias, float* __restrict__ C,
        float* __restrict__ C2, int M, int K, int Ncols)
{
    __shared__ float As[128][16];   // [row][k]
    __shared__ float Bs[16][128];   // [k][col]
    int tid = threadIdx.x;
    int row0 = blockIdx.x * 128;
    int col0 = blockIdx.y * 128;
    int tx = tid & 15, ty = tid >> 4;

    float acc[8][8];
#pragma unroll
    for (int i = 0; i < 8; i++)
#pragma unroll
        for (int j = 0; j < 8; j++) acc[i][j] = 0.f;

    for (int kt = 0; kt < K; kt += 16) {
#pragma unroll
        for (int l = 0; l < 2; l++) {
            int idx = tid + l * 256;
            // A: 128 rows x 16 k = 512 float4
            int arow = idx >> 2, ac = (idx & 3) * 4;
            float4 av = make_float4(0.f, 0.f, 0.f, 0.f);
            int gr = row0 + arow;
            if (gr < M) av = *reinterpret_cast<const float4*>(&A[(size_t)gr * K + kt + ac]);
            *reinterpret_cast<float4*>(&As[arow][ac]) = av;
            // B: 16 k x 128 cols
            int brow = idx >> 5, bc = (idx & 31) * 4;
            float4 bv = *reinterpret_cast<const float4*>(&B[(size_t)(kt + brow) * Ncols + col0 + bc]);
            *reinterpret_cast<float4*>(&Bs[brow][bc]) = bv;
        }
        __syncthreads();
#pragma unroll
        for (int k = 0; k < 16; k++) {
            float a[8], b[8];
#pragma unroll
            for (int i = 0; i < 4; i++) {
                a[i]     = As[ty * 4 + i][k];
                a[4 + i] = As[64 + ty * 4 + i][k];
            }
            float4 b0 = *reinterpret_cast<const float4*>(&Bs[k][tx * 4]);
            float4 b1 = *reinterpret_cast<const float4*>(&Bs[k][64 + tx * 4]);
            b[0] = b0.x; b[1] = b0.y; b[2] = b0.z; b[3] = b0.w;
            b[4] = b1.x; b[5] = b1.y; b[6] = b1.z; b[7] = b1.w;
#pragma unroll
            for (int i = 0; i < 8; i++)
#pragma unroll
                for (int j = 0; j < 8; j++) acc[i][j] += a[i] * b[j];
        }
        __syncthreads();
    }

#pragma unroll
    for (int i = 0; i < 8; i++) {
        int r = row0 + ((i < 4) ? (ty * 4 + i) : (64 + ty * 4 + (i - 4)));
        if (r >= M) continue;
#pragma unroll
        for (int jj = 0; jj < 2; jj++) {
            int c = col0 + ((jj == 0) ? (tx * 4) : (64 + tx * 4));
            float4 v;
            v.x = acc[i][jj * 4 + 0];
            v.y = acc[i][jj * 4 + 1];
            v.z = acc[i][jj * 4 + 2];
            v.w = acc[i][jj * 4 + 3];
            if (bias) {
                v.x += bias[c + 0]; v.y += bias[c + 1];
                v.z += bias[c + 2]; v.w += bias[c + 3];
            }
            *reinterpret_cast<float4*>(&C[(size_t)r * Ncols + c]) = v;
            if (C2) *reinterpret_cast<float4*>(&C2[(size_t)r * Ncols + c]) = v;
        }
    }
}

// ---------------- aggregation: agg[i] = dinv[i]^2*hw[i] + sum_e nrm*hw[src] + conv_b ----------------
// warp per node (4 nodes per warp), fused BN sum/sumsq stats
__global__ void __launch_bounds__(256)
k_aggregate(const float* __restrict__ hw, const float* __restrict__ cb)
{
    __shared__ float ssum[Hh], ssq[Hh];
    ssum[threadIdx.x] = 0.f;
    ssq[threadIdx.x] = 0.f;
    __syncthreads();

    int warp = threadIdx.x >> 5, lane = threadIdx.x & 31;
    float tsum[8], tsq[8];
#pragma unroll
    for (int k = 0; k < 8; k++) { tsum[k] = 0.f; tsq[k] = 0.f; }

    int base = (blockIdx.x * 8 + warp) * 4;
    for (int n = 0; n < 4; n++) {
        int i = base + n;
        if (i >= Nn) break;
        float di = g_dinv[i];
        float wself = di * di;
        const float* hrow = hw + (size_t)i * Hh;
        float acc[8];
#pragma unroll
        for (int k = 0; k < 8; k++) acc[k] = wself * hrow[lane + 32 * k];
        int e0 = g_rowoff[i], e1 = g_rowoff[i + 1];
        for (int e = e0; e < e1; e++) {
            int s = g_csr_src[e];
            float nr = g_csr_nrm[e];
            const float* srow = hw + (size_t)s * Hh;
#pragma unroll
            for (int k = 0; k < 8; k++) acc[k] += nr * srow[lane + 32 * k];
        }
#pragma unroll
        for (int k = 0; k < 8; k++) {
            float v = acc[k] + cb[lane + 32 * k];
            g_agg[(size_t)i * Hh + lane + 32 * k] = v;
            tsum[k] += v;
            tsq[k] += v * v;
        }
    }
#pragma unroll
    for (int k = 0; k < 8; k++) {
        atomicAdd(&ssum[lane + 32 * k], tsum[k]);
        atomicAdd(&ssq[lane + 32 * k], tsq[k]);
    }
    __syncthreads();
    atomicAdd(&g_bsum[threadIdx.x], (double)ssum[threadIdx.x]);
    atomicAdd(&g_bsq[threadIdx.x], (double)ssq[threadIdx.x]);
}

__global__ void k_stats_final() {
    int c = threadIdx.x;
    double m = g_bsum[c] / (double)Nn;
    double v = g_bsq[c] / (double)Nn - m * m;
    g_mean[c] = (float)m;
    g_rstd[c] = (float)(1.0 / sqrt(v + (double)BN_EPS));
}

// ---------------- BN + ReLU + residual + mix accumulate ----------------
__global__ void __launch_bounds__(256)
k_bnapply(const float* __restrict__ gamma, const float* __restrict__ beta,
          int layer, float prevCoef)
{
    int idx = blockIdx.x * blockDim.x + threadIdx.x;   // over Nn*64 float4
    if (idx >= Nn * (Hh / 4)) return;
    int c4 = (idx & 63);
    float4 a  = reinterpret_cast<const float4*>(g_agg)[idx];
    float4 mn = reinterpret_cast<const float4*>(g_mean)[c4];
    float4 rs = reinterpret_cast<const float4*>(g_rstd)[c4];
    float4 gm = reinterpret_cast<const float4*>(gamma)[c4];
    float4 bt = reinterpret_cast<const float4*>(beta)[c4];
    float4 xi = reinterpret_cast<const float4*>(g_xin)[idx];
    float4 hp = reinterpret_cast<const float4*>(g_h)[idx];
    float w = g_wsoft[layer];

    float4 hn;
    hn.x = fmaxf((a.x - mn.x) * rs.x * gm.x + bt.x, 0.f) + 0.2f * xi.x + prevCoef * hp.x;
    hn.y = fmaxf((a.y - mn.y) * rs.y * gm.y + bt.y, 0.f) + 0.2f * xi.y + prevCoef * hp.y;
    hn.z = fmaxf((a.z - mn.z) * rs.z * gm.z + bt.z, 0.f) + 0.2f * xi.z + prevCoef * hp.z;
    hn.w = fmaxf((a.w - mn.w) * rs.w * gm.w + bt.w, 0.f) + 0.2f * xi.w + prevCoef * hp.w;

    reinterpret_cast<float4*>(g_h)[idx] = hn;

    float4 mx;
    if (layer == 0) {
        mx.x = w * hn.x; mx.y = w * hn.y; mx.z = w * hn.z; mx.w = w * hn.w;
    } else {
        mx = reinterpret_cast<const float4*>(g_mix)[idx];
        mx.x += w * hn.x; mx.y += w * hn.y; mx.z += w * hn.z; mx.w += w * hn.w;
    }
    reinterpret_cast<float4*>(g_mix)[idx] = mx;
}

// ---------------- output: logits = mix @ out_w + out_b, then log_softmax ----------------
__global__ void __launch_bounds__(256)
k_output(const float* __restrict__ mix, const float* __restrict__ ow,
         const float* __restrict__ ob, float* __restrict__ out)
{
    __shared__ float sw[Hh * 41];   // stride 41 -> conflict-free (gcd(9,32)=1)
    __shared__ float sb[Cc];
    __shared__ float srow[8][48];
    for (int t = threadIdx.x; t < Hh * Cc; t += 256) {
        int k = t / Cc, c = t % Cc;
        sw[k * 41 + c] = ow[t];
    }
    if (threadIdx.x < Cc) sb[threadIdx.x] = ob[threadIdx.x];
    __syncthreads();

    int warp = threadIdx.x >> 5, lane = threadIdx.x & 31;
    for (int row = blockIdx.x * 8 + warp; row < Nn; row += gridDim.x * 8) {
        float m[8];
#pragma unroll
        for (int j = 0; j < 8; j++) m[j] = mix[(size_t)row * Hh + lane + 32 * j];
        for (int c = 0; c < Cc; c++) {
            float p = 0.f;
#pragma unroll
            for (int j = 0; j < 8; j++) p += m[j] * sw[(lane + 32 * j) * 41 + c];
#pragma unroll
            for (int off = 16; off > 0; off >>= 1) p += __shfl_xor_sync(0xffffffffu, p, off);
            if (lane == 0) srow[warp][c] = p + sb[c];
        }
        __syncwarp();
        float v1 = srow[warp][lane];                                   // c = lane (0..31)
        float v2 = (lane < 8) ? srow[warp][32 + lane] : -1e30f;        // c = 32+lane
        float mx = fmaxf(v1, v2);
#pragma unroll
        for (int off = 16; off > 0; off >>= 1) mx = fmaxf(mx, __shfl_xor_sync(0xffffffffu, mx, off));
        float s = expf(v1 - mx) + ((lane < 8) ? expf(v2 - mx) : 0.f);
#pragma unroll
        for (int off = 16; off > 0; off >>= 1) s += __shfl_xor_sync(0xffffffffu, s, off);
        float lse = mx + logf(s);
        out[(size_t)row * Cc + lane] = v1 - lse;
        if (lane < 8) out[(size_t)row * Cc + 32 + lane] = v2 - lse;
        __syncwarp();
    }
}

// ---------------- launch ----------------
extern "C" void kernel_launch(void* const* d_in, const int* in_sizes, int n_in,
                              void* d_out, int out_size)
{
    const float* x      = (const float*)d_in[0];
    const int*   ei     = (const int*)d_in[1];
    const float* w_in   = (const float*)d_in[2];
    const float* b_in   = (const float*)d_in[3];
    const float* conv_w = (const float*)d_in[4];
    const float* conv_b = (const float*)d_in[5];
    const float* bn_g   = (const float*)d_in[6];
    const float* bn_b   = (const float*)d_in[7];
    const float* out_w  = (const float*)d_in[8];
    const float* out_b  = (const float*)d_in[9];
    const float* res_w  = (const float*)d_in[10];
    float* out = (float*)d_out;

    (void)in_sizes; (void)n_in; (void)out_size;

    // graph setup
    k_softmax_w<<<1, 1>>>(res_w);
    k_zero_deg<<<(Nn + 255) / 256, 256>>>();
    k_count<<<(Ee + 255) / 256, 256>>>(ei);
    k_dinv<<<(Nn + 255) / 256, 256>>>();
    int nsb = (Nn + 511) / 512;   // 196
    k_scan1<<<nsb, 512>>>();
    k_scan2<<<1, 1>>>(nsb);
    k_scan3<<<nsb, 512>>>();
    k_scatter<<<(Ee + 255) / 256, 256>>>(ei);

    // device pointers to globals
    float *p_h, *p_hw, *p_xin, *p_mix;
    cudaGetSymbolAddress((void**)&p_h, g_h);
    cudaGetSymbolAddress((void**)&p_hw, g_hw);
    cudaGetSymbolAddress((void**)&p_xin, g_xin);
    cudaGetSymbolAddress((void**)&p_mix, g_mix);

    dim3 gg((Nn + 127) / 128, Hh / 128);

    // input fc: h = x @ w_in + b_in; also copy to x_input
    k_sgemm<<<gg, 256>>>(x, w_in, b_in, p_h, p_xin, Nn, FIN, Hh);

    for (int l = 0; l < Ll; l++) {
        k_sgemm<<<gg, 256>>>(p_h, conv_w + (size_t)l * Hh * Hh, nullptr, p_hw, nullptr, Nn, Hh, Hh);
        k_zero_stats<<<1, 256>>>();
        k_aggregate<<<(Nn + 31) / 32, 256>>>(p_hw, conv_b + (size_t)l * Hh);
        k_stats_final<<<1, 256>>>();
        k_bnapply<<<(Nn * (Hh / 4) + 255) / 256, 256>>>(bn_g + (size_t)l * Hh, bn_b + (size_t)l * Hh,
                                                        l, (l == 0) ? 0.0f : 0.7f);
    }

    k_output<<<1563, 256>>>(p_mix, out_w, out_b, out);
}

// round 2
// speedup vs baseline: 1.1306x; 1.1306x over previous
#include <cuda_runtime.h>
#include <math.h>
#include <stdint.h>

#define Nn 100000
#define Ee 300000
#define Hh 256
#define Cc 40
#define Ll 6
#define FIN 128
#define BN_EPS 1e-5f

// ---------------- device scratch (no allocations allowed) ----------------
__device__ float g_h[Nn * Hh];      // current h (also "prev")
__device__ float g_hw[Nn * Hh];     // h @ W
__device__ float g_agg[Nn * Hh];    // aggregated messages + bias
__device__ float g_xin[Nn * Hh];    // x_input (h after input fc)
__device__ float g_mix[Nn * Hh];    // weighted layer mix
__device__ float g_dinv[Nn];
__device__ int   g_deg[Nn];
__device__ int   g_cursor[Nn];
__device__ int   g_rowoff[Nn + 1];
__device__ int   g_csr_src[Ee];
__device__ float g_csr_nrm[Ee];
__device__ double g_bsum[Hh];
__device__ double g_bsq[Hh];
__device__ float g_mean[Hh];
__device__ float g_rstd[Hh];
__device__ float g_wsoft[Ll];
__device__ int   g_bsums_scan[256];

// ---------------- setup kernels ----------------
__global__ void k_zero_deg() {
    int i = blockIdx.x * blockDim.x + threadIdx.x;
    if (i < Nn) { g_deg[i] = 0; g_cursor[i] = 0; }
}

__global__ void k_count(const int* __restrict__ ei) {
    int e = blockIdx.x * blockDim.x + threadIdx.x;
    if (e < Ee) atomicAdd(&g_deg[ei[Ee + e]], 1);
}

__global__ void k_dinv() {
    int i = blockIdx.x * blockDim.x + threadIdx.x;
    if (i < Nn) g_dinv[i] = rsqrtf((float)(g_deg[i] + 1));  // +1 self loop
}

__global__ void k_scan1() {
    __shared__ int s[512];
    int i = blockIdx.x * 512 + threadIdx.x;
    int v = (i < Nn) ? g_deg[i] : 0;
    s[threadIdx.x] = v;
    __syncthreads();
    int x = v;
#pragma unroll
    for (int off = 1; off < 512; off <<= 1) {
        int t = (threadIdx.x >= off) ? s[threadIdx.x - off] : 0;
        __syncthreads();
        x += t;
        s[threadIdx.x] = x;
        __syncthreads();
    }
    if (i < Nn) g_rowoff[i] = x - v;
    if (threadIdx.x == 511) g_bsums_scan[blockIdx.x] = x;
}

__global__ void k_scan2(int nb) {
    int acc = 0;
    for (int b = 0; b < nb; b++) { int t = g_bsums_scan[b]; g_bsums_scan[b] = acc; acc += t; }
    g_rowoff[Nn] = acc;
}

__global__ void k_scan3() {
    int i = blockIdx.x * 512 + threadIdx.x;
    if (i < Nn) g_rowoff[i] += g_bsums_scan[blockIdx.x];
}

__global__ void k_scatter(const int* __restrict__ ei) {
    int e = blockIdx.x * blockDim.x + threadIdx.x;
    if (e < Ee) {
        int s = ei[e];
        int d = ei[Ee + e];
        int pos = g_rowoff[d] + atomicAdd(&g_cursor[d], 1);
        g_csr_src[pos] = s;
        g_csr_nrm[pos] = g_dinv[s] * g_dinv[d];
    }
}

__global__ void k_softmax_w(const float* __restrict__ rw) {
    float mx = -1e30f;
    for (int l = 0; l < Ll; l++) mx = fmaxf(mx, rw[l]);
    float s = 0.f;
    float e[Ll];
    for (int l = 0; l < Ll; l++) { e[l] = expf(rw[l] - mx); s += e[l]; }
    for (int l = 0; l < Ll; l++) g_wsoft[l] = e[l] / s;
}

__global__ void k_zero_stats() {
    int t = threadIdx.x;
    if (t < Hh) { g_bsum[t] = 0.0; g_bsq[t] = 0.0; }
}

// ---------------- 3xTF32 tensor-core GEMM ----------------
// C[M,256] = A[M,K] @ B[K,256] (+bias), optional duplicate write C2.
// BM=64, BN=256 (full width), BK=16, 256 threads (8 warps, 2x4), warp tile 32x64.
// Split-precision: v = hi + lo, hi = trunc13(v); compute hi*hi + lo*hi + hi*lo.

__device__ __forceinline__ void mma_tf32(float c[4], const uint32_t a[4], const uint32_t b[2]) {
    asm volatile(
        "mma.sync.aligned.m16n8k8.row.col.f32.tf32.tf32.f32 "
        "{%0,%1,%2,%3}, {%4,%5,%6,%7}, {%8,%9}, {%0,%1,%2,%3};\n"
        : "+f"(c[0]), "+f"(c[1]), "+f"(c[2]), "+f"(c[3])
        : "r"(a[0]), "r"(a[1]), "r"(a[2]), "r"(a[3]), "r"(b[0]), "r"(b[1]));
}

__device__ __forceinline__ float trunc_hi(float v) {
    return __uint_as_float(__float_as_uint(v) & 0xffffe000u);
}

__global__ void __launch_bounds__(256, 2)
k_gemm_tf32(const float* __restrict__ A, const float* __restrict__ B,
            const float* __restrict__ bias, float* __restrict__ C,
            float* __restrict__ C2, int M, int K)
{
    const int N = 256;
    __shared__ float As_hi[16][72];    // [k][m], stride 72 (%32==8 -> conflict-free frag loads)
    __shared__ float As_lo[16][72];
    __shared__ float Bs_hi[16][264];   // [k][n], stride 264 (%32==8)
    __shared__ float Bs_lo[16][264];

    int tid = threadIdx.x;
    int lane = tid & 31, wid = tid >> 5;
    int wm = wid >> 2, wn = wid & 3;       // warp grid 2 x 4
    int g = lane >> 2, tig = lane & 3;
    int row0 = blockIdx.x * 64;

    float c[2][8][4];
#pragma unroll
    for (int t = 0; t < 2; t++)
#pragma unroll
        for (int u = 0; u < 8; u++)
#pragma unroll
            for (int j = 0; j < 4; j++) c[t][u][j] = 0.f;

    int arow = tid >> 2;             // 0..63
    int acol = (tid & 3) * 4;        // 0,4,8,12
    int brow = tid >> 4;             // 0..15
    int bcol = (tid & 15) * 4;       // 0..60

    for (int kt = 0; kt < K; kt += 16) {
        // ---- stage A tile (64 x 16), transposed into [k][m] ----
        float4 av = make_float4(0.f, 0.f, 0.f, 0.f);
        if (row0 + arow < M)
            av = *reinterpret_cast<const float4*>(&A[(size_t)(row0 + arow) * K + kt + acol]);
        {
            float vv[4] = {av.x, av.y, av.z, av.w};
#pragma unroll
            for (int j = 0; j < 4; j++) {
                float hi = trunc_hi(vv[j]);
                As_hi[acol + j][arow] = hi;
                As_lo[acol + j][arow] = vv[j] - hi;
            }
        }
        // ---- stage B tile (16 x 256) ----
#pragma unroll
        for (int cc = 0; cc < 4; cc++) {
            float4 bv = *reinterpret_cast<const float4*>(&B[(size_t)(kt + brow) * N + cc * 64 + bcol]);
            float4 hv, lv;
            hv.x = trunc_hi(bv.x); lv.x = bv.x - hv.x;
            hv.y = trunc_hi(bv.y); lv.y = bv.y - hv.y;
            hv.z = trunc_hi(bv.z); lv.z = bv.z - hv.z;
            hv.w = trunc_hi(bv.w); lv.w = bv.w - hv.w;
            *reinterpret_cast<float4*>(&Bs_hi[brow][cc * 64 + bcol]) = hv;
            *reinterpret_cast<float4*>(&Bs_lo[brow][cc * 64 + bcol]) = lv;
        }
        __syncthreads();

#pragma unroll
        for (int k8 = 0; k8 < 16; k8 += 8) {
            uint32_t ah[2][4], al[2][4];
#pragma unroll
            for (int t = 0; t < 2; t++) {
                int mb = wm * 32 + t * 16;
                ah[t][0] = __float_as_uint(As_hi[k8 + tig][mb + g]);
                ah[t][1] = __float_as_uint(As_hi[k8 + tig][mb + g + 8]);
                ah[t][2] = __float_as_uint(As_hi[k8 + tig + 4][mb + g]);
                ah[t][3] = __float_as_uint(As_hi[k8 + tig + 4][mb + g + 8]);
                al[t][0] = __float_as_uint(As_lo[k8 + tig][mb + g]);
                al[t][1] = __float_as_uint(As_lo[k8 + tig][mb + g + 8]);
                al[t][2] = __float_as_uint(As_lo[k8 + tig + 4][mb + g]);
                al[t][3] = __float_as_uint(As_lo[k8 + tig + 4][mb + g + 8]);
            }
            uint32_t b[8][2];
            // hi B: accumulate ah*bh + al*bh
#pragma unroll
            for (int u = 0; u < 8; u++) {
                int nb = wn * 64 + u * 8 + g;
                b[u][0] = __float_as_uint(Bs_hi[k8 + tig][nb]);
                b[u][1] = __float_as_uint(Bs_hi[k8 + tig + 4][nb]);
            }
#pragma unroll
            for (int t = 0; t < 2; t++)
#pragma unroll
                for (int u = 0; u < 8; u++) {
                    mma_tf32(c[t][u], ah[t], b[u]);
                    mma_tf32(c[t][u], al[t], b[u]);
                }
            // lo B: accumulate ah*bl
#pragma unroll
            for (int u = 0; u < 8; u++) {
                int nb = wn * 64 + u * 8 + g;
                b[u][0] = __float_as_uint(Bs_lo[k8 + tig][nb]);
                b[u][1] = __float_as_uint(Bs_lo[k8 + tig + 4][nb]);
            }
#pragma unroll
            for (int t = 0; t < 2; t++)
#pragma unroll
                for (int u = 0; u < 8; u++)
                    mma_tf32(c[t][u], ah[t], b[u]);
        }
        __syncthreads();
    }

    // ---- epilogue ----
#pragma unroll
    for (int t = 0; t < 2; t++) {
        int r0 = row0 + wm * 32 + t * 16 + g;
        int r1 = r0 + 8;
#pragma unroll
        for (int u = 0; u < 8; u++) {
            int col = wn * 64 + u * 8 + 2 * tig;
            float2 v0 = make_float2(c[t][u][0], c[t][u][1]);
            float2 v1 = make_float2(c[t][u][2], c[t][u][3]);
            if (bias) {
                float b0 = bias[col], b1 = bias[col + 1];
                v0.x += b0; v0.y += b1;
                v1.x += b0; v1.y += b1;
            }
            if (r0 < M) {
                *reinterpret_cast<float2*>(&C[(size_t)r0 * N + col]) = v0;
                if (C2) *reinterpret_cast<float2*>(&C2[(size_t)r0 * N + col]) = v0;
            }
            if (r1 < M) {
                *reinterpret_cast<float2*>(&C[(size_t)r1 * N + col]) = v1;
                if (C2) *reinterpret_cast<float2*>(&C2[(size_t)r1 * N + col]) = v1;
            }
        }
    }
}

// ---------------- aggregation + fused BN stats ----------------
__global__ void __launch_bounds__(256)
k_aggregate(const float* __restrict__ hw, const float* __restrict__ cb)
{
    __shared__ float ssum[Hh], ssq[Hh];
    ssum[threadIdx.x] = 0.f;
    ssq[threadIdx.x] = 0.f;
    __syncthreads();

    int warp = threadIdx.x >> 5, lane = threadIdx.x & 31;
    float tsum[8], tsq[8];
#pragma unroll
    for (int k = 0; k < 8; k++) { tsum[k] = 0.f; tsq[k] = 0.f; }

    int base = (blockIdx.x * 8 + warp) * 4;
    for (int n = 0; n < 4; n++) {
        int i = base + n;
        if (i >= Nn) break;
        float di = g_dinv[i];
        float wself = di * di;
        const float* hrow = hw + (size_t)i * Hh;
        float acc[8];
#pragma unroll
        for (int k = 0; k < 8; k++) acc[k] = wself * hrow[lane + 32 * k];
        int e0 = g_rowoff[i], e1 = g_rowoff[i + 1];
        for (int e = e0; e < e1; e++) {
            int s = g_csr_src[e];
            float nr = g_csr_nrm[e];
            const float* srow = hw + (size_t)s * Hh;
#pragma unroll
            for (int k = 0; k < 8; k++) acc[k] += nr * srow[lane + 32 * k];
        }
#pragma unroll
        for (int k = 0; k < 8; k++) {
            float v = acc[k] + cb[lane + 32 * k];
            g_agg[(size_t)i * Hh + lane + 32 * k] = v;
            tsum[k] += v;
            tsq[k] += v * v;
        }
    }
#pragma unroll
    for (int k = 0; k < 8; k++) {
        atomicAdd(&ssum[lane + 32 * k], tsum[k]);
        atomicAdd(&ssq[lane + 32 * k], tsq[k]);
    }
    __syncthreads();
    atomicAdd(&g_bsum[threadIdx.x], (double)ssum[threadIdx.x]);
    atomicAdd(&g_bsq[threadIdx.x], (double)ssq[threadIdx.x]);
}

__global__ void k_stats_final() {
    int c = threadIdx.x;
    double m = g_bsum[c] / (double)Nn;
    double v = g_bsq[c] / (double)Nn - m * m;
    g_mean[c] = (float)m;
    g_rstd[c] = (float)(1.0 / sqrt(v + (double)BN_EPS));
}

// ---------------- BN + ReLU + residual + mix accumulate ----------------
__global__ void __launch_bounds__(256)
k_bnapply(const float* __restrict__ gamma, const float* __restrict__ beta,
          int layer, float prevCoef)
{
    int idx = blockIdx.x * blockDim.x + threadIdx.x;
    if (idx >= Nn * (Hh / 4)) return;
    int c4 = (idx & 63);
    float4 a  = reinterpret_cast<const float4*>(g_agg)[idx];
    float4 mn = reinterpret_cast<const float4*>(g_mean)[c4];
    float4 rs = reinterpret_cast<const float4*>(g_rstd)[c4];
    float4 gm = reinterpret_cast<const float4*>(gamma)[c4];
    float4 bt = reinterpret_cast<const float4*>(beta)[c4];
    float4 xi = reinterpret_cast<const float4*>(g_xin)[idx];
    float4 hp = reinterpret_cast<const float4*>(g_h)[idx];
    float w = g_wsoft[layer];

    float4 hn;
    hn.x = fmaxf((a.x - mn.x) * rs.x * gm.x + bt.x, 0.f) + 0.2f * xi.x + prevCoef * hp.x;
    hn.y = fmaxf((a.y - mn.y) * rs.y * gm.y + bt.y, 0.f) + 0.2f * xi.y + prevCoef * hp.y;
    hn.z = fmaxf((a.z - mn.z) * rs.z * gm.z + bt.z, 0.f) + 0.2f * xi.z + prevCoef * hp.z;
    hn.w = fmaxf((a.w - mn.w) * rs.w * gm.w + bt.w, 0.f) + 0.2f * xi.w + prevCoef * hp.w;

    reinterpret_cast<float4*>(g_h)[idx] = hn;

    float4 mx;
    if (layer == 0) {
        mx.x = w * hn.x; mx.y = w * hn.y; mx.z = w * hn.z; mx.w = w * hn.w;
    } else {
        mx = reinterpret_cast<const float4*>(g_mix)[idx];
        mx.x += w * hn.x; mx.y += w * hn.y; mx.z += w * hn.z; mx.w += w * hn.w;
    }
    reinterpret_cast<float4*>(g_mix)[idx] = mx;
}

// ---------------- output: logits = mix @ out_w + out_b, then log_softmax ----------------
__global__ void __launch_bounds__(256)
k_output(const float* __restrict__ mix, const float* __restrict__ ow,
         const float* __restrict__ ob, float* __restrict__ out)
{
    __shared__ float sw[Hh * 41];
    __shared__ float sb[Cc];
    __shared__ float srow[8][48];
    for (int t = threadIdx.x; t < Hh * Cc; t += 256) {
        int k = t / Cc, c = t % Cc;
        sw[k * 41 + c] = ow[t];
    }
    if (threadIdx.x < Cc) sb[threadIdx.x] = ob[threadIdx.x];
    __syncthreads();

    int warp = threadIdx.x >> 5, lane = threadIdx.x & 31;
    for (int row = blockIdx.x * 8 + warp; row < Nn; row += gridDim.x * 8) {
        float m[8];
#pragma unroll
        for (int j = 0; j < 8; j++) m[j] = mix[(size_t)row * Hh + lane + 32 * j];
        for (int c = 0; c < Cc; c++) {
            float p = 0.f;
#pragma unroll
            for (int j = 0; j < 8; j++) p += m[j] * sw[(lane + 32 * j) * 41 + c];
#pragma unroll
            for (int off = 16; off > 0; off >>= 1) p += __shfl_xor_sync(0xffffffffu, p, off);
            if (lane == 0) srow[warp][c] = p + sb[c];
        }
        __syncwarp();
        float v1 = srow[warp][lane];
        float v2 = (lane < 8) ? srow[warp][32 + lane] : -1e30f;
        float mx = fmaxf(v1, v2);
#pragma unroll
        for (int off = 16; off > 0; off >>= 1) mx = fmaxf(mx, __shfl_xor_sync(0xffffffffu, mx, off));
        float s = expf(v1 - mx) + ((lane < 8) ? expf(v2 - mx) : 0.f);
#pragma unroll
        for (int off = 16; off > 0; off >>= 1) s += __shfl_xor_sync(0xffffffffu, s, off);
        float lse = mx + logf(s);
        out[(size_t)row * Cc + lane] = v1 - lse;
        if (lane < 8) out[(size_t)row * Cc + 32 + lane] = v2 - lse;
        __syncwarp();
    }
}

// ---------------- launch ----------------
extern "C" void kernel_launch(void* const* d_in, const int* in_sizes, int n_in,
                              void* d_out, int out_size)
{
    const float* x      = (const float*)d_in[0];
    const int*   ei     = (const int*)d_in[1];
    const float* w_in   = (const float*)d_in[2];
    const float* b_in   = (const float*)d_in[3];
    const float* conv_w = (const float*)d_in[4];
    const float* conv_b = (const float*)d_in[5];
    const float* bn_g   = (const float*)d_in[6];
    const float* bn_b   = (const float*)d_in[7];
    const float* out_w  = (const float*)d_in[8];
    const float* out_b  = (const float*)d_in[9];
    const float* res_w  = (const float*)d_in[10];
    float* out = (float*)d_out;

    (void)in_sizes; (void)n_in; (void)out_size;

    k_softmax_w<<<1, 1>>>(res_w);
    k_zero_deg<<<(Nn + 255) / 256, 256>>>();
    k_count<<<(Ee + 255) / 256, 256>>>(ei);
    k_dinv<<<(Nn + 255) / 256, 256>>>();
    int nsb = (Nn + 511) / 512;
    k_scan1<<<nsb, 512>>>();
    k_scan2<<<1, 1>>>(nsb);
    k_scan3<<<nsb, 512>>>();
    k_scatter<<<(Ee + 255) / 256, 256>>>(ei);

    float *p_h, *p_hw, *p_xin, *p_mix;
    cudaGetSymbolAddress((void**)&p_h, g_h);
    cudaGetSymbolAddress((void**)&p_hw, g_hw);
    cudaGetSymbolAddress((void**)&p_xin, g_xin);
    cudaGetSymbolAddress((void**)&p_mix, g_mix);

    int gblocks = (Nn + 63) / 64;   // 1563

    // input fc: h = x @ w_in + b_in; duplicate to x_input
    k_gemm_tf32<<<gblocks, 256>>>(x, w_in, b_in, p_h, p_xin, Nn, FIN);

    for (int l = 0; l < Ll; l++) {
        k_gemm_tf32<<<gblocks, 256>>>(p_h, conv_w + (size_t)l * Hh * Hh, nullptr, p_hw, nullptr, Nn, Hh);
        k_zero_stats<<<1, 256>>>();
        k_aggregate<<<(Nn + 31) / 32, 256>>>(p_hw, conv_b + (size_t)l * Hh);
        k_stats_final<<<1, 256>>>();
        k_bnapply<<<(Nn * (Hh / 4) + 255) / 256, 256>>>(bn_g + (size_t)l * Hh, bn_b + (size_t)l * Hh,
                                                        l, (l == 0) ? 0.0f : 0.7f);
    }

    k_output<<<1563, 256>>>(p_mix, out_w, out_b, out);
}

// round 4
// speedup vs baseline: 1.4266x; 1.2618x over previous
#include <cuda_runtime.h>
#include <cuda_bf16.h>
#include <math.h>
#include <stdint.h>

#define Nn 100000
#define Ee 300000
#define Hh 256
#define Cc 40
#define Ll 6
#define FIN 128
#define BN_EPS 1e-5f

// ---------------- device scratch ----------------
__device__ float g_h[Nn * Hh];      // current h fp32 (prev for residual)
__device__ float g_hw[Nn * Hh];     // h @ W
__device__ float g_agg[Nn * Hh];
__device__ float g_xin[Nn * Hh];
__device__ float g_mix[Nn * Hh];
__device__ __nv_bfloat16 g_ahi[Nn * Hh];   // bf16 split of current h (GEMM A)
__device__ __nv_bfloat16 g_alo[Nn * Hh];
__device__ __nv_bfloat16 g_xhi[Nn * FIN];  // bf16 split of x
__device__ __nv_bfloat16 g_xlo[Nn * FIN];
// transposed split weights: input fc (256x128) then 6 conv (256x256)
#define BT_IN_OFF 0
#define BT_CONV_OFF (Hh * FIN)
__device__ __nv_bfloat16 g_bthi[Hh * FIN + Ll * Hh * Hh];
__device__ __nv_bfloat16 g_btlo[Hh * FIN + Ll * Hh * Hh];
__device__ float g_dinv[Nn];
__device__ int   g_deg[Nn];
__device__ int   g_cursor[Nn];
__device__ int   g_rowoff[Nn + 1];
__device__ int   g_csr_src[Ee];
__device__ float g_csr_nrm[Ee];
__device__ double g_bsum[Hh];
__device__ double g_bsq[Hh];
__device__ float g_mean[Hh];
__device__ float g_rstd[Hh];
__device__ float g_wsoft[Ll];
__device__ int   g_bsums_scan[256];

// ---------------- helpers ----------------
__device__ __forceinline__ uint32_t smem_u32(const void* p) {
    uint32_t a;
    asm("{ .reg .u64 t; cvta.to.shared.u64 t, %1; cvt.u32.u64 %0, t; }" : "=r"(a) : "l"(p));
    return a;
}
__device__ __forceinline__ void cpasync16(uint32_t dst, const void* src, int szbytes) {
    asm volatile("cp.async.cg.shared.global [%0], [%1], 16, %2;"
                 :: "r"(dst), "l"(src), "r"(szbytes) : "memory");
}
#define CP_COMMIT() asm volatile("cp.async.commit_group;" ::: "memory")
#define CP_WAIT(n)  asm volatile("cp.async.wait_group %0;" :: "n"(n) : "memory")

__device__ __forceinline__ void ldsm4(uint32_t& r0, uint32_t& r1, uint32_t& r2, uint32_t& r3, uint32_t addr) {
    asm volatile("ldmatrix.sync.aligned.m8n8.x4.shared.b16 {%0,%1,%2,%3}, [%4];"
                 : "=r"(r0), "=r"(r1), "=r"(r2), "=r"(r3) : "r"(addr));
}
__device__ __forceinline__ void mma_bf16(float c[4], const uint32_t a[4], uint32_t b0, uint32_t b1) {
    asm volatile("mma.sync.aligned.m16n8k16.row.col.f32.bf16.bf16.f32 "
                 "{%0,%1,%2,%3}, {%4,%5,%6,%7}, {%8,%9}, {%0,%1,%2,%3};"
                 : "+f"(c[0]), "+f"(c[1]), "+f"(c[2]), "+f"(c[3])
                 : "r"(a[0]), "r"(a[1]), "r"(a[2]), "r"(a[3]), "r"(b0), "r"(b1));
}
__device__ __forceinline__ uint32_t bf2_pack(__nv_bfloat16 a, __nv_bfloat16 b) {
    __nv_bfloat162 t;
    t.x = a; t.y = b;
    return *reinterpret_cast<uint32_t*>(&t);
}
__device__ __forceinline__ void split_pair(float v0, float v1, uint32_t& hi, uint32_t& lo) {
    __nv_bfloat16 h0 = __float2bfloat16(v0), h1 = __float2bfloat16(v1);
    __nv_bfloat16 l0 = __float2bfloat16(v0 - __bfloat162float(h0));
    __nv_bfloat16 l1 = __float2bfloat16(v1 - __bfloat162float(h1));
    hi = bf2_pack(h0, h1);
    lo = bf2_pack(l0, l1);
}

// ---------------- bf16 split GEMM: C[M,256] = A[M,K] @ B[K,256] ----------------
// A given as bf16 hi/lo [M,K]; B as transposed bf16 hi/lo [256,K] (K-major).
// BM=128, BN=256, BK=64, 512 threads (16 warps, 4x4), warp tile 32x64.
// smem per stage: Ahi 16K | Alo 16K | Bhi 32K | Blo 32K = 96KB; 2 stages = 192KB.
#define ST_SZ   98304
#define SM_ALO  16384
#define SM_BHI  32768
#define SM_BLO  65536
#define SMEM_DYN (2 * ST_SZ)

__global__ void __launch_bounds__(512, 1)
k_gemm(const __nv_bfloat16* __restrict__ Ahi, const __nv_bfloat16* __restrict__ Alo,
       const __nv_bfloat16* __restrict__ Bhi, const __nv_bfloat16* __restrict__ Blo,
       const float* __restrict__ bias, float* __restrict__ C, float* __restrict__ C2,
       __nv_bfloat16* __restrict__ Chi, __nv_bfloat16* __restrict__ Clo,
       int M, int K)
{
    extern __shared__ char smem[];
    uint32_t sb = smem_u32(smem);
    int tid = threadIdx.x;
    int lane = tid & 31, wid = tid >> 5;
    int wm = wid >> 2, wn = wid & 3;
    int row0 = blockIdx.x * 128;
    int nc = K >> 6;   // chunks of 64

    const char* AhiC = (const char*)Ahi;
    const char* AloC = (const char*)Alo;
    const char* BhiC = (const char*)Bhi;
    const char* BloC = (const char*)Blo;

    float c[2][8][4];
#pragma unroll
    for (int mt = 0; mt < 2; mt++)
#pragma unroll
        for (int nt = 0; nt < 8; nt++)
#pragma unroll
            for (int j = 0; j < 4; j++) c[mt][nt][j] = 0.f;

    auto stage_load = [&](int s, int kc) {
        uint32_t so = sb + s * ST_SZ;
        // A tiles: 128 rows x 64 cols bf16 -> 1024 16B chunks per split
#pragma unroll
        for (int j = 0; j < 2; j++) {
            int flat = tid + j * 512;
            int row = flat >> 3, cq = flat & 7;
            int grow = row0 + row;
            int sz = (grow < M) ? 16 : 0;
            int gc = (grow < M) ? grow : (M - 1);
            size_t srcoff = ((size_t)gc * K + kc * 64 + cq * 8) * 2;
            uint32_t dst = so + row * 128 + ((cq ^ (row & 7)) << 4);
            cpasync16(dst, AhiC + srcoff, sz);
            cpasync16(dst + SM_ALO, AloC + srcoff, sz);
        }
        // B tiles: 256 rows x 64 cols bf16 -> 2048 chunks per split
#pragma unroll
        for (int j = 0; j < 4; j++) {
            int flat = tid + j * 512;
            int n = flat >> 3, cq = flat & 7;
            size_t srcoff = ((size_t)n * K + kc * 64 + cq * 8) * 2;
            uint32_t dst = so + SM_BHI + n * 128 + ((cq ^ (n & 7)) << 4);
            cpasync16(dst, BhiC + srcoff, 16);
            cpasync16(dst + 32768, BloC + srcoff, 16);
        }
    };

    stage_load(0, 0);
    CP_COMMIT();

    for (int kc = 0; kc < nc; kc++) {
        if (kc + 1 < nc) {
            stage_load((kc + 1) & 1, kc + 1);
            CP_COMMIT();
            CP_WAIT(1);
        } else {
            CP_WAIT(0);
        }
        __syncthreads();

        uint32_t so = sb + (kc & 1) * ST_SZ;
#pragma unroll
        for (int ks = 0; ks < 4; ks++) {
            uint32_t ah[2][4], al[2][4];
#pragma unroll
            for (int mt = 0; mt < 2; mt++) {
                int ml = wm * 32 + mt * 16 + (lane & 7) + ((lane >> 3) & 1) * 8;
                int ck = 2 * ks + (lane >> 4);
                uint32_t ab = so + ml * 128 + ((ck ^ (ml & 7)) << 4);
                ldsm4(ah[mt][0], ah[mt][1], ah[mt][2], ah[mt][3], ab);
                ldsm4(al[mt][0], al[mt][1], al[mt][2], al[mt][3], ab + SM_ALO);
            }
#pragma unroll
            for (int np = 0; np < 4; np++) {
                int nl = wn * 64 + np * 16 + (lane & 7) + ((lane >> 4) << 3);
                int ck = 2 * ks + ((lane >> 3) & 1);
                uint32_t bb = so + SM_BHI + nl * 128 + ((ck ^ (nl & 7)) << 4);
                uint32_t bh[4], bl[4];
                ldsm4(bh[0], bh[1], bh[2], bh[3], bb);
                ldsm4(bl[0], bl[1], bl[2], bl[3], bb + 32768);
#pragma unroll
                for (int mt = 0; mt < 2; mt++) {
                    mma_bf16(c[mt][np * 2 + 0], ah[mt], bh[0], bh[1]);
                    mma_bf16(c[mt][np * 2 + 0], al[mt], bh[0], bh[1]);
                    mma_bf16(c[mt][np * 2 + 0], ah[mt], bl[0], bl[1]);
                    mma_bf16(c[mt][np * 2 + 1], ah[mt], bh[2], bh[3]);
                    mma_bf16(c[mt][np * 2 + 1], al[mt], bh[2], bh[3]);
                    mma_bf16(c[mt][np * 2 + 1], ah[mt], bl[2], bl[3]);
                }
            }
        }
        __syncthreads();
    }

    // epilogue
#pragma unroll
    for (int mt = 0; mt < 2; mt++) {
        int r = row0 + wm * 32 + mt * 16 + (lane >> 2);
#pragma unroll
        for (int nt = 0; nt < 8; nt++) {
            int col = wn * 64 + nt * 8 + ((lane & 3) << 1);
            float v0 = c[mt][nt][0], v1 = c[mt][nt][1];
            float v2 = c[mt][nt][2], v3 = c[mt][nt][3];
            if (bias) {
                float b0 = bias[col], b1 = bias[col + 1];
                v0 += b0; v1 += b1; v2 += b0; v3 += b1;
            }
            if (r < M) {
                size_t o = (size_t)r * Hh + col;
                *reinterpret_cast<float2*>(&C[o]) = make_float2(v0, v1);
                if (C2) *reinterpret_cast<float2*>(&C2[o]) = make_float2(v0, v1);
                if (Chi) {
                    uint32_t hi, lo;
                    split_pair(v0, v1, hi, lo);
                    *reinterpret_cast<uint32_t*>(&Chi[o]) = hi;
                    *reinterpret_cast<uint32_t*>(&Clo[o]) = lo;
                }
            }
            if (r + 8 < M) {
                size_t o = (size_t)(r + 8) * Hh + col;
                *reinterpret_cast<float2*>(&C[o]) = make_float2(v2, v3);
                if (C2) *reinterpret_cast<float2*>(&C2[o]) = make_float2(v2, v3);
                if (Chi) {
                    uint32_t hi, lo;
                    split_pair(v2, v3, hi, lo);
                    *reinterpret_cast<uint32_t*>(&Chi[o]) = hi;
                    *reinterpret_cast<uint32_t*>(&Clo[o]) = lo;
                }
            }
        }
    }
}

// ---------------- splits ----------------
__global__ void k_split_w(const float* __restrict__ W, __nv_bfloat16* __restrict__ hi,
                          __nv_bfloat16* __restrict__ lo, int K)
{
    int idx = blockIdx.x * 256 + threadIdx.x;
    if (idx >= Hh * K) return;
    int n = idx / K, k = idx - n * K;
    float v = W[(size_t)k * Hh + n];
    __nv_bfloat16 h = __float2bfloat16(v);
    hi[idx] = h;
    lo[idx] = __float2bfloat16(v - __bfloat162float(h));
}

__global__ void k_split_x(const float* __restrict__ x)
{
    int idx = blockIdx.x * 256 + threadIdx.x;
    if (idx >= Nn * FIN) return;
    float v = x[idx];
    __nv_bfloat16 h = __float2bfloat16(v);
    g_xhi[idx] = h;
    g_xlo[idx] = __float2bfloat16(v - __bfloat162float(h));
}

// ---------------- setup kernels ----------------
__global__ void k_zero_deg() {
    int i = blockIdx.x * blockDim.x + threadIdx.x;
    if (i < Nn) { g_deg[i] = 0; g_cursor[i] = 0; }
}
__global__ void k_count(const int* __restrict__ ei) {
    int e = blockIdx.x * blockDim.x + threadIdx.x;
    if (e < Ee) atomicAdd(&g_deg[ei[Ee + e]], 1);
}
__global__ void k_dinv() {
    int i = blockIdx.x * blockDim.x + threadIdx.x;
    if (i < Nn) g_dinv[i] = rsqrtf((float)(g_deg[i] + 1));
}
__global__ void k_scan1() {
    __shared__ int s[512];
    int i = blockIdx.x * 512 + threadIdx.x;
    int v = (i < Nn) ? g_deg[i] : 0;
    s[threadIdx.x] = v;
    __syncthreads();
    int x = v;
#pragma unroll
    for (int off = 1; off < 512; off <<= 1) {
        int t = (threadIdx.x >= off) ? s[threadIdx.x - off] : 0;
        __syncthreads();
        x += t;
        s[threadIdx.x] = x;
        __syncthreads();
    }
    if (i < Nn) g_rowoff[i] = x - v;
    if (threadIdx.x == 511) g_bsums_scan[blockIdx.x] = x;
}
__global__ void k_scan2(int nb) {
    int acc = 0;
    for (int b = 0; b < nb; b++) { int t = g_bsums_scan[b]; g_bsums_scan[b] = acc; acc += t; }
    g_rowoff[Nn] = acc;
}
__global__ void k_scan3() {
    int i = blockIdx.x * 512 + threadIdx.x;
    if (i < Nn) g_rowoff[i] += g_bsums_scan[blockIdx.x];
}
__global__ void k_scatter(const int* __restrict__ ei) {
    int e = blockIdx.x * blockDim.x + threadIdx.x;
    if (e < Ee) {
        int s = ei[e];
        int d = ei[Ee + e];
        int pos = g_rowoff[d] + atomicAdd(&g_cursor[d], 1);
        g_csr_src[pos] = s;
        g_csr_nrm[pos] = g_dinv[s] * g_dinv[d];
    }
}
__global__ void k_softmax_w(const float* __restrict__ rw) {
    float mx = -1e30f;
    for (int l = 0; l < Ll; l++) mx = fmaxf(mx, rw[l]);
    float s = 0.f;
    float e[Ll];
    for (int l = 0; l < Ll; l++) { e[l] = expf(rw[l] - mx); s += e[l]; }
    for (int l = 0; l < Ll; l++) g_wsoft[l] = e[l] / s;
}
__global__ void k_zero_stats() {
    int t = threadIdx.x;
    if (t < Hh) { g_bsum[t] = 0.0; g_bsq[t] = 0.0; }
}

// ---------------- aggregation + fused BN stats ----------------
__global__ void __launch_bounds__(256)
k_aggregate(const float* __restrict__ hw, const float* __restrict__ cb)
{
    __shared__ float ssum[Hh], ssq[Hh];
    ssum[threadIdx.x] = 0.f;
    ssq[threadIdx.x] = 0.f;
    __syncthreads();

    int warp = threadIdx.x >> 5, lane = threadIdx.x & 31;
    float tsum[8], tsq[8];
#pragma unroll
    for (int k = 0; k < 8; k++) { tsum[k] = 0.f; tsq[k] = 0.f; }

    int base = (blockIdx.x * 8 + warp) * 4;
    for (int n = 0; n < 4; n++) {
        int i = base + n;
        if (i >= Nn) break;
        float di = g_dinv[i];
        float wself = di * di;
        const float* hrow = hw + (size_t)i * Hh;
        float acc[8];
#pragma unroll
        for (int k = 0; k < 8; k++) acc[k] = wself * hrow[lane + 32 * k];
        int e0 = g_rowoff[i], e1 = g_rowoff[i + 1];
        for (int e = e0; e < e1; e++) {
            int s = g_csr_src[e];
            float nr = g_csr_nrm[e];
            const float* srow = hw + (size_t)s * Hh;
#pragma unroll
            for (int k = 0; k < 8; k++) acc[k] += nr * srow[lane + 32 * k];
        }
#pragma unroll
        for (int k = 0; k < 8; k++) {
            float v = acc[k] + cb[lane + 32 * k];
            g_agg[(size_t)i * Hh + lane + 32 * k] = v;
            tsum[k] += v;
            tsq[k] += v * v;
        }
    }
#pragma unroll
    for (int k = 0; k < 8; k++) {
        atomicAdd(&ssum[lane + 32 * k], tsum[k]);
        atomicAdd(&ssq[lane + 32 * k], tsq[k]);
    }
    __syncthreads();
    atomicAdd(&g_bsum[threadIdx.x], (double)ssum[threadIdx.x]);
    atomicAdd(&g_bsq[threadIdx.x], (double)ssq[threadIdx.x]);
}

__global__ void k_stats_final() {
    int c = threadIdx.x;
    double m = g_bsum[c] / (double)Nn;
    double v = g_bsq[c] / (double)Nn - m * m;
    g_mean[c] = (float)m;
    g_rstd[c] = (float)(1.0 / sqrt(v + (double)BN_EPS));
}

// ---------------- BN + ReLU + residual + mix + bf16 split of new h ----------------
__global__ void __launch_bounds__(256)
k_bnapply(const float* __restrict__ gamma, const float* __restrict__ beta,
          int layer, float prevCoef)
{
    int idx = blockIdx.x * blockDim.x + threadIdx.x;
    if (idx >= Nn * (Hh / 4)) return;
    int c4 = (idx & 63);
    float4 a  = reinterpret_cast<const float4*>(g_agg)[idx];
    float4 mn = reinterpret_cast<const float4*>(g_mean)[c4];
    float4 rs = reinterpret_cast<const float4*>(g_rstd)[c4];
    float4 gm = reinterpret_cast<const float4*>(gamma)[c4];
    float4 bt = reinterpret_cast<const float4*>(beta)[c4];
    float4 xi = reinterpret_cast<const float4*>(g_xin)[idx];
    float4 hp = reinterpret_cast<const float4*>(g_h)[idx];
    float w = g_wsoft[layer];

    float4 hn;
    hn.x = fmaxf((a.x - mn.x) * rs.x * gm.x + bt.x, 0.f) + 0.2f * xi.x + prevCoef * hp.x;
    hn.y = fmaxf((a.y - mn.y) * rs.y * gm.y + bt.y, 0.f) + 0.2f * xi.y + prevCoef * hp.y;
    hn.z = fmaxf((a.z - mn.z) * rs.z * gm.z + bt.z, 0.f) + 0.2f * xi.z + prevCoef * hp.z;
    hn.w = fmaxf((a.w - mn.w) * rs.w * gm.w + bt.w, 0.f) + 0.2f * xi.w + prevCoef * hp.w;

    reinterpret_cast<float4*>(g_h)[idx] = hn;

    uint32_t hi0, lo0, hi1, lo1;
    split_pair(hn.x, hn.y, hi0, lo0);
    split_pair(hn.z, hn.w, hi1, lo1);
    uint32_t* ahi = reinterpret_cast<uint32_t*>(g_ahi);
    uint32_t* alo = reinterpret_cast<uint32_t*>(g_alo);
    ahi[idx * 2] = hi0;  ahi[idx * 2 + 1] = hi1;
    alo[idx * 2] = lo0;  alo[idx * 2 + 1] = lo1;

    float4 mx;
    if (layer == 0) {
        mx.x = w * hn.x; mx.y = w * hn.y; mx.z = w * hn.z; mx.w = w * hn.w;
    } else {
        mx = reinterpret_cast<const float4*>(g_mix)[idx];
        mx.x += w * hn.x; mx.y += w * hn.y; mx.z += w * hn.z; mx.w += w * hn.w;
    }
    reinterpret_cast<float4*>(g_mix)[idx] = mx;
}

// ---------------- output: logits + log_softmax ----------------
__global__ void __launch_bounds__(256)
k_output(const float* __restrict__ mix, const float* __restrict__ ow,
         const float* __restrict__ ob, float* __restrict__ out)
{
    __shared__ float sw[Hh * 41];
    __shared__ float sb2[Cc];
    __shared__ float srow[8][48];
    for (int t = threadIdx.x; t < Hh * Cc; t += 256) {
        int k = t / Cc, c = t % Cc;
        sw[k * 41 + c] = ow[t];
    }
    if (threadIdx.x < Cc) sb2[threadIdx.x] = ob[threadIdx.x];
    __syncthreads();

    int warp = threadIdx.x >> 5, lane = threadIdx.x & 31;
    for (int row = blockIdx.x * 8 + warp; row < Nn; row += gridDim.x * 8) {
        float m[8];
#pragma unroll
        for (int j = 0; j < 8; j++) m[j] = mix[(size_t)row * Hh + lane + 32 * j];
        for (int c = 0; c < Cc; c++) {
            float p = 0.f;
#pragma unroll
            for (int j = 0; j < 8; j++) p += m[j] * sw[(lane + 32 * j) * 41 + c];
#pragma unroll
            for (int off = 16; off > 0; off >>= 1) p += __shfl_xor_sync(0xffffffffu, p, off);
            if (lane == 0) srow[warp][c] = p + sb2[c];
        }
        __syncwarp();
        float v1 = srow[warp][lane];
        float v2 = (lane < 8) ? srow[warp][32 + lane] : -1e30f;
        float mx = fmaxf(v1, v2);
#pragma unroll
        for (int off = 16; off > 0; off >>= 1) mx = fmaxf(mx, __shfl_xor_sync(0xffffffffu, mx, off));
        float s = expf(v1 - mx) + ((lane < 8) ? expf(v2 - mx) : 0.f);
#pragma unroll
        for (int off = 16; off > 0; off >>= 1) s += __shfl_xor_sync(0xffffffffu, s, off);
        float lse = mx + logf(s);
        out[(size_t)row * Cc + lane] = v1 - lse;
        if (lane < 8) out[(size_t)row * Cc + 32 + lane] = v2 - lse;
        __syncwarp();
    }
}

// ---------------- launch ----------------
extern "C" void kernel_launch(void* const* d_in, const int* in_sizes, int n_in,
                              void* d_out, int out_size)
{
    const float* x      = (const float*)d_in[0];
    const int*   ei     = (const int*)d_in[1];
    const float* w_in   = (const float*)d_in[2];
    const float* b_in   = (const float*)d_in[3];
    const float* conv_w = (const float*)d_in[4];
    const float* conv_b = (const float*)d_in[5];
    const float* bn_g   = (const float*)d_in[6];
    const float* bn_b   = (const float*)d_in[7];
    const float* out_w  = (const float*)d_in[8];
    const float* out_b  = (const float*)d_in[9];
    const float* res_w  = (const float*)d_in[10];
    float* out = (float*)d_out;

    (void)in_sizes; (void)n_in; (void)out_size;

    static int smem_set = 0;
    if (!smem_set) {
        cudaFuncSetAttribute(k_gemm, cudaFuncAttributeMaxDynamicSharedMemorySize, SMEM_DYN);
        smem_set = 1;
    }

    k_softmax_w<<<1, 1>>>(res_w);
    k_zero_deg<<<(Nn + 255) / 256, 256>>>();
    k_count<<<(Ee + 255) / 256, 256>>>(ei);
    k_dinv<<<(Nn + 255) / 256, 256>>>();
    int nsb = (Nn + 511) / 512;
    k_scan1<<<nsb, 512>>>();
    k_scan2<<<1, 1>>>(nsb);
    k_scan3<<<nsb, 512>>>();
    k_scatter<<<(Ee + 255) / 256, 256>>>(ei);

    float *p_h, *p_hw, *p_xin, *p_mix;
    __nv_bfloat16 *p_ahi, *p_alo, *p_xhi, *p_xlo, *p_bthi, *p_btlo;
    cudaGetSymbolAddress((void**)&p_h, g_h);
    cudaGetSymbolAddress((void**)&p_hw, g_hw);
    cudaGetSymbolAddress((void**)&p_xin, g_xin);
    cudaGetSymbolAddress((void**)&p_mix, g_mix);
    cudaGetSymbolAddress((void**)&p_ahi, g_ahi);
    cudaGetSymbolAddress((void**)&p_alo, g_alo);
    cudaGetSymbolAddress((void**)&p_xhi, g_xhi);
    cudaGetSymbolAddress((void**)&p_xlo, g_xlo);
    cudaGetSymbolAddress((void**)&p_bthi, g_bthi);
    cudaGetSymbolAddress((void**)&p_btlo, g_btlo);

    // pre-split inputs & weights to bf16 hi/lo
    k_split_x<<<(Nn * FIN + 255) / 256, 256>>>(x);
    k_split_w<<<(Hh * FIN + 255) / 256, 256>>>(w_in, p_bthi + BT_IN_OFF, p_btlo + BT_IN_OFF, FIN);
    for (int l = 0; l < Ll; l++)
        k_split_w<<<(Hh * Hh + 255) / 256, 256>>>(conv_w + (size_t)l * Hh * Hh,
                                                  p_bthi + BT_CONV_OFF + (size_t)l * Hh * Hh,
                                                  p_btlo + BT_CONV_OFF + (size_t)l * Hh * Hh, Hh);

    int gblocks = (Nn + 127) / 128;   // 782

    // input fc: h = x @ w_in + b_in -> g_h (fp32), g_xin (fp32), g_ahi/g_alo (bf16 splits)
    k_gemm<<<gblocks, 512, SMEM_DYN>>>(p_xhi, p_xlo, p_bthi + BT_IN_OFF, p_btlo + BT_IN_OFF,
                                       b_in, p_h, p_xin, p_ahi, p_alo, Nn, FIN);

    for (int l = 0; l < Ll; l++) {
        k_gemm<<<gblocks, 512, SMEM_DYN>>>(p_ahi, p_alo,
                                           p_bthi + BT_CONV_OFF + (size_t)l * Hh * Hh,
                                           p_btlo + BT_CONV_OFF + (size_t)l * Hh * Hh,
                                           nullptr, p_hw, nullptr, nullptr, nullptr, Nn, Hh);
        k_zero_stats<<<1, 256>>>();
        k_aggregate<<<(Nn + 31) / 32, 256>>>(p_hw, conv_b + (size_t)l * Hh);
        k_stats_final<<<1, 256>>>();
        k_bnapply<<<(Nn * (Hh / 4) + 255) / 256, 256>>>(bn_g + (size_t)l * Hh, bn_b + (size_t)l * Hh,
                                                        l, (l == 0) ? 0.0f : 0.7f);
    }

    k_output<<<1563, 256>>>(p_mix, out_w, out_b, out);
}

// round 5
// speedup vs baseline: 1.5207x; 1.0660x over previous
#include <cuda_runtime.h>
#include <cuda_bf16.h>
#include <math.h>
#include <stdint.h>

#define Nn 100000
#define Ee 300000
#define Hh 256
#define Cc 40
#define Ll 6
#define FIN 128
#define BN_EPS 1e-5f

// ---------------- device scratch ----------------
__device__ float g_hw[Nn * Hh];     // h @ W
__device__ float g_agg[Nn * Hh];
__device__ float g_xin[Nn * Hh];
__device__ float g_mix[Nn * Hh];
__device__ __nv_bfloat16 g_ahi[Nn * Hh];   // bf16 split of current h (GEMM A + residual state)
__device__ __nv_bfloat16 g_alo[Nn * Hh];
__device__ __nv_bfloat16 g_xhi[Nn * FIN];  // bf16 split of x
__device__ __nv_bfloat16 g_xlo[Nn * FIN];
#define BT_IN_OFF 0
#define BT_CONV_OFF (Hh * FIN)
__device__ __nv_bfloat16 g_bthi[Hh * FIN + Ll * Hh * Hh];
__device__ __nv_bfloat16 g_btlo[Hh * FIN + Ll * Hh * Hh];
__device__ float g_dinv[Nn];
__device__ int   g_deg[Nn];
__device__ int   g_cursor[Nn];
__device__ int   g_rowoff[Nn + 1];
__device__ int   g_csr_src[Ee];
__device__ float g_csr_nrm[Ee];
__device__ double g_bsum[Ll][Hh];   // zero-init; last aggregate block self-resets
__device__ double g_bsq[Ll][Hh];
__device__ int    g_aggdone[Ll];
__device__ float g_mean[Hh];
__device__ float g_rstd[Hh];
__device__ float g_wsoft[Ll];
__device__ int   g_bsums_scan[256];

// ---------------- helpers ----------------
__device__ __forceinline__ uint32_t smem_u32(const void* p) {
    uint32_t a;
    asm("{ .reg .u64 t; cvta.to.shared.u64 t, %1; cvt.u32.u64 %0, t; }" : "=r"(a) : "l"(p));
    return a;
}
__device__ __forceinline__ void cpasync16(uint32_t dst, const void* src, int szbytes) {
    asm volatile("cp.async.cg.shared.global [%0], [%1], 16, %2;"
                 :: "r"(dst), "l"(src), "r"(szbytes) : "memory");
}
#define CP_COMMIT() asm volatile("cp.async.commit_group;" ::: "memory")
#define CP_WAIT(n)  asm volatile("cp.async.wait_group %0;" :: "n"(n) : "memory")

__device__ __forceinline__ void ldsm4(uint32_t& r0, uint32_t& r1, uint32_t& r2, uint32_t& r3, uint32_t addr) {
    asm volatile("ldmatrix.sync.aligned.m8n8.x4.shared.b16 {%0,%1,%2,%3}, [%4];"
                 : "=r"(r0), "=r"(r1), "=r"(r2), "=r"(r3) : "r"(addr));
}
__device__ __forceinline__ void mma_bf16(float c[4], const uint32_t a[4], uint32_t b0, uint32_t b1) {
    asm volatile("mma.sync.aligned.m16n8k16.row.col.f32.bf16.bf16.f32 "
                 "{%0,%1,%2,%3}, {%4,%5,%6,%7}, {%8,%9}, {%0,%1,%2,%3};"
                 : "+f"(c[0]), "+f"(c[1]), "+f"(c[2]), "+f"(c[3])
                 : "r"(a[0]), "r"(a[1]), "r"(a[2]), "r"(a[3]), "r"(b0), "r"(b1));
}
__device__ __forceinline__ uint32_t bf2_pack(__nv_bfloat16 a, __nv_bfloat16 b) {
    __nv_bfloat162 t;
    t.x = a; t.y = b;
    return *reinterpret_cast<uint32_t*>(&t);
}
__device__ __forceinline__ void split_pair(float v0, float v1, uint32_t& hi, uint32_t& lo) {
    __nv_bfloat16 h0 = __float2bfloat16(v0), h1 = __float2bfloat16(v1);
    __nv_bfloat16 l0 = __float2bfloat16(v0 - __bfloat162float(h0));
    __nv_bfloat16 l1 = __float2bfloat16(v1 - __bfloat162float(h1));
    hi = bf2_pack(h0, h1);
    lo = bf2_pack(l0, l1);
}
__device__ __forceinline__ float2 unpack2(uint32_t hi, uint32_t lo) {
    __nv_bfloat162 H = *reinterpret_cast<__nv_bfloat162*>(&hi);
    __nv_bfloat162 L = *reinterpret_cast<__nv_bfloat162*>(&lo);
    return make_float2(__bfloat162float(H.x) + __bfloat162float(L.x),
                       __bfloat162float(H.y) + __bfloat162float(L.y));
}

// ---------------- bf16 split GEMM (unchanged core) ----------------
#define ST_SZ   98304
#define SM_ALO  16384
#define SM_BHI  32768
#define SMEM_DYN (2 * ST_SZ)

__global__ void __launch_bounds__(512, 1)
k_gemm(const __nv_bfloat16* __restrict__ Ahi, const __nv_bfloat16* __restrict__ Alo,
       const __nv_bfloat16* __restrict__ Bhi, const __nv_bfloat16* __restrict__ Blo,
       const float* __restrict__ bias, float* __restrict__ C,
       __nv_bfloat16* __restrict__ Chi, __nv_bfloat16* __restrict__ Clo,
       int M, int K)
{
    extern __shared__ char smem[];
    uint32_t sb = smem_u32(smem);
    int tid = threadIdx.x;
    int lane = tid & 31, wid = tid >> 5;
    int wm = wid >> 2, wn = wid & 3;
    int row0 = blockIdx.x * 128;
    int nc = K >> 6;

    const char* AhiC = (const char*)Ahi;
    const char* AloC = (const char*)Alo;
    const char* BhiC = (const char*)Bhi;
    const char* BloC = (const char*)Blo;

    float c[2][8][4];
#pragma unroll
    for (int mt = 0; mt < 2; mt++)
#pragma unroll
        for (int nt = 0; nt < 8; nt++)
#pragma unroll
            for (int j = 0; j < 4; j++) c[mt][nt][j] = 0.f;

    auto stage_load = [&](int s, int kc) {
        uint32_t so = sb + s * ST_SZ;
#pragma unroll
        for (int j = 0; j < 2; j++) {
            int flat = tid + j * 512;
            int row = flat >> 3, cq = flat & 7;
            int grow = row0 + row;
            int sz = (grow < M) ? 16 : 0;
            int gc = (grow < M) ? grow : (M - 1);
            size_t srcoff = ((size_t)gc * K + kc * 64 + cq * 8) * 2;
            uint32_t dst = so + row * 128 + ((cq ^ (row & 7)) << 4);
            cpasync16(dst, AhiC + srcoff, sz);
            cpasync16(dst + SM_ALO, AloC + srcoff, sz);
        }
#pragma unroll
        for (int j = 0; j < 4; j++) {
            int flat = tid + j * 512;
            int n = flat >> 3, cq = flat & 7;
            size_t srcoff = ((size_t)n * K + kc * 64 + cq * 8) * 2;
            uint32_t dst = so + SM_BHI + n * 128 + ((cq ^ (n & 7)) << 4);
            cpasync16(dst, BhiC + srcoff, 16);
            cpasync16(dst + 32768, BloC + srcoff, 16);
        }
    };

    stage_load(0, 0);
    CP_COMMIT();

    for (int kc = 0; kc < nc; kc++) {
        if (kc + 1 < nc) {
            stage_load((kc + 1) & 1, kc + 1);
            CP_COMMIT();
            CP_WAIT(1);
        } else {
            CP_WAIT(0);
        }
        __syncthreads();

        uint32_t so = sb + (kc & 1) * ST_SZ;
#pragma unroll
        for (int ks = 0; ks < 4; ks++) {
            uint32_t ah[2][4], al[2][4];
#pragma unroll
            for (int mt = 0; mt < 2; mt++) {
                int ml = wm * 32 + mt * 16 + (lane & 7) + ((lane >> 3) & 1) * 8;
                int ck = 2 * ks + (lane >> 4);
                uint32_t ab = so + ml * 128 + ((ck ^ (ml & 7)) << 4);
                ldsm4(ah[mt][0], ah[mt][1], ah[mt][2], ah[mt][3], ab);
                ldsm4(al[mt][0], al[mt][1], al[mt][2], al[mt][3], ab + SM_ALO);
            }
#pragma unroll
            for (int np = 0; np < 4; np++) {
                int nl = wn * 64 + np * 16 + (lane & 7) + ((lane >> 4) << 3);
                int ck = 2 * ks + ((lane >> 3) & 1);
                uint32_t bb = so + SM_BHI + nl * 128 + ((ck ^ (nl & 7)) << 4);
                uint32_t bh[4], bl[4];
                ldsm4(bh[0], bh[1], bh[2], bh[3], bb);
                ldsm4(bl[0], bl[1], bl[2], bl[3], bb + 32768);
#pragma unroll
                for (int mt = 0; mt < 2; mt++) {
                    mma_bf16(c[mt][np * 2 + 0], ah[mt], bh[0], bh[1]);
                    mma_bf16(c[mt][np * 2 + 0], al[mt], bh[0], bh[1]);
                    mma_bf16(c[mt][np * 2 + 0], ah[mt], bl[0], bl[1]);
                    mma_bf16(c[mt][np * 2 + 1], ah[mt], bh[2], bh[3]);
                    mma_bf16(c[mt][np * 2 + 1], al[mt], bh[2], bh[3]);
                    mma_bf16(c[mt][np * 2 + 1], ah[mt], bl[2], bl[3]);
                }
            }
        }
        __syncthreads();
    }

#pragma unroll
    for (int mt = 0; mt < 2; mt++) {
        int r = row0 + wm * 32 + mt * 16 + (lane >> 2);
#pragma unroll
        for (int nt = 0; nt < 8; nt++) {
            int col = wn * 64 + nt * 8 + ((lane & 3) << 1);
            float v0 = c[mt][nt][0], v1 = c[mt][nt][1];
            float v2 = c[mt][nt][2], v3 = c[mt][nt][3];
            if (bias) {
                float b0 = bias[col], b1 = bias[col + 1];
                v0 += b0; v1 += b1; v2 += b0; v3 += b1;
            }
            if (r < M) {
                size_t o = (size_t)r * Hh + col;
                *reinterpret_cast<float2*>(&C[o]) = make_float2(v0, v1);
                if (Chi) {
                    uint32_t hi, lo;
                    split_pair(v0, v1, hi, lo);
                    *reinterpret_cast<uint32_t*>(&Chi[o]) = hi;
                    *reinterpret_cast<uint32_t*>(&Clo[o]) = lo;
                }
            }
            if (r + 8 < M) {
                size_t o = (size_t)(r + 8) * Hh + col;
                *reinterpret_cast<float2*>(&C[o]) = make_float2(v2, v3);
                if (Chi) {
                    uint32_t hi, lo;
                    split_pair(v2, v3, hi, lo);
                    *reinterpret_cast<uint32_t*>(&Chi[o]) = hi;
                    *reinterpret_cast<uint32_t*>(&Clo[o]) = lo;
                }
            }
        }
    }
}

// ---------------- splits ----------------
__global__ void k_split_w(const float* __restrict__ W, __nv_bfloat16* __restrict__ hi,
                          __nv_bfloat16* __restrict__ lo, int K)
{
    int idx = blockIdx.x * 256 + threadIdx.x;
    if (idx >= Hh * K) return;
    int n = idx / K, k = idx - n * K;
    float v = W[(size_t)k * Hh + n];
    __nv_bfloat16 h = __float2bfloat16(v);
    hi[idx] = h;
    lo[idx] = __float2bfloat16(v - __bfloat162float(h));
}

__global__ void k_split_wconv(const float* __restrict__ W)   // all 6 conv layers
{
    int idx = blockIdx.x * 256 + threadIdx.x;
    if (idx >= Ll * Hh * Hh) return;
    int l = idx >> 16;
    int r = idx & 65535;
    int n = r >> 8, k = r & 255;
    float v = W[(size_t)l * Hh * Hh + (size_t)k * Hh + n];
    __nv_bfloat16 h = __float2bfloat16(v);
    g_bthi[BT_CONV_OFF + idx] = h;
    g_btlo[BT_CONV_OFF + idx] = __float2bfloat16(v - __bfloat162float(h));
}

__global__ void k_split_x(const float* __restrict__ x)
{
    int idx = blockIdx.x * 256 + threadIdx.x;
    if (idx >= Nn * FIN) return;
    float v = x[idx];
    __nv_bfloat16 h = __float2bfloat16(v);
    g_xhi[idx] = h;
    g_xlo[idx] = __float2bfloat16(v - __bfloat162float(h));
}

// ---------------- setup kernels ----------------
__global__ void k_zero_deg() {
    int i = blockIdx.x * blockDim.x + threadIdx.x;
    if (i < Nn) { g_deg[i] = 0; g_cursor[i] = 0; }
}
__global__ void k_count(const int* __restrict__ ei) {
    int e = blockIdx.x * blockDim.x + threadIdx.x;
    if (e < Ee) atomicAdd(&g_deg[ei[Ee + e]], 1);
}
__global__ void k_dinv() {
    int i = blockIdx.x * blockDim.x + threadIdx.x;
    if (i < Nn) g_dinv[i] = rsqrtf((float)(g_deg[i] + 1));
}
__global__ void k_scan1() {
    __shared__ int s[512];
    int i = blockIdx.x * 512 + threadIdx.x;
    int v = (i < Nn) ? g_deg[i] : 0;
    s[threadIdx.x] = v;
    __syncthreads();
    int x = v;
#pragma unroll
    for (int off = 1; off < 512; off <<= 1) {
        int t = (threadIdx.x >= off) ? s[threadIdx.x - off] : 0;
        __syncthreads();
        x += t;
        s[threadIdx.x] = x;
        __syncthreads();
    }
    if (i < Nn) g_rowoff[i] = x - v;
    if (threadIdx.x == 511) g_bsums_scan[blockIdx.x] = x;
}
__global__ void k_scan2(int nb) {
    int acc = 0;
    for (int b = 0; b < nb; b++) { int t = g_bsums_scan[b]; g_bsums_scan[b] = acc; acc += t; }
    g_rowoff[Nn] = acc;
}
__global__ void k_scan3() {
    int i = blockIdx.x * 512 + threadIdx.x;
    if (i < Nn) g_rowoff[i] += g_bsums_scan[blockIdx.x];
}
__global__ void k_scatter(const int* __restrict__ ei) {
    int e = blockIdx.x * blockDim.x + threadIdx.x;
    if (e < Ee) {
        int s = ei[e];
        int d = ei[Ee + e];
        int pos = g_rowoff[d] + atomicAdd(&g_cursor[d], 1);
        g_csr_src[pos] = s;
        g_csr_nrm[pos] = g_dinv[s] * g_dinv[d];
    }
}
__global__ void k_softmax_w(const float* __restrict__ rw) {
    float mx = -1e30f;
    for (int l = 0; l < Ll; l++) mx = fmaxf(mx, rw[l]);
    float s = 0.f;
    float e[Ll];
    for (int l = 0; l < Ll; l++) { e[l] = expf(rw[l] - mx); s += e[l]; }
    for (int l = 0; l < Ll; l++) g_wsoft[l] = e[l] / s;
}

// ---------------- aggregation + fused BN stats + last-block finalize ----------------
__global__ void __launch_bounds__(256)
k_aggregate(const float* __restrict__ hw, const float* __restrict__ cb, int layer)
{
    __shared__ float ssum[Hh], ssq[Hh];
    ssum[threadIdx.x] = 0.f;
    ssq[threadIdx.x] = 0.f;
    __syncthreads();

    int warp = threadIdx.x >> 5, lane = threadIdx.x & 31;
    float tsum[8], tsq[8];
#pragma unroll
    for (int k = 0; k < 8; k++) { tsum[k] = 0.f; tsq[k] = 0.f; }

    int base = (blockIdx.x * 8 + warp) * 4;
    for (int n = 0; n < 4; n++) {
        int i = base + n;
        if (i >= Nn) break;
        float di = g_dinv[i];
        float wself = di * di;
        const float* hrow = hw + (size_t)i * Hh;
        float acc[8];
#pragma unroll
        for (int k = 0; k < 8; k++) acc[k] = wself * hrow[lane + 32 * k];
        int e0 = g_rowoff[i], e1 = g_rowoff[i + 1];
        for (int e = e0; e < e1; e++) {
            int s = g_csr_src[e];
            float nr = g_csr_nrm[e];
            const float* srow = hw + (size_t)s * Hh;
#pragma unroll
            for (int k = 0; k < 8; k++) acc[k] += nr * srow[lane + 32 * k];
        }
#pragma unroll
        for (int k = 0; k < 8; k++) {
            float v = acc[k] + cb[lane + 32 * k];
            g_agg[(size_t)i * Hh + lane + 32 * k] = v;
            tsum[k] += v;
            tsq[k] += v * v;
        }
    }
#pragma unroll
    for (int k = 0; k < 8; k++) {
        atomicAdd(&ssum[lane + 32 * k], tsum[k]);
        atomicAdd(&ssq[lane + 32 * k], tsq[k]);
    }
    __syncthreads();
    atomicAdd(&g_bsum[layer][threadIdx.x], (double)ssum[threadIdx.x]);
    atomicAdd(&g_bsq[layer][threadIdx.x], (double)ssq[threadIdx.x]);
    __threadfence();
    __syncthreads();

    __shared__ int isLast;
    if (threadIdx.x == 0)
        isLast = (atomicAdd(&g_aggdone[layer], 1) == (int)gridDim.x - 1);
    __syncthreads();
    if (isLast) {
        __threadfence();
        int c = threadIdx.x;
        double m = g_bsum[layer][c] / (double)Nn;
        double v = g_bsq[layer][c] / (double)Nn - m * m;
        g_mean[c] = (float)m;
        g_rstd[c] = (float)(1.0 / sqrt(v + (double)BN_EPS));
        g_bsum[layer][c] = 0.0;     // self-reset for next call / graph replay
        g_bsq[layer][c] = 0.0;
        if (c == 0) g_aggdone[layer] = 0;
    }
}

// ---------------- BN + ReLU + residual + mix (h kept only as bf16 pair) ----------------
__global__ void __launch_bounds__(256)
k_bnapply(const float* __restrict__ gamma, const float* __restrict__ beta,
          int layer, float prevCoef)
{
    int idx = blockIdx.x * blockDim.x + threadIdx.x;
    if (idx >= Nn * (Hh / 4)) return;
    int c4 = (idx & 63);
    float4 a  = reinterpret_cast<const float4*>(g_agg)[idx];
    float4 mn = reinterpret_cast<const float4*>(g_mean)[c4];
    float4 rs = reinterpret_cast<const float4*>(g_rstd)[c4];
    float4 gm = reinterpret_cast<const float4*>(gamma)[c4];
    float4 bt = reinterpret_cast<const float4*>(beta)[c4];
    float4 xi = reinterpret_cast<const float4*>(g_xin)[idx];
    uint2 hpak = reinterpret_cast<const uint2*>(g_ahi)[idx];
    uint2 lpak = reinterpret_cast<const uint2*>(g_alo)[idx];
    float2 hp01 = unpack2(hpak.x, lpak.x);
    float2 hp23 = unpack2(hpak.y, lpak.y);
    float w = g_wsoft[layer];

    float4 hn;
    hn.x = fmaxf((a.x - mn.x) * rs.x * gm.x + bt.x, 0.f) + 0.2f * xi.x + prevCoef * hp01.x;
    hn.y = fmaxf((a.y - mn.y) * rs.y * gm.y + bt.y, 0.f) + 0.2f * xi.y + prevCoef * hp01.y;
    hn.z = fmaxf((a.z - mn.z) * rs.z * gm.z + bt.z, 0.f) + 0.2f * xi.z + prevCoef * hp23.x;
    hn.w = fmaxf((a.w - mn.w) * rs.w * gm.w + bt.w, 0.f) + 0.2f * xi.w + prevCoef * hp23.y;

    uint2 nh, nl;
    split_pair(hn.x, hn.y, nh.x, nl.x);
    split_pair(hn.z, hn.w, nh.y, nl.y);
    reinterpret_cast<uint2*>(g_ahi)[idx] = nh;
    reinterpret_cast<uint2*>(g_alo)[idx] = nl;

    float4 mx;
    if (layer == 0) {
        mx.x = w * hn.x; mx.y = w * hn.y; mx.z = w * hn.z; mx.w = w * hn.w;
    } else {
        mx = reinterpret_cast<const float4*>(g_mix)[idx];
        mx.x += w * hn.x; mx.y += w * hn.y; mx.z += w * hn.z; mx.w += w * hn.w;
    }
    reinterpret_cast<float4*>(g_mix)[idx] = mx;
}

// ---------------- output: logits + log_softmax ----------------
__global__ void __launch_bounds__(256)
k_output(const float* __restrict__ mix, const float* __restrict__ ow,
         const float* __restrict__ ob, float* __restrict__ out)
{
    __shared__ float sw[Hh * 41];
    __shared__ float sb2[Cc];
    __shared__ float srow[8][48];
    for (int t = threadIdx.x; t < Hh * Cc; t += 256) {
        int k = t / Cc, c = t % Cc;
        sw[k * 41 + c] = ow[t];
    }
    if (threadIdx.x < Cc) sb2[threadIdx.x] = ob[threadIdx.x];
    __syncthreads();

    int warp = threadIdx.x >> 5, lane = threadIdx.x & 31;
    for (int row = blockIdx.x * 8 + warp; row < Nn; row += gridDim.x * 8) {
        float m[8];
#pragma unroll
        for (int j = 0; j < 8; j++) m[j] = mix[(size_t)row * Hh + lane + 32 * j];
        for (int c = 0; c < Cc; c++) {
            float p = 0.f;
#pragma unroll
            for (int j = 0; j < 8; j++) p += m[j] * sw[(lane + 32 * j) * 41 + c];
#pragma unroll
            for (int off = 16; off > 0; off >>= 1) p += __shfl_xor_sync(0xffffffffu, p, off);
            if (lane == 0) srow[warp][c] = p + sb2[c];
        }
        __syncwarp();
        float v1 = srow[warp][lane];
        float v2 = (lane < 8) ? srow[warp][32 + lane] : -1e30f;
        float mx = fmaxf(v1, v2);
#pragma unroll
        for (int off = 16; off > 0; off >>= 1) mx = fmaxf(mx, __shfl_xor_sync(0xffffffffu, mx, off));
        float s = expf(v1 - mx) + ((lane < 8) ? expf(v2 - mx) : 0.f);
#pragma unroll
        for (int off = 16; off > 0; off >>= 1) s += __shfl_xor_sync(0xffffffffu, s, off);
        float lse = mx + logf(s);
        out[(size_t)row * Cc + lane] = v1 - lse;
        if (lane < 8) out[(size_t)row * Cc + 32 + lane] = v2 - lse;
        __syncwarp();
    }
}

// ---------------- launch ----------------
extern "C" void kernel_launch(void* const* d_in, const int* in_sizes, int n_in,
                              void* d_out, int out_size)
{
    const float* x      = (const float*)d_in[0];
    const int*   ei     = (const int*)d_in[1];
    const float* w_in   = (const float*)d_in[2];
    const float* b_in   = (const float*)d_in[3];
    const float* conv_w = (const float*)d_in[4];
    const float* conv_b = (const float*)d_in[5];
    const float* bn_g   = (const float*)d_in[6];
    const float* bn_b   = (const float*)d_in[7];
    const float* out_w  = (const float*)d_in[8];
    const float* out_b  = (const float*)d_in[9];
    const float* res_w  = (const float*)d_in[10];
    float* out = (float*)d_out;

    (void)in_sizes; (void)n_in; (void)out_size;

    static cudaStream_t s2 = nullptr;
    static cudaEvent_t evFork = nullptr, evJoin = nullptr;
    if (!s2) {
        cudaStreamCreate(&s2);
        cudaEventCreateWithFlags(&evFork, cudaEventDisableTiming);
        cudaEventCreateWithFlags(&evJoin, cudaEventDisableTiming);
        cudaFuncSetAttribute(k_gemm, cudaFuncAttributeMaxDynamicSharedMemorySize, SMEM_DYN);
    }

    float *p_hw, *p_xin, *p_mix;
    __nv_bfloat16 *p_ahi, *p_alo, *p_xhi, *p_xlo, *p_bthi, *p_btlo;
    cudaGetSymbolAddress((void**)&p_hw, g_hw);
    cudaGetSymbolAddress((void**)&p_xin, g_xin);
    cudaGetSymbolAddress((void**)&p_mix, g_mix);
    cudaGetSymbolAddress((void**)&p_ahi, g_ahi);
    cudaGetSymbolAddress((void**)&p_alo, g_alo);
    cudaGetSymbolAddress((void**)&p_xhi, g_xhi);
    cudaGetSymbolAddress((void**)&p_xlo, g_xlo);
    cudaGetSymbolAddress((void**)&p_bthi, g_bthi);
    cudaGetSymbolAddress((void**)&p_btlo, g_btlo);

    int gblocks = (Nn + 127) / 128;   // 782

    // fork point for CSR setup stream
    cudaEventRecord(evFork, 0);
    cudaStreamWaitEvent(s2, evFork, 0);

    // stream 0: splits + input GEMM (GEMM = user launch #4 for ncu visibility)
    k_split_x<<<(Nn * FIN + 255) / 256, 256>>>(x);                                       // 1
    k_split_w<<<(Hh * FIN + 255) / 256, 256>>>(w_in, p_bthi, p_btlo, FIN);               // 2
    k_split_wconv<<<(Ll * Hh * Hh + 255) / 256, 256>>>(conv_w);                          // 3
    k_gemm<<<gblocks, 512, SMEM_DYN>>>(p_xhi, p_xlo, p_bthi + BT_IN_OFF, p_btlo + BT_IN_OFF,
                                       b_in, p_xin, p_ahi, p_alo, Nn, FIN);              // 4

    // s2: CSR build, overlaps with the above
    k_softmax_w<<<1, 1, 0, s2>>>(res_w);
    k_zero_deg<<<(Nn + 255) / 256, 256, 0, s2>>>();
    k_count<<<(Ee + 255) / 256, 256, 0, s2>>>(ei);
    k_dinv<<<(Nn + 255) / 256, 256, 0, s2>>>();
    int nsb = (Nn + 511) / 512;
    k_scan1<<<nsb, 512, 0, s2>>>();
    k_scan2<<<1, 1, 0, s2>>>(nsb);
    k_scan3<<<nsb, 512, 0, s2>>>();
    k_scatter<<<(Ee + 255) / 256, 256, 0, s2>>>(ei);
    cudaEventRecord(evJoin, s2);
    cudaStreamWaitEvent(0, evJoin, 0);

    for (int l = 0; l < Ll; l++) {
        k_gemm<<<gblocks, 512, SMEM_DYN>>>(p_ahi, p_alo,
                                           p_bthi + BT_CONV_OFF + (size_t)l * Hh * Hh,
                                           p_btlo + BT_CONV_OFF + (size_t)l * Hh * Hh,
                                           nullptr, p_hw, nullptr, nullptr, Nn, Hh);
        k_aggregate<<<(Nn + 31) / 32, 256>>>(p_hw, conv_b + (size_t)l * Hh, l);
        k_bnapply<<<(Nn * (Hh / 4) + 255) / 256, 256>>>(bn_g + (size_t)l * Hh, bn_b + (size_t)l * Hh,
                                                        l, (l == 0) ? 0.0f : 0.7f);
    }

    k_output<<<1563, 256>>>(p_mix, out_w, out_b, out);
}

// round 6
// speedup vs baseline: 1.5232x; 1.0017x over previous
#include <cuda_runtime.h>
#include <cuda_bf16.h>
#include <math.h>
#include <stdint.h>

#define Nn 100000
#define Ee 300000
#define Hh 256
#define Cc 40
#define Ll 6
#define FIN 128
#define BN_EPS 1e-5f

// ---------------- device scratch ----------------
__device__ float g_hw[Nn * Hh];     // h @ W
__device__ float g_agg[Nn * Hh];
__device__ float g_xin[Nn * Hh];
__device__ float g_mix[Nn * Hh];
__device__ __nv_bfloat16 g_ahi[Nn * Hh];   // bf16 split of current h
__device__ __nv_bfloat16 g_alo[Nn * Hh];
__device__ __nv_bfloat16 g_xhi[Nn * FIN];
__device__ __nv_bfloat16 g_xlo[Nn * FIN];
#define BT_IN_OFF 0
#define BT_CONV_OFF (Hh * FIN)
__device__ __nv_bfloat16 g_bthi[Hh * FIN + Ll * Hh * Hh];
__device__ __nv_bfloat16 g_btlo[Hh * FIN + Ll * Hh * Hh];
__device__ float g_dinv[Nn];
__device__ int   g_deg[Nn];
__device__ int   g_cursor[Nn];
__device__ int   g_rowoff[Nn + 1];
__device__ int   g_csr_src[Ee];
__device__ float g_csr_nrm[Ee];
__device__ double g_bsum[Ll][Hh];
__device__ double g_bsq[Ll][Hh];
__device__ int    g_aggdone[Ll];
__device__ float g_mean[Hh];
__device__ float g_rstd[Hh];
__device__ float g_wsoft[Ll];
__device__ int   g_bsums_scan[256];

// ---------------- helpers ----------------
__device__ __forceinline__ uint32_t smem_u32(const void* p) {
    uint32_t a;
    asm("{ .reg .u64 t; cvta.to.shared.u64 t, %1; cvt.u32.u64 %0, t; }" : "=r"(a) : "l"(p));
    return a;
}
__device__ __forceinline__ void cpasync16(uint32_t dst, const void* src, int szbytes) {
    asm volatile("cp.async.cg.shared.global [%0], [%1], 16, %2;"
                 :: "r"(dst), "l"(src), "r"(szbytes) : "memory");
}
#define CP_COMMIT() asm volatile("cp.async.commit_group;" ::: "memory")
#define CP_WAIT(n)  asm volatile("cp.async.wait_group %0;" :: "n"(n) : "memory")

__device__ __forceinline__ void ldsm4(uint32_t& r0, uint32_t& r1, uint32_t& r2, uint32_t& r3, uint32_t addr) {
    asm volatile("ldmatrix.sync.aligned.m8n8.x4.shared.b16 {%0,%1,%2,%3}, [%4];"
                 : "=r"(r0), "=r"(r1), "=r"(r2), "=r"(r3) : "r"(addr));
}
__device__ __forceinline__ void mma_bf16(float c[4], const uint32_t a[4], uint32_t b0, uint32_t b1) {
    asm volatile("mma.sync.aligned.m16n8k16.row.col.f32.bf16.bf16.f32 "
                 "{%0,%1,%2,%3}, {%4,%5,%6,%7}, {%8,%9}, {%0,%1,%2,%3};"
                 : "+f"(c[0]), "+f"(c[1]), "+f"(c[2]), "+f"(c[3])
                 : "r"(a[0]), "r"(a[1]), "r"(a[2]), "r"(a[3]), "r"(b0), "r"(b1));
}
__device__ __forceinline__ uint32_t bf2_pack(__nv_bfloat16 a, __nv_bfloat16 b) {
    __nv_bfloat162 t;
    t.x = a; t.y = b;
    return *reinterpret_cast<uint32_t*>(&t);
}
__device__ __forceinline__ void split_pair(float v0, float v1, uint32_t& hi, uint32_t& lo) {
    __nv_bfloat16 h0 = __float2bfloat16(v0), h1 = __float2bfloat16(v1);
    __nv_bfloat16 l0 = __float2bfloat16(v0 - __bfloat162float(h0));
    __nv_bfloat16 l1 = __float2bfloat16(v1 - __bfloat162float(h1));
    hi = bf2_pack(h0, h1);
    lo = bf2_pack(l0, l1);
}
__device__ __forceinline__ float2 unpack2(uint32_t hi, uint32_t lo) {
    __nv_bfloat162 H = *reinterpret_cast<__nv_bfloat162*>(&hi);
    __nv_bfloat162 L = *reinterpret_cast<__nv_bfloat162*>(&lo);
    return make_float2(__bfloat162float(H.x) + __bfloat162float(L.x),
                       __bfloat162float(H.y) + __bfloat162float(L.y));
}

// ---------------- bf16 split GEMM ----------------
#define ST_SZ   98304
#define SM_ALO  16384
#define SM_BHI  32768
#define SMEM_DYN (2 * ST_SZ)

__global__ void __launch_bounds__(512, 1)
k_gemm(const __nv_bfloat16* __restrict__ Ahi, const __nv_bfloat16* __restrict__ Alo,
       const __nv_bfloat16* __restrict__ Bhi, const __nv_bfloat16* __restrict__ Blo,
       const float* __restrict__ bias, float* __restrict__ C,
       __nv_bfloat16* __restrict__ Chi, __nv_bfloat16* __restrict__ Clo,
       int M, int K)
{
    extern __shared__ char smem[];
    uint32_t sb = smem_u32(smem);
    int tid = threadIdx.x;
    int lane = tid & 31, wid = tid >> 5;
    int wm = wid >> 2, wn = wid & 3;
    int row0 = blockIdx.x * 128;
    int nc = K >> 6;

    const char* AhiC = (const char*)Ahi;
    const char* AloC = (const char*)Alo;
    const char* BhiC = (const char*)Bhi;
    const char* BloC = (const char*)Blo;

    float c[2][8][4];
#pragma unroll
    for (int mt = 0; mt < 2; mt++)
#pragma unroll
        for (int nt = 0; nt < 8; nt++)
#pragma unroll
            for (int j = 0; j < 4; j++) c[mt][nt][j] = 0.f;

    auto stage_load = [&](int s, int kc) {
        uint32_t so = sb + s * ST_SZ;
#pragma unroll
        for (int j = 0; j < 2; j++) {
            int flat = tid + j * 512;
            int row = flat >> 3, cq = flat & 7;
            int grow = row0 + row;
            int sz = (grow < M) ? 16 : 0;
            int gc = (grow < M) ? grow : (M - 1);
            size_t srcoff = ((size_t)gc * K + kc * 64 + cq * 8) * 2;
            uint32_t dst = so + row * 128 + ((cq ^ (row & 7)) << 4);
            cpasync16(dst, AhiC + srcoff, sz);
            cpasync16(dst + SM_ALO, AloC + srcoff, sz);
        }
#pragma unroll
        for (int j = 0; j < 4; j++) {
            int flat = tid + j * 512;
            int n = flat >> 3, cq = flat & 7;
            size_t srcoff = ((size_t)n * K + kc * 64 + cq * 8) * 2;
            uint32_t dst = so + SM_BHI + n * 128 + ((cq ^ (n & 7)) << 4);
            cpasync16(dst, BhiC + srcoff, 16);
            cpasync16(dst + 32768, BloC + srcoff, 16);
        }
    };

    stage_load(0, 0);
    CP_COMMIT();

    for (int kc = 0; kc < nc; kc++) {
        if (kc + 1 < nc) {
            stage_load((kc + 1) & 1, kc + 1);
            CP_COMMIT();
            CP_WAIT(1);
        } else {
            CP_WAIT(0);
        }
        __syncthreads();

        uint32_t so = sb + (kc & 1) * ST_SZ;
#pragma unroll
        for (int ks = 0; ks < 4; ks++) {
            uint32_t ah[2][4], al[2][4];
#pragma unroll
            for (int mt = 0; mt < 2; mt++) {
                int ml = wm * 32 + mt * 16 + (lane & 7) + ((lane >> 3) & 1) * 8;
                int ck = 2 * ks + (lane >> 4);
                uint32_t ab = so + ml * 128 + ((ck ^ (ml & 7)) << 4);
                ldsm4(ah[mt][0], ah[mt][1], ah[mt][2], ah[mt][3], ab);
                ldsm4(al[mt][0], al[mt][1], al[mt][2], al[mt][3], ab + SM_ALO);
            }
            // process n-tiles in pairs; within a pair emit term-major blocks of 8
            // independent mmas (RAW reuse distance 8 instead of 1)
#pragma unroll
            for (int npp = 0; npp < 2; npp++) {
                uint32_t bh[2][4], bl[2][4];
#pragma unroll
                for (int j = 0; j < 2; j++) {
                    int np = npp * 2 + j;
                    int nl = wn * 64 + np * 16 + (lane & 7) + ((lane >> 4) << 3);
                    int ck = 2 * ks + ((lane >> 3) & 1);
                    uint32_t bb = so + SM_BHI + nl * 128 + ((ck ^ (nl & 7)) << 4);
                    ldsm4(bh[j][0], bh[j][1], bh[j][2], bh[j][3], bb);
                    ldsm4(bl[j][0], bl[j][1], bl[j][2], bl[j][3], bb + 32768);
                }
                // term 1: ah * bh
#pragma unroll
                for (int j = 0; j < 2; j++) {
                    int nb = (npp * 2 + j) * 2;
#pragma unroll
                    for (int mt = 0; mt < 2; mt++) {
                        mma_bf16(c[mt][nb + 0], ah[mt], bh[j][0], bh[j][1]);
                        mma_bf16(c[mt][nb + 1], ah[mt], bh[j][2], bh[j][3]);
                    }
                }
                // term 2: al * bh
#pragma unroll
                for (int j = 0; j < 2; j++) {
                    int nb = (npp * 2 + j) * 2;
#pragma unroll
                    for (int mt = 0; mt < 2; mt++) {
                        mma_bf16(c[mt][nb + 0], al[mt], bh[j][0], bh[j][1]);
                        mma_bf16(c[mt][nb + 1], al[mt], bh[j][2], bh[j][3]);
                    }
                }
                // term 3: ah * bl
#pragma unroll
                for (int j = 0; j < 2; j++) {
                    int nb = (npp * 2 + j) * 2;
#pragma unroll
                    for (int mt = 0; mt < 2; mt++) {
                        mma_bf16(c[mt][nb + 0], ah[mt], bl[j][0], bl[j][1]);
                        mma_bf16(c[mt][nb + 1], ah[mt], bl[j][2], bl[j][3]);
                    }
                }
            }
        }
        __syncthreads();
    }

#pragma unroll
    for (int mt = 0; mt < 2; mt++) {
        int r = row0 + wm * 32 + mt * 16 + (lane >> 2);
#pragma unroll
        for (int nt = 0; nt < 8; nt++) {
            int col = wn * 64 + nt * 8 + ((lane & 3) << 1);
            float v0 = c[mt][nt][0], v1 = c[mt][nt][1];
            float v2 = c[mt][nt][2], v3 = c[mt][nt][3];
            if (bias) {
                float b0 = bias[col], b1 = bias[col + 1];
                v0 += b0; v1 += b1; v2 += b0; v3 += b1;
            }
            if (r < M) {
                size_t o = (size_t)r * Hh + col;
                *reinterpret_cast<float2*>(&C[o]) = make_float2(v0, v1);
                if (Chi) {
                    uint32_t hi, lo;
                    split_pair(v0, v1, hi, lo);
                    *reinterpret_cast<uint32_t*>(&Chi[o]) = hi;
                    *reinterpret_cast<uint32_t*>(&Clo[o]) = lo;
                }
            }
            if (r + 8 < M) {
                size_t o = (size_t)(r + 8) * Hh + col;
                *reinterpret_cast<float2*>(&C[o]) = make_float2(v2, v3);
                if (Chi) {
                    uint32_t hi, lo;
                    split_pair(v2, v3, hi, lo);
                    *reinterpret_cast<uint32_t*>(&Chi[o]) = hi;
                    *reinterpret_cast<uint32_t*>(&Clo[o]) = lo;
                }
            }
        }
    }
}

// ---------------- splits ----------------
__global__ void k_split_w(const float* __restrict__ W, __nv_bfloat16* __restrict__ hi,
                          __nv_bfloat16* __restrict__ lo, int K)
{
    int idx = blockIdx.x * 256 + threadIdx.x;
    if (idx >= Hh * K) return;
    int n = idx / K, k = idx - n * K;
    float v = W[(size_t)k * Hh + n];
    __nv_bfloat16 h = __float2bfloat16(v);
    hi[idx] = h;
    lo[idx] = __float2bfloat16(v - __bfloat162float(h));
}

__global__ void k_split_wconv(const float* __restrict__ W)
{
    int idx = blockIdx.x * 256 + threadIdx.x;
    if (idx >= Ll * Hh * Hh) return;
    int l = idx >> 16;
    int r = idx & 65535;
    int n = r >> 8, k = r & 255;
    float v = W[(size_t)l * Hh * Hh + (size_t)k * Hh + n];
    __nv_bfloat16 h = __float2bfloat16(v);
    g_bthi[BT_CONV_OFF + idx] = h;
    g_btlo[BT_CONV_OFF + idx] = __float2bfloat16(v - __bfloat162float(h));
}

__global__ void k_split_x(const float* __restrict__ x)
{
    int idx = blockIdx.x * 256 + threadIdx.x;
    if (idx >= Nn * FIN) return;
    float v = x[idx];
    __nv_bfloat16 h = __float2bfloat16(v);
    g_xhi[idx] = h;
    g_xlo[idx] = __float2bfloat16(v - __bfloat162float(h));
}

// ---------------- setup kernels ----------------
__global__ void k_zero_deg() {
    int i = blockIdx.x * blockDim.x + threadIdx.x;
    if (i < Nn) { g_deg[i] = 0; g_cursor[i] = 0; }
}
__global__ void k_count(const int* __restrict__ ei) {
    int e = blockIdx.x * blockDim.x + threadIdx.x;
    if (e < Ee) atomicAdd(&g_deg[ei[Ee + e]], 1);
}
__global__ void k_dinv() {
    int i = blockIdx.x * blockDim.x + threadIdx.x;
    if (i < Nn) g_dinv[i] = rsqrtf((float)(g_deg[i] + 1));
}
__global__ void k_scan1() {
    __shared__ int s[512];
    int i = blockIdx.x * 512 + threadIdx.x;
    int v = (i < Nn) ? g_deg[i] : 0;
    s[threadIdx.x] = v;
    __syncthreads();
    int x = v;
#pragma unroll
    for (int off = 1; off < 512; off <<= 1) {
        int t = (threadIdx.x >= off) ? s[threadIdx.x - off] : 0;
        __syncthreads();
        x += t;
        s[threadIdx.x] = x;
        __syncthreads();
    }
    if (i < Nn) g_rowoff[i] = x - v;
    if (threadIdx.x == 511) g_bsums_scan[blockIdx.x] = x;
}
__global__ void k_scan2(int nb) {
    int acc = 0;
    for (int b = 0; b < nb; b++) { int t = g_bsums_scan[b]; g_bsums_scan[b] = acc; acc += t; }
    g_rowoff[Nn] = acc;
}
__global__ void k_scan3() {
    int i = blockIdx.x * 512 + threadIdx.x;
    if (i < Nn) g_rowoff[i] += g_bsums_scan[blockIdx.x];
}
__global__ void k_scatter(const int* __restrict__ ei) {
    int e = blockIdx.x * blockDim.x + threadIdx.x;
    if (e < Ee) {
        int s = ei[e];
        int d = ei[Ee + e];
        int pos = g_rowoff[d] + atomicAdd(&g_cursor[d], 1);
        g_csr_src[pos] = s;
        g_csr_nrm[pos] = g_dinv[s] * g_dinv[d];
    }
}
__global__ void k_softmax_w(const float* __restrict__ rw) {
    float mx = -1e30f;
    for (int l = 0; l < Ll; l++) mx = fmaxf(mx, rw[l]);
    float s = 0.f;
    float e[Ll];
    for (int l = 0; l < Ll; l++) { e[l] = expf(rw[l] - mx); s += e[l]; }
    for (int l = 0; l < Ll; l++) g_wsoft[l] = e[l] / s;
}

// ---------------- aggregation + fused BN stats + last-block finalize ----------------
__global__ void __launch_bounds__(256)
k_aggregate(const float* __restrict__ hw, const float* __restrict__ cb, int layer)
{
    __shared__ float ssum[Hh], ssq[Hh];
    ssum[threadIdx.x] = 0.f;
    ssq[threadIdx.x] = 0.f;
    __syncthreads();

    int warp = threadIdx.x >> 5, lane = threadIdx.x & 31;
    float tsum[8], tsq[8];
#pragma unroll
    for (int k = 0; k < 8; k++) { tsum[k] = 0.f; tsq[k] = 0.f; }

    int base = (blockIdx.x * 8 + warp) * 4;
    for (int n = 0; n < 4; n++) {
        int i = base + n;
        if (i >= Nn) break;
        float di = g_dinv[i];
        float wself = di * di;
        const float* hrow = hw + (size_t)i * Hh;
        float acc[8];
#pragma unroll
        for (int k = 0; k < 8; k++) acc[k] = wself * hrow[lane + 32 * k];
        int e0 = g_rowoff[i], e1 = g_rowoff[i + 1];
        for (int e = e0; e < e1; e++) {
            int s = g_csr_src[e];
            float nr = g_csr_nrm[e];
            const float* srow = hw + (size_t)s * Hh;
#pragma unroll
            for (int k = 0; k < 8; k++) acc[k] += nr * srow[lane + 32 * k];
        }
#pragma unroll
        for (int k = 0; k < 8; k++) {
            float v = acc[k] + cb[lane + 32 * k];
            g_agg[(size_t)i * Hh + lane + 32 * k] = v;
            tsum[k] += v;
            tsq[k] += v * v;
        }
    }
#pragma unroll
    for (int k = 0; k < 8; k++) {
        atomicAdd(&ssum[lane + 32 * k], tsum[k]);
        atomicAdd(&ssq[lane + 32 * k], tsq[k]);
    }
    __syncthreads();
    atomicAdd(&g_bsum[layer][threadIdx.x], (double)ssum[threadIdx.x]);
    atomicAdd(&g_bsq[layer][threadIdx.x], (double)ssq[threadIdx.x]);
    __threadfence();
    __syncthreads();

    __shared__ int isLast;
    if (threadIdx.x == 0)
        isLast = (atomicAdd(&g_aggdone[layer], 1) == (int)gridDim.x - 1);
    __syncthreads();
    if (isLast) {
        __threadfence();
        int c = threadIdx.x;
        double m = g_bsum[layer][c] / (double)Nn;
        double v = g_bsq[layer][c] / (double)Nn - m * m;
        g_mean[c] = (float)m;
        g_rstd[c] = (float)(1.0 / sqrt(v + (double)BN_EPS));
        g_bsum[layer][c] = 0.0;
        g_bsq[layer][c] = 0.0;
        if (c == 0) g_aggdone[layer] = 0;
    }
}

// ---------------- BN + ReLU + residual + mix ----------------
__global__ void __launch_bounds__(256)
k_bnapply(const float* __restrict__ gamma, const float* __restrict__ beta,
          int layer, float prevCoef)
{
    int idx = blockIdx.x * blockDim.x + threadIdx.x;
    if (idx >= Nn * (Hh / 4)) return;
    int c4 = (idx & 63);
    float4 a  = reinterpret_cast<const float4*>(g_agg)[idx];
    float4 mn = reinterpret_cast<const float4*>(g_mean)[c4];
    float4 rs = reinterpret_cast<const float4*>(g_rstd)[c4];
    float4 gm = reinterpret_cast<const float4*>(gamma)[c4];
    float4 bt = reinterpret_cast<const float4*>(beta)[c4];
    float4 xi = reinterpret_cast<const float4*>(g_xin)[idx];
    uint2 hpak = reinterpret_cast<const uint2*>(g_ahi)[idx];
    uint2 lpak = reinterpret_cast<const uint2*>(g_alo)[idx];
    float2 hp01 = unpack2(hpak.x, lpak.x);
    float2 hp23 = unpack2(hpak.y, lpak.y);
    float w = g_wsoft[layer];

    float4 hn;
    hn.x = fmaxf((a.x - mn.x) * rs.x * gm.x + bt.x, 0.f) + 0.2f * xi.x + prevCoef * hp01.x;
    hn.y = fmaxf((a.y - mn.y) * rs.y * gm.y + bt.y, 0.f) + 0.2f * xi.y + prevCoef * hp01.y;
    hn.z = fmaxf((a.z - mn.z) * rs.z * gm.z + bt.z, 0.f) + 0.2f * xi.z + prevCoef * hp23.x;
    hn.w = fmaxf((a.w - mn.w) * rs.w * gm.w + bt.w, 0.f) + 0.2f * xi.w + prevCoef * hp23.y;

    uint2 nh, nl;
    split_pair(hn.x, hn.y, nh.x, nl.x);
    split_pair(hn.z, hn.w, nh.y, nl.y);
    reinterpret_cast<uint2*>(g_ahi)[idx] = nh;
    reinterpret_cast<uint2*>(g_alo)[idx] = nl;

    float4 mx;
    if (layer == 0) {
        mx.x = w * hn.x; mx.y = w * hn.y; mx.z = w * hn.z; mx.w = w * hn.w;
    } else {
        mx = reinterpret_cast<const float4*>(g_mix)[idx];
        mx.x += w * hn.x; mx.y += w * hn.y; mx.z += w * hn.z; mx.w += w * hn.w;
    }
    reinterpret_cast<float4*>(g_mix)[idx] = mx;
}

// ---------------- output: logits + log_softmax ----------------
__global__ void __launch_bounds__(256)
k_output(const float* __restrict__ mix, const float* __restrict__ ow,
         const float* __restrict__ ob, float* __restrict__ out)
{
    __shared__ float sw[Hh * 41];
    __shared__ float sb2[Cc];
    __shared__ float srow[8][48];
    for (int t = threadIdx.x; t < Hh * Cc; t += 256) {
        int k = t / Cc, c = t % Cc;
        sw[k * 41 + c] = ow[t];
    }
    if (threadIdx.x < Cc) sb2[threadIdx.x] = ob[threadIdx.x];
    __syncthreads();

    int warp = threadIdx.x >> 5, lane = threadIdx.x & 31;
    for (int row = blockIdx.x * 8 + warp; row < Nn; row += gridDim.x * 8) {
        float m[8];
#pragma unroll
        for (int j = 0; j < 8; j++) m[j] = mix[(size_t)row * Hh + lane + 32 * j];
        for (int c = 0; c < Cc; c++) {
            float p = 0.f;
#pragma unroll
            for (int j = 0; j < 8; j++) p += m[j] * sw[(lane + 32 * j) * 41 + c];
#pragma unroll
            for (int off = 16; off > 0; off >>= 1) p += __shfl_xor_sync(0xffffffffu, p, off);
            if (lane == 0) srow[warp][c] = p + sb2[c];
        }
        __syncwarp();
        float v1 = srow[warp][lane];
        float v2 = (lane < 8) ? srow[warp][32 + lane] : -1e30f;
        float mx = fmaxf(v1, v2);
#pragma unroll
        for (int off = 16; off > 0; off >>= 1) mx = fmaxf(mx, __shfl_xor_sync(0xffffffffu, mx, off));
        float s = expf(v1 - mx) + ((lane < 8) ? expf(v2 - mx) : 0.f);
#pragma unroll
        for (int off = 16; off > 0; off >>= 1) s += __shfl_xor_sync(0xffffffffu, s, off);
        float lse = mx + logf(s);
        out[(size_t)row * Cc + lane] = v1 - lse;
        if (lane < 8) out[(size_t)row * Cc + 32 + lane] = v2 - lse;
        __syncwarp();
    }
}

// ---------------- launch ----------------
extern "C" void kernel_launch(void* const* d_in, const int* in_sizes, int n_in,
                              void* d_out, int out_size)
{
    const float* x      = (const float*)d_in[0];
    const int*   ei     = (const int*)d_in[1];
    const float* w_in   = (const float*)d_in[2];
    const float* b_in   = (const float*)d_in[3];
    const float* conv_w = (const float*)d_in[4];
    const float* conv_b = (const float*)d_in[5];
    const float* bn_g   = (const float*)d_in[6];
    const float* bn_b   = (const float*)d_in[7];
    const float* out_w  = (const float*)d_in[8];
    const float* out_b  = (const float*)d_in[9];
    const float* res_w  = (const float*)d_in[10];
    float* out = (float*)d_out;

    (void)in_sizes; (void)n_in; (void)out_size;

    static cudaStream_t s2 = nullptr;
    static cudaEvent_t evFork = nullptr, evJoin = nullptr;
    if (!s2) {
        cudaStreamCreate(&s2);
        cudaEventCreateWithFlags(&evFork, cudaEventDisableTiming);
        cudaEventCreateWithFlags(&evJoin, cudaEventDisableTiming);
        cudaFuncSetAttribute(k_gemm, cudaFuncAttributeMaxDynamicSharedMemorySize, SMEM_DYN);
    }

    float *p_hw, *p_xin, *p_mix;
    __nv_bfloat16 *p_ahi, *p_alo, *p_xhi, *p_xlo, *p_bthi, *p_btlo;
    cudaGetSymbolAddress((void**)&p_hw, g_hw);
    cudaGetSymbolAddress((void**)&p_xin, g_xin);
    cudaGetSymbolAddress((void**)&p_mix, g_mix);
    cudaGetSymbolAddress((void**)&p_ahi, g_ahi);
    cudaGetSymbolAddress((void**)&p_alo, g_alo);
    cudaGetSymbolAddress((void**)&p_xhi, g_xhi);
    cudaGetSymbolAddress((void**)&p_xlo, g_xlo);
    cudaGetSymbolAddress((void**)&p_bthi, g_bthi);
    cudaGetSymbolAddress((void**)&p_btlo, g_btlo);

    int gblocks = (Nn + 127) / 128;   // 782

    cudaEventRecord(evFork, 0);
    cudaStreamWaitEvent(s2, evFork, 0);

    k_split_x<<<(Nn * FIN + 255) / 256, 256>>>(x);
    k_split_w<<<(Hh * FIN + 255) / 256, 256>>>(w_in, p_bthi, p_btlo, FIN);
    k_split_wconv<<<(Ll * Hh * Hh + 255) / 256, 256>>>(conv_w);
    k_gemm<<<gblocks, 512, SMEM_DYN>>>(p_xhi, p_xlo, p_bthi + BT_IN_OFF, p_btlo + BT_IN_OFF,
                                       b_in, p_xin, p_ahi, p_alo, Nn, FIN);

    k_softmax_w<<<1, 1, 0, s2>>>(res_w);
    k_zero_deg<<<(Nn + 255) / 256, 256, 0, s2>>>();
    k_count<<<(Ee + 255) / 256, 256, 0, s2>>>(ei);
    k_dinv<<<(Nn + 255) / 256, 256, 0, s2>>>();
    int nsb = (Nn + 511) / 512;
    k_scan1<<<nsb, 512, 0, s2>>>();
    k_scan2<<<1, 1, 0, s2>>>(nsb);
    k_scan3<<<nsb, 512, 0, s2>>>();
    k_scatter<<<(Ee + 255) / 256, 256, 0, s2>>>(ei);
    cudaEventRecord(evJoin, s2);
    cudaStreamWaitEvent(0, evJoin, 0);

    for (int l = 0; l < Ll; l++) {
        k_gemm<<<gblocks, 512, SMEM_DYN>>>(p_ahi, p_alo,
                                           p_bthi + BT_CONV_OFF + (size_t)l * Hh * Hh,
                                           p_btlo + BT_CONV_OFF + (size_t)l * Hh * Hh,
                                           nullptr, p_hw, nullptr, nullptr, Nn, Hh);
        k_aggregate<<<(Nn + 31) / 32, 256>>>(p_hw, conv_b + (size_t)l * Hh, l);
        k_bnapply<<<(Nn * (Hh / 4) + 255) / 256, 256>>>(bn_g + (size_t)l * Hh, bn_b + (size_t)l * Hh,
                                                        l, (l == 0) ? 0.0f : 0.7f);
    }

    k_output<<<1563, 256>>>(p_mix, out_w, out_b, out);
}

// round 7
// speedup vs baseline: 1.5385x; 1.0100x over previous
#include <cuda_runtime.h>
#include <cuda_bf16.h>
#include <math.h>
#include <stdint.h>

#define Nn 100000
#define Ee 300000
#define Hh 256
#define Cc 40
#define Ll 6
#define FIN 128
#define BN_EPS 1e-5f

// ---------------- device scratch ----------------
__device__ float g_hw[Nn * Hh];
__device__ float g_agg[Nn * Hh];
__device__ float g_xin[Nn * Hh];
__device__ float g_mix[Nn * Hh];
__device__ __nv_bfloat16 g_ahi[Nn * Hh];
__device__ __nv_bfloat16 g_alo[Nn * Hh];
__device__ __nv_bfloat16 g_xhi[Nn * FIN];
__device__ __nv_bfloat16 g_xlo[Nn * FIN];
#define BT_IN_OFF 0
#define BT_CONV_OFF (Hh * FIN)
__device__ __nv_bfloat16 g_bthi[Hh * FIN + Ll * Hh * Hh];
__device__ __nv_bfloat16 g_btlo[Hh * FIN + Ll * Hh * Hh];
__device__ float g_dinv[Nn];
__device__ int   g_deg[Nn];
__device__ int   g_cursor[Nn];
__device__ int   g_rowoff[Nn + 1];
__device__ int   g_csr_src[Ee];
__device__ float g_csr_nrm[Ee];
__device__ double g_bsum[Ll][Hh];
__device__ double g_bsq[Ll][Hh];
__device__ int    g_aggdone[Ll];
__device__ float g_mean[Hh];
__device__ float g_rstd[Hh];
__device__ float g_wsoft[Ll];
__device__ int   g_bsums_scan[256];

// ---------------- helpers ----------------
__device__ __forceinline__ uint32_t smem_u32(const void* p) {
    uint32_t a;
    asm("{ .reg .u64 t; cvta.to.shared.u64 t, %1; cvt.u32.u64 %0, t; }" : "=r"(a) : "l"(p));
    return a;
}
__device__ __forceinline__ void cpasync16(uint32_t dst, const void* src, int szbytes) {
    asm volatile("cp.async.cg.shared.global [%0], [%1], 16, %2;"
                 :: "r"(dst), "l"(src), "r"(szbytes) : "memory");
}
#define CP_COMMIT() asm volatile("cp.async.commit_group;" ::: "memory")
#define CP_WAIT(n)  asm volatile("cp.async.wait_group %0;" :: "n"(n) : "memory")

__device__ __forceinline__ void ldsm4(uint32_t& r0, uint32_t& r1, uint32_t& r2, uint32_t& r3, uint32_t addr) {
    asm volatile("ldmatrix.sync.aligned.m8n8.x4.shared.b16 {%0,%1,%2,%3}, [%4];"
                 : "=r"(r0), "=r"(r1), "=r"(r2), "=r"(r3) : "r"(addr));
}
__device__ __forceinline__ void mma_bf16(float c[4], const uint32_t a[4], uint32_t b0, uint32_t b1) {
    asm volatile("mma.sync.aligned.m16n8k16.row.col.f32.bf16.bf16.f32 "
                 "{%0,%1,%2,%3}, {%4,%5,%6,%7}, {%8,%9}, {%0,%1,%2,%3};"
                 : "+f"(c[0]), "+f"(c[1]), "+f"(c[2]), "+f"(c[3])
                 : "r"(a[0]), "r"(a[1]), "r"(a[2]), "r"(a[3]), "r"(b0), "r"(b1));
}
__device__ __forceinline__ uint32_t bf2_pack(__nv_bfloat16 a, __nv_bfloat16 b) {
    __nv_bfloat162 t;
    t.x = a; t.y = b;
    return *reinterpret_cast<uint32_t*>(&t);
}
__device__ __forceinline__ void split_pair(float v0, float v1, uint32_t& hi, uint32_t& lo) {
    __nv_bfloat16 h0 = __float2bfloat16(v0), h1 = __float2bfloat16(v1);
    __nv_bfloat16 l0 = __float2bfloat16(v0 - __bfloat162float(h0));
    __nv_bfloat16 l1 = __float2bfloat16(v1 - __bfloat162float(h1));
    hi = bf2_pack(h0, h1);
    lo = bf2_pack(l0, l1);
}
__device__ __forceinline__ float2 unpack2(uint32_t hi, uint32_t lo) {
    __nv_bfloat162 H = *reinterpret_cast<__nv_bfloat162*>(&hi);
    __nv_bfloat162 L = *reinterpret_cast<__nv_bfloat162*>(&lo);
    return make_float2(__bfloat162float(H.x) + __bfloat162float(L.x),
                       __bfloat162float(H.y) + __bfloat162float(L.y));
}

// ---------------- bf16 split GEMM, 2 CTAs/SM ----------------
// CTA: BM=128, BN=128 (blockIdx.y = column half), BK=32, 256 threads (8 warps 4x2,
// warp tile 32x64). 3-stage cp.async pipeline. stage = Ahi 8K|Alo 8K|Bhi 8K|Blo 8K = 32KB.
#define ST_SZ   32768
#define SM_ALO  8192
#define SM_BHI  16384
#define SMEM_DYN (3 * ST_SZ)

__global__ void __launch_bounds__(256, 2)
k_gemm(const __nv_bfloat16* __restrict__ Ahi, const __nv_bfloat16* __restrict__ Alo,
       const __nv_bfloat16* __restrict__ Bhi, const __nv_bfloat16* __restrict__ Blo,
       const float* __restrict__ bias, float* __restrict__ C,
       __nv_bfloat16* __restrict__ Chi, __nv_bfloat16* __restrict__ Clo,
       int M, int K)
{
    extern __shared__ char smem[];
    uint32_t sb = smem_u32(smem);
    int tid = threadIdx.x;
    int lane = tid & 31, wid = tid >> 5;
    int wm = wid >> 1, wn = wid & 1;         // 4 x 2 warp grid
    int row0 = blockIdx.x * 128;
    int nb0 = blockIdx.y * 128;               // column block offset into BN=256 weights
    int nc = K >> 5;                          // chunks of 32

    const char* AhiC = (const char*)Ahi;
    const char* AloC = (const char*)Alo;
    const char* BhiC = (const char*)Bhi;
    const char* BloC = (const char*)Blo;

    float c[2][8][4];
#pragma unroll
    for (int mt = 0; mt < 2; mt++)
#pragma unroll
        for (int nt = 0; nt < 8; nt++)
#pragma unroll
            for (int j = 0; j < 4; j++) c[mt][nt][j] = 0.f;

    auto stage_load = [&](int s, int kc) {
        uint32_t so = sb + s * ST_SZ;
        // A: 128 rows x 32 k (64B rows, 4x16B chunks), hi+lo
#pragma unroll
        for (int j = 0; j < 2; j++) {
            int flat = tid + j * 256;
            int row = flat >> 2, cq = flat & 3;
            int grow = row0 + row;
            int sz = (grow < M) ? 16 : 0;
            int gc = (grow < M) ? grow : (M - 1);
            size_t srcoff = ((size_t)gc * K + kc * 32 + cq * 8) * 2;
            uint32_t dst = so + row * 64 + ((cq ^ ((row >> 1) & 3)) << 4);
            cpasync16(dst, AhiC + srcoff, sz);
            cpasync16(dst + SM_ALO, AloC + srcoff, sz);
        }
        // B: 128 n-rows x 32 k, hi+lo
#pragma unroll
        for (int j = 0; j < 2; j++) {
            int flat = tid + j * 256;
            int n = flat >> 2, cq = flat & 3;
            size_t srcoff = ((size_t)(nb0 + n) * K + kc * 32 + cq * 8) * 2;
            uint32_t dst = so + SM_BHI + n * 64 + ((cq ^ ((n >> 1) & 3)) << 4);
            cpasync16(dst, BhiC + srcoff, 16);
            cpasync16(dst + 8192, BloC + srcoff, 16);
        }
    };

    stage_load(0, 0);
    CP_COMMIT();
    if (nc > 1) { stage_load(1, 1); CP_COMMIT(); }

    for (int kc = 0; kc < nc; kc++) {
        if (kc + 2 < nc) {
            stage_load((kc + 2) % 3, kc + 2);
            CP_COMMIT();
            CP_WAIT(2);
        } else {
            CP_WAIT(0);
        }
        __syncthreads();

        uint32_t so = sb + (kc % 3) * ST_SZ;
#pragma unroll
        for (int ks = 0; ks < 2; ks++) {
            uint32_t ah[2][4], al[2][4];
#pragma unroll
            for (int mt = 0; mt < 2; mt++) {
                int ml = wm * 32 + mt * 16 + (lane & 7) + ((lane >> 3) & 1) * 8;
                int ck = 2 * ks + (lane >> 4);
                uint32_t ab = so + ml * 64 + ((ck ^ ((ml >> 1) & 3)) << 4);
                ldsm4(ah[mt][0], ah[mt][1], ah[mt][2], ah[mt][3], ab);
                ldsm4(al[mt][0], al[mt][1], al[mt][2], al[mt][3], ab + SM_ALO);
            }
#pragma unroll
            for (int npp = 0; npp < 2; npp++) {
                uint32_t bh[2][4], bl[2][4];
#pragma unroll
                for (int j = 0; j < 2; j++) {
                    int np = npp * 2 + j;
                    int nl = wn * 64 + np * 16 + (lane & 7) + ((lane >> 4) << 3);
                    int ck = 2 * ks + ((lane >> 3) & 1);
                    uint32_t bb = so + SM_BHI + nl * 64 + ((ck ^ ((nl >> 1) & 3)) << 4);
                    ldsm4(bh[j][0], bh[j][1], bh[j][2], bh[j][3], bb);
                    ldsm4(bl[j][0], bl[j][1], bl[j][2], bl[j][3], bb + 8192);
                }
#pragma unroll
                for (int j = 0; j < 2; j++) {
                    int nb = (npp * 2 + j) * 2;
#pragma unroll
                    for (int mt = 0; mt < 2; mt++) {
                        mma_bf16(c[mt][nb + 0], ah[mt], bh[j][0], bh[j][1]);
                        mma_bf16(c[mt][nb + 1], ah[mt], bh[j][2], bh[j][3]);
                    }
                }
#pragma unroll
                for (int j = 0; j < 2; j++) {
                    int nb = (npp * 2 + j) * 2;
#pragma unroll
                    for (int mt = 0; mt < 2; mt++) {
                        mma_bf16(c[mt][nb + 0], al[mt], bh[j][0], bh[j][1]);
                        mma_bf16(c[mt][nb + 1], al[mt], bh[j][2], bh[j][3]);
                    }
                }
#pragma unroll
                for (int j = 0; j < 2; j++) {
                    int nb = (npp * 2 + j) * 2;
#pragma unroll
                    for (int mt = 0; mt < 2; mt++) {
                        mma_bf16(c[mt][nb + 0], ah[mt], bl[j][0], bl[j][1]);
                        mma_bf16(c[mt][nb + 1], ah[mt], bl[j][2], bl[j][3]);
                    }
                }
            }
        }
        __syncthreads();
    }

#pragma unroll
    for (int mt = 0; mt < 2; mt++) {
        int r = row0 + wm * 32 + mt * 16 + (lane >> 2);
#pragma unroll
        for (int nt = 0; nt < 8; nt++) {
            int col = nb0 + wn * 64 + nt * 8 + ((lane & 3) << 1);
            float v0 = c[mt][nt][0], v1 = c[mt][nt][1];
            float v2 = c[mt][nt][2], v3 = c[mt][nt][3];
            if (bias) {
                float b0 = bias[col], b1 = bias[col + 1];
                v0 += b0; v1 += b1; v2 += b0; v3 += b1;
            }
            if (r < M) {
                size_t o = (size_t)r * Hh + col;
                *reinterpret_cast<float2*>(&C[o]) = make_float2(v0, v1);
                if (Chi) {
                    uint32_t hi, lo;
                    split_pair(v0, v1, hi, lo);
                    *reinterpret_cast<uint32_t*>(&Chi[o]) = hi;
                    *reinterpret_cast<uint32_t*>(&Clo[o]) = lo;
                }
            }
            if (r + 8 < M) {
                size_t o = (size_t)(r + 8) * Hh + col;
                *reinterpret_cast<float2*>(&C[o]) = make_float2(v2, v3);
                if (Chi) {
                    uint32_t hi, lo;
                    split_pair(v2, v3, hi, lo);
                    *reinterpret_cast<uint32_t*>(&Chi[o]) = hi;
                    *reinterpret_cast<uint32_t*>(&Clo[o]) = lo;
                }
            }
        }
    }
}

// ---------------- splits ----------------
__global__ void k_split_w(const float* __restrict__ W, __nv_bfloat16* __restrict__ hi,
                          __nv_bfloat16* __restrict__ lo, int K)
{
    int idx = blockIdx.x * 256 + threadIdx.x;
    if (idx >= Hh * K) return;
    int n = idx / K, k = idx - n * K;
    float v = W[(size_t)k * Hh + n];
    __nv_bfloat16 h = __float2bfloat16(v);
    hi[idx] = h;
    lo[idx] = __float2bfloat16(v - __bfloat162float(h));
}

__global__ void k_split_wconv(const float* __restrict__ W)
{
    int idx = blockIdx.x * 256 + threadIdx.x;
    if (idx >= Ll * Hh * Hh) return;
    int l = idx >> 16;
    int r = idx & 65535;
    int n = r >> 8, k = r & 255;
    float v = W[(size_t)l * Hh * Hh + (size_t)k * Hh + n];
    __nv_bfloat16 h = __float2bfloat16(v);
    g_bthi[BT_CONV_OFF + idx] = h;
    g_btlo[BT_CONV_OFF + idx] = __float2bfloat16(v - __bfloat162float(h));
}

__global__ void k_split_x(const float* __restrict__ x)
{
    int idx = blockIdx.x * 256 + threadIdx.x;
    if (idx >= Nn * FIN) return;
    float v = x[idx];
    __nv_bfloat16 h = __float2bfloat16(v);
    g_xhi[idx] = h;
    g_xlo[idx] = __float2bfloat16(v - __bfloat162float(h));
}

// ---------------- setup kernels ----------------
__global__ void k_zero_deg() {
    int i = blockIdx.x * blockDim.x + threadIdx.x;
    if (i < Nn) { g_deg[i] = 0; g_cursor[i] = 0; }
}
__global__ void k_count(const int* __restrict__ ei) {
    int e = blockIdx.x * blockDim.x + threadIdx.x;
    if (e < Ee) atomicAdd(&g_deg[ei[Ee + e]], 1);
}
__global__ void k_dinv() {
    int i = blockIdx.x * blockDim.x + threadIdx.x;
    if (i < Nn) g_dinv[i] = rsqrtf((float)(g_deg[i] + 1));
}
__global__ void k_scan1() {
    __shared__ int s[512];
    int i = blockIdx.x * 512 + threadIdx.x;
    int v = (i < Nn) ? g_deg[i] : 0;
    s[threadIdx.x] = v;
    __syncthreads();
    int x = v;
#pragma unroll
    for (int off = 1; off < 512; off <<= 1) {
        int t = (threadIdx.x >= off) ? s[threadIdx.x - off] : 0;
        __syncthreads();
        x += t;
        s[threadIdx.x] = x;
        __syncthreads();
    }
    if (i < Nn) g_rowoff[i] = x - v;
    if (threadIdx.x == 511) g_bsums_scan[blockIdx.x] = x;
}
__global__ void k_scan2(int nb) {
    int acc = 0;
    for (int b = 0; b < nb; b++) { int t = g_bsums_scan[b]; g_bsums_scan[b] = acc; acc += t; }
    g_rowoff[Nn] = acc;
}
__global__ void k_scan3() {
    int i = blockIdx.x * 512 + threadIdx.x;
    if (i < Nn) g_rowoff[i] += g_bsums_scan[blockIdx.x];
}
__global__ void k_scatter(const int* __restrict__ ei) {
    int e = blockIdx.x * blockDim.x + threadIdx.x;
    if (e < Ee) {
        int s = ei[e];
        int d = ei[Ee + e];
        int pos = g_rowoff[d] + atomicAdd(&g_cursor[d], 1);
        g_csr_src[pos] = s;
        g_csr_nrm[pos] = g_dinv[s] * g_dinv[d];
    }
}
__global__ void k_softmax_w(const float* __restrict__ rw) {
    float mx = -1e30f;
    for (int l = 0; l < Ll; l++) mx = fmaxf(mx, rw[l]);
    float s = 0.f;
    float e[Ll];
    for (int l = 0; l < Ll; l++) { e[l] = expf(rw[l] - mx); s += e[l]; }
    for (int l = 0; l < Ll; l++) g_wsoft[l] = e[l] / s;
}

// ---------------- aggregation + fused BN stats + last-block finalize ----------------
__global__ void __launch_bounds__(256)
k_aggregate(const float* __restrict__ hw, const float* __restrict__ cb, int layer)
{
    __shared__ float ssum[Hh], ssq[Hh];
    ssum[threadIdx.x] = 0.f;
    ssq[threadIdx.x] = 0.f;
    __syncthreads();

    int warp = threadIdx.x >> 5, lane = threadIdx.x & 31;
    float tsum[8], tsq[8];
#pragma unroll
    for (int k = 0; k < 8; k++) { tsum[k] = 0.f; tsq[k] = 0.f; }

    int base = (blockIdx.x * 8 + warp) * 4;
    for (int n = 0; n < 4; n++) {
        int i = base + n;
        if (i >= Nn) break;
        float di = g_dinv[i];
        float wself = di * di;
        const float* hrow = hw + (size_t)i * Hh;
        float acc[8];
#pragma unroll
        for (int k = 0; k < 8; k++) acc[k] = wself * hrow[lane + 32 * k];
        int e0 = g_rowoff[i], e1 = g_rowoff[i + 1];
        for (int e = e0; e < e1; e++) {
            int s = g_csr_src[e];
            float nr = g_csr_nrm[e];
            const float* srow = hw + (size_t)s * Hh;
#pragma unroll
            for (int k = 0; k < 8; k++) acc[k] += nr * srow[lane + 32 * k];
        }
#pragma unroll
        for (int k = 0; k < 8; k++) {
            float v = acc[k] + cb[lane + 32 * k];
            g_agg[(size_t)i * Hh + lane + 32 * k] = v;
            tsum[k] += v;
            tsq[k] += v * v;
        }
    }
#pragma unroll
    for (int k = 0; k < 8; k++) {
        atomicAdd(&ssum[lane + 32 * k], tsum[k]);
        atomicAdd(&ssq[lane + 32 * k], tsq[k]);
    }
    __syncthreads();
    atomicAdd(&g_bsum[layer][threadIdx.x], (double)ssum[threadIdx.x]);
    atomicAdd(&g_bsq[layer][threadIdx.x], (double)ssq[threadIdx.x]);
    __threadfence();
    __syncthreads();

    __shared__ int isLast;
    if (threadIdx.x == 0)
        isLast = (atomicAdd(&g_aggdone[layer], 1) == (int)gridDim.x - 1);
    __syncthreads();
    if (isLast) {
        __threadfence();
        int c = threadIdx.x;
        double m = g_bsum[layer][c] / (double)Nn;
        double v = g_bsq[layer][c] / (double)Nn - m * m;
        g_mean[c] = (float)m;
        g_rstd[c] = (float)(1.0 / sqrt(v + (double)BN_EPS));
        g_bsum[layer][c] = 0.0;
        g_bsq[layer][c] = 0.0;
        if (c == 0) g_aggdone[layer] = 0;
    }
}

// ---------------- BN + ReLU + residual + mix ----------------
__global__ void __launch_bounds__(256)
k_bnapply(const float* __restrict__ gamma, const float* __restrict__ beta,
          int layer, float prevCoef)
{
    int idx = blockIdx.x * blockDim.x + threadIdx.x;
    if (idx >= Nn * (Hh / 4)) return;
    int c4 = (idx & 63);
    float4 a  = reinterpret_cast<const float4*>(g_agg)[idx];
    float4 mn = reinterpret_cast<const float4*>(g_mean)[c4];
    float4 rs = reinterpret_cast<const float4*>(g_rstd)[c4];
    float4 gm = reinterpret_cast<const float4*>(gamma)[c4];
    float4 bt = reinterpret_cast<const float4*>(beta)[c4];
    float4 xi = reinterpret_cast<const float4*>(g_xin)[idx];
    uint2 hpak = reinterpret_cast<const uint2*>(g_ahi)[idx];
    uint2 lpak = reinterpret_cast<const uint2*>(g_alo)[idx];
    float2 hp01 = unpack2(hpak.x, lpak.x);
    float2 hp23 = unpack2(hpak.y, lpak.y);
    float w = g_wsoft[layer];

    float4 hn;
    hn.x = fmaxf((a.x - mn.x) * rs.x * gm.x + bt.x, 0.f) + 0.2f * xi.x + prevCoef * hp01.x;
    hn.y = fmaxf((a.y - mn.y) * rs.y * gm.y + bt.y, 0.f) + 0.2f * xi.y + prevCoef * hp01.y;
    hn.z = fmaxf((a.z - mn.z) * rs.z * gm.z + bt.z, 0.f) + 0.2f * xi.z + prevCoef * hp23.x;
    hn.w = fmaxf((a.w - mn.w) * rs.w * gm.w + bt.w, 0.f) + 0.2f * xi.w + prevCoef * hp23.y;

    uint2 nh, nl;
    split_pair(hn.x, hn.y, nh.x, nl.x);
    split_pair(hn.z, hn.w, nh.y, nl.y);
    reinterpret_cast<uint2*>(g_ahi)[idx] = nh;
    reinterpret_cast<uint2*>(g_alo)[idx] = nl;

    float4 mx;
    if (layer == 0) {
        mx.x = w * hn.x; mx.y = w * hn.y; mx.z = w * hn.z; mx.w = w * hn.w;
    } else {
        mx = reinterpret_cast<const float4*>(g_mix)[idx];
        mx.x += w * hn.x; mx.y += w * hn.y; mx.z += w * hn.z; mx.w += w * hn.w;
    }
    reinterpret_cast<float4*>(g_mix)[idx] = mx;
}

// ---------------- output: logits + log_softmax ----------------
__global__ void __launch_bounds__(256)
k_output(const float* __restrict__ mix, const float* __restrict__ ow,
         const float* __restrict__ ob, float* __restrict__ out)
{
    __shared__ float sw[Hh * 41];
    __shared__ float sb2[Cc];
    __shared__ float srow[8][48];
    for (int t = threadIdx.x; t < Hh * Cc; t += 256) {
        int k = t / Cc, c = t % Cc;
        sw[k * 41 + c] = ow[t];
    }
    if (threadIdx.x < Cc) sb2[threadIdx.x] = ob[threadIdx.x];
    __syncthreads();

    int warp = threadIdx.x >> 5, lane = threadIdx.x & 31;
    for (int row = blockIdx.x * 8 + warp; row < Nn; row += gridDim.x * 8) {
        float m[8];
#pragma unroll
        for (int j = 0; j < 8; j++) m[j] = mix[(size_t)row * Hh + lane + 32 * j];
        for (int c = 0; c < Cc; c++) {
            float p = 0.f;
#pragma unroll
            for (int j = 0; j < 8; j++) p += m[j] * sw[(lane + 32 * j) * 41 + c];
#pragma unroll
            for (int off = 16; off > 0; off >>= 1) p += __shfl_xor_sync(0xffffffffu, p, off);
            if (lane == 0) srow[warp][c] = p + sb2[c];
        }
        __syncwarp();
        float v1 = srow[warp][lane];
        float v2 = (lane < 8) ? srow[warp][32 + lane] : -1e30f;
        float mx = fmaxf(v1, v2);
#pragma unroll
        for (int off = 16; off > 0; off >>= 1) mx = fmaxf(mx, __shfl_xor_sync(0xffffffffu, mx, off));
        float s = expf(v1 - mx) + ((lane < 8) ? expf(v2 - mx) : 0.f);
#pragma unroll
        for (int off = 16; off > 0; off >>= 1) s += __shfl_xor_sync(0xffffffffu, s, off);
        float lse = mx + logf(s);
        out[(size_t)row * Cc + lane] = v1 - lse;
        if (lane < 8) out[(size_t)row * Cc + 32 + lane] = v2 - lse;
        __syncwarp();
    }
}

// ---------------- launch ----------------
extern "C" void kernel_launch(void* const* d_in, const int* in_sizes, int n_in,
                              void* d_out, int out_size)
{
    const float* x      = (const float*)d_in[0];
    const int*   ei     = (const int*)d_in[1];
    const float* w_in   = (const float*)d_in[2];
    const float* b_in   = (const float*)d_in[3];
    const float* conv_w = (const float*)d_in[4];
    const float* conv_b = (const float*)d_in[5];
    const float* bn_g   = (const float*)d_in[6];
    const float* bn_b   = (const float*)d_in[7];
    const float* out_w  = (const float*)d_in[8];
    const float* out_b  = (const float*)d_in[9];
    const float* res_w  = (const float*)d_in[10];
    float* out = (float*)d_out;

    (void)in_sizes; (void)n_in; (void)out_size;

    static cudaStream_t s2 = nullptr;
    static cudaEvent_t evFork = nullptr, evJoin = nullptr;
    if (!s2) {
        cudaStreamCreate(&s2);
        cudaEventCreateWithFlags(&evFork, cudaEventDisableTiming);
        cudaEventCreateWithFlags(&evJoin, cudaEventDisableTiming);
        cudaFuncSetAttribute(k_gemm, cudaFuncAttributeMaxDynamicSharedMemorySize, SMEM_DYN);
    }

    float *p_hw, *p_xin, *p_mix;
    __nv_bfloat16 *p_ahi, *p_alo, *p_xhi, *p_xlo, *p_bthi, *p_btlo;
    cudaGetSymbolAddress((void**)&p_hw, g_hw);
    cudaGetSymbolAddress((void**)&p_xin, g_xin);
    cudaGetSymbolAddress((void**)&p_mix, g_mix);
    cudaGetSymbolAddress((void**)&p_ahi, g_ahi);
    cudaGetSymbolAddress((void**)&p_alo, g_alo);
    cudaGetSymbolAddress((void**)&p_xhi, g_xhi);
    cudaGetSymbolAddress((void**)&p_xlo, g_xlo);
    cudaGetSymbolAddress((void**)&p_bthi, g_bthi);
    cudaGetSymbolAddress((void**)&p_btlo, g_btlo);

    dim3 gg((Nn + 127) / 128, 2);   // 782 x 2

    cudaEventRecord(evFork, 0);
    cudaStreamWaitEvent(s2, evFork, 0);

    k_split_x<<<(Nn * FIN + 255) / 256, 256>>>(x);
    k_split_w<<<(Hh * FIN + 255) / 256, 256>>>(w_in, p_bthi, p_btlo, FIN);
    k_split_wconv<<<(Ll * Hh * Hh + 255) / 256, 256>>>(conv_w);
    k_gemm<<<gg, 256, SMEM_DYN>>>(p_xhi, p_xlo, p_bthi + BT_IN_OFF, p_btlo + BT_IN_OFF,
                                  b_in, p_xin, p_ahi, p_alo, Nn, FIN);

    k_softmax_w<<<1, 1, 0, s2>>>(res_w);
    k_zero_deg<<<(Nn + 255) / 256, 256, 0, s2>>>();
    k_count<<<(Ee + 255) / 256, 256, 0, s2>>>(ei);
    k_dinv<<<(Nn + 255) / 256, 256, 0, s2>>>();
    int nsb = (Nn + 511) / 512;
    k_scan1<<<nsb, 512, 0, s2>>>();
    k_scan2<<<1, 1, 0, s2>>>(nsb);
    k_scan3<<<nsb, 512, 0, s2>>>();
    k_scatter<<<(Ee + 255) / 256, 256, 0, s2>>>(ei);
    cudaEventRecord(evJoin, s2);
    cudaStreamWaitEvent(0, evJoin, 0);

    for (int l = 0; l < Ll; l++) {
        k_gemm<<<gg, 256, SMEM_DYN>>>(p_ahi, p_alo,
                                      p_bthi + BT_CONV_OFF + (size_t)l * Hh * Hh,
                                      p_btlo + BT_CONV_OFF + (size_t)l * Hh * Hh,
                                      nullptr, p_hw, nullptr, nullptr, Nn, Hh);
        k_aggregate<<<(Nn + 31) / 32, 256>>>(p_hw, conv_b + (size_t)l * Hh, l);
        k_bnapply<<<(Nn * (Hh / 4) + 255) / 256, 256>>>(bn_g + (size_t)l * Hh, bn_b + (size_t)l * Hh,
                                                        l, (l == 0) ? 0.0f : 0.7f);
    }

    k_output<<<1563, 256>>>(p_mix, out_w, out_b, out);
}

// round 8
// speedup vs baseline: 1.5713x; 1.0213x over previous
#include <cuda_runtime.h>
#include <cuda_bf16.h>
#include <math.h>
#include <stdint.h>

#define Nn 100000
#define Ee 300000
#define Hh 256
#define Cc 40
#define Ll 6
#define FIN 128
#define BN_EPS 1e-5f

// ---------------- device scratch ----------------
__device__ float g_hw[Nn * Hh];
__device__ float g_agg[Nn * Hh];
__device__ float g_xin[Nn * Hh];
__device__ float g_mix[Nn * Hh];
__device__ __nv_bfloat16 g_ahi[Nn * Hh];
__device__ __nv_bfloat16 g_alo[Nn * Hh];
__device__ __nv_bfloat16 g_xhi[Nn * FIN];
__device__ __nv_bfloat16 g_xlo[Nn * FIN];
#define BT_IN_OFF 0
#define BT_CONV_OFF (Hh * FIN)
__device__ __nv_bfloat16 g_bthi[Hh * FIN + Ll * Hh * Hh];
__device__ __nv_bfloat16 g_btlo[Hh * FIN + Ll * Hh * Hh];
__device__ float g_dinv[Nn];
__device__ int   g_deg[Nn];
__device__ int   g_cursor[Nn];
__device__ int   g_rowoff[Nn + 1];
__device__ int   g_csr_src[Ee];
__device__ float g_csr_nrm[Ee];
__device__ double g_bsum[Ll][Hh];
__device__ double g_bsq[Ll][Hh];
__device__ int    g_aggdone[Ll];
__device__ float g_mean[Hh];
__device__ float g_rstd[Hh];
__device__ float g_wsoft[Ll];
__device__ int   g_bsums_scan[256];

// ---------------- helpers ----------------
__device__ __forceinline__ uint32_t smem_u32(const void* p) {
    uint32_t a;
    asm("{ .reg .u64 t; cvta.to.shared.u64 t, %1; cvt.u32.u64 %0, t; }" : "=r"(a) : "l"(p));
    return a;
}
__device__ __forceinline__ void cpasync16(uint32_t dst, const void* src, int szbytes) {
    asm volatile("cp.async.cg.shared.global [%0], [%1], 16, %2;"
                 :: "r"(dst), "l"(src), "r"(szbytes) : "memory");
}
#define CP_COMMIT() asm volatile("cp.async.commit_group;" ::: "memory")
#define CP_WAIT(n)  asm volatile("cp.async.wait_group %0;" :: "n"(n) : "memory")

__device__ __forceinline__ void ldsm4(uint32_t& r0, uint32_t& r1, uint32_t& r2, uint32_t& r3, uint32_t addr) {
    asm volatile("ldmatrix.sync.aligned.m8n8.x4.shared.b16 {%0,%1,%2,%3}, [%4];"
                 : "=r"(r0), "=r"(r1), "=r"(r2), "=r"(r3) : "r"(addr));
}
__device__ __forceinline__ void mma_bf16(float c[4], const uint32_t a[4], uint32_t b0, uint32_t b1) {
    asm volatile("mma.sync.aligned.m16n8k16.row.col.f32.bf16.bf16.f32 "
                 "{%0,%1,%2,%3}, {%4,%5,%6,%7}, {%8,%9}, {%0,%1,%2,%3};"
                 : "+f"(c[0]), "+f"(c[1]), "+f"(c[2]), "+f"(c[3])
                 : "r"(a[0]), "r"(a[1]), "r"(a[2]), "r"(a[3]), "r"(b0), "r"(b1));
}
__device__ __forceinline__ uint32_t bf2_pack(__nv_bfloat16 a, __nv_bfloat16 b) {
    __nv_bfloat162 t;
    t.x = a; t.y = b;
    return *reinterpret_cast<uint32_t*>(&t);
}
__device__ __forceinline__ void split_pair(float v0, float v1, uint32_t& hi, uint32_t& lo) {
    __nv_bfloat16 h0 = __float2bfloat16(v0), h1 = __float2bfloat16(v1);
    __nv_bfloat16 l0 = __float2bfloat16(v0 - __bfloat162float(h0));
    __nv_bfloat16 l1 = __float2bfloat16(v1 - __bfloat162float(h1));
    hi = bf2_pack(h0, h1);
    lo = bf2_pack(l0, l1);
}
__device__ __forceinline__ float2 unpack2(uint32_t hi, uint32_t lo) {
    __nv_bfloat162 H = *reinterpret_cast<__nv_bfloat162*>(&hi);
    __nv_bfloat162 L = *reinterpret_cast<__nv_bfloat162*>(&lo);
    return make_float2(__bfloat162float(H.x) + __bfloat162float(L.x),
                       __bfloat162float(H.y) + __bfloat162float(L.y));
}

// ---------------- bf16 split GEMM, 3 CTAs/SM ----------------
// CTA: BM=128, BN=64 (gridDim.x = 4 column blocks -> adjacent blocks share A in L2),
// BK=32, 256 threads (8 warps 4m x 2n), warp tile 32x32.
// 3-stage cp.async pipeline; stage = Ahi 8K | Alo 8K | Bhi 4K | Blo 4K = 24KB.
#define ST_SZ   24576
#define SM_ALO  8192
#define SM_BHI  16384
#define SM_BLO  20480
#define SMEM_DYN (3 * ST_SZ)

__global__ void __launch_bounds__(256, 3)
k_gemm(const __nv_bfloat16* __restrict__ Ahi, const __nv_bfloat16* __restrict__ Alo,
       const __nv_bfloat16* __restrict__ Bhi, const __nv_bfloat16* __restrict__ Blo,
       const float* __restrict__ bias, float* __restrict__ C,
       __nv_bfloat16* __restrict__ Chi, __nv_bfloat16* __restrict__ Clo,
       int M, int K)
{
    extern __shared__ char smem[];
    uint32_t sb = smem_u32(smem);
    int tid = threadIdx.x;
    int lane = tid & 31, wid = tid >> 5;
    int wm = wid >> 1, wn = wid & 1;          // 4m x 2n warp grid
    int row0 = blockIdx.y * 128;
    int nb0 = blockIdx.x * 64;                // column block (x fastest -> A reuse in L2)
    int nc = K >> 5;

    const char* AhiC = (const char*)Ahi;
    const char* AloC = (const char*)Alo;
    const char* BhiC = (const char*)Bhi;
    const char* BloC = (const char*)Blo;

    float c[2][4][4];
#pragma unroll
    for (int mt = 0; mt < 2; mt++)
#pragma unroll
        for (int nt = 0; nt < 4; nt++)
#pragma unroll
            for (int j = 0; j < 4; j++) c[mt][nt][j] = 0.f;

    auto stage_load = [&](int s, int kc) {
        uint32_t so = sb + s * ST_SZ;
        // A: 128 rows x 32 k (64B rows, 4 x 16B chunks), hi+lo
#pragma unroll
        for (int j = 0; j < 2; j++) {
            int flat = tid + j * 256;
            int row = flat >> 2, cq = flat & 3;
            int grow = row0 + row;
            int sz = (grow < M) ? 16 : 0;
            int gc = (grow < M) ? grow : (M - 1);
            size_t srcoff = ((size_t)gc * K + kc * 32 + cq * 8) * 2;
            uint32_t dst = so + row * 64 + ((cq ^ ((row >> 1) & 3)) << 4);
            cpasync16(dst, AhiC + srcoff, sz);
            cpasync16(dst + SM_ALO, AloC + srcoff, sz);
        }
        // B: 64 n-rows x 32 k, hi+lo (one pass, 256 threads)
        {
            int n = tid >> 2, cq = tid & 3;
            size_t srcoff = ((size_t)(nb0 + n) * K + kc * 32 + cq * 8) * 2;
            uint32_t dst = so + SM_BHI + n * 64 + ((cq ^ ((n >> 1) & 3)) << 4);
            cpasync16(dst, BhiC + srcoff, 16);
            cpasync16(dst + 4096, BloC + srcoff, 16);
        }
    };

    stage_load(0, 0);
    CP_COMMIT();
    if (nc > 1) { stage_load(1, 1); CP_COMMIT(); }

    for (int kc = 0; kc < nc; kc++) {
        if (kc + 2 < nc) {
            stage_load((kc + 2) % 3, kc + 2);
            CP_COMMIT();
            CP_WAIT(2);
        } else {
            CP_WAIT(0);
        }
        __syncthreads();

        uint32_t so = sb + (kc % 3) * ST_SZ;
#pragma unroll
        for (int ks = 0; ks < 2; ks++) {
            uint32_t ah[2][4], al[2][4];
#pragma unroll
            for (int mt = 0; mt < 2; mt++) {
                int ml = wm * 32 + mt * 16 + (lane & 7) + ((lane >> 3) & 1) * 8;
                int ck = 2 * ks + (lane >> 4);
                uint32_t ab = so + ml * 64 + ((ck ^ ((ml >> 1) & 3)) << 4);
                ldsm4(ah[mt][0], ah[mt][1], ah[mt][2], ah[mt][3], ab);
                ldsm4(al[mt][0], al[mt][1], al[mt][2], al[mt][3], ab + SM_ALO);
            }
            uint32_t bh[2][4], bl[2][4];
#pragma unroll
            for (int j = 0; j < 2; j++) {
                int nl = wn * 32 + j * 16 + (lane & 7) + ((lane >> 4) << 3);
                int ck = 2 * ks + ((lane >> 3) & 1);
                uint32_t bb = so + SM_BHI + nl * 64 + ((ck ^ ((nl >> 1) & 3)) << 4);
                ldsm4(bh[j][0], bh[j][1], bh[j][2], bh[j][3], bb);
                ldsm4(bl[j][0], bl[j][1], bl[j][2], bl[j][3], bb + 4096);
            }
            // term 1: ah * bh   (8 independent mmas per block)
#pragma unroll
            for (int j = 0; j < 2; j++) {
                int nb = j * 2;
#pragma unroll
                for (int mt = 0; mt < 2; mt++) {
                    mma_bf16(c[mt][nb + 0], ah[mt], bh[j][0], bh[j][1]);
                    mma_bf16(c[mt][nb + 1], ah[mt], bh[j][2], bh[j][3]);
                }
            }
            // term 2: al * bh
#pragma unroll
            for (int j = 0; j < 2; j++) {
                int nb = j * 2;
#pragma unroll
                for (int mt = 0; mt < 2; mt++) {
                    mma_bf16(c[mt][nb + 0], al[mt], bh[j][0], bh[j][1]);
                    mma_bf16(c[mt][nb + 1], al[mt], bh[j][2], bh[j][3]);
                }
            }
            // term 3: ah * bl
#pragma unroll
            for (int j = 0; j < 2; j++) {
                int nb = j * 2;
#pragma unroll
                for (int mt = 0; mt < 2; mt++) {
                    mma_bf16(c[mt][nb + 0], ah[mt], bl[j][0], bl[j][1]);
                    mma_bf16(c[mt][nb + 1], ah[mt], bl[j][2], bl[j][3]);
                }
            }
        }
        __syncthreads();
    }

#pragma unroll
    for (int mt = 0; mt < 2; mt++) {
        int r = row0 + wm * 32 + mt * 16 + (lane >> 2);
#pragma unroll
        for (int nt = 0; nt < 4; nt++) {
            int col = nb0 + wn * 32 + nt * 8 + ((lane & 3) << 1);
            float v0 = c[mt][nt][0], v1 = c[mt][nt][1];
            float v2 = c[mt][nt][2], v3 = c[mt][nt][3];
            if (bias) {
                float b0 = bias[col], b1 = bias[col + 1];
                v0 += b0; v1 += b1; v2 += b0; v3 += b1;
            }
            if (r < M) {
                size_t o = (size_t)r * Hh + col;
                *reinterpret_cast<float2*>(&C[o]) = make_float2(v0, v1);
                if (Chi) {
                    uint32_t hi, lo;
                    split_pair(v0, v1, hi, lo);
                    *reinterpret_cast<uint32_t*>(&Chi[o]) = hi;
                    *reinterpret_cast<uint32_t*>(&Clo[o]) = lo;
                }
            }
            if (r + 8 < M) {
                size_t o = (size_t)(r + 8) * Hh + col;
                *reinterpret_cast<float2*>(&C[o]) = make_float2(v2, v3);
                if (Chi) {
                    uint32_t hi, lo;
                    split_pair(v2, v3, hi, lo);
                    *reinterpret_cast<uint32_t*>(&Chi[o]) = hi;
                    *reinterpret_cast<uint32_t*>(&Clo[o]) = lo;
                }
            }
        }
    }
}

// ---------------- splits ----------------
__global__ void k_split_w(const float* __restrict__ W, __nv_bfloat16* __restrict__ hi,
                          __nv_bfloat16* __restrict__ lo, int K)
{
    int idx = blockIdx.x * 256 + threadIdx.x;
    if (idx >= Hh * K) return;
    int n = idx / K, k = idx - n * K;
    float v = W[(size_t)k * Hh + n];
    __nv_bfloat16 h = __float2bfloat16(v);
    hi[idx] = h;
    lo[idx] = __float2bfloat16(v - __bfloat162float(h));
}

__global__ void k_split_wconv(const float* __restrict__ W)
{
    int idx = blockIdx.x * 256 + threadIdx.x;
    if (idx >= Ll * Hh * Hh) return;
    int l = idx >> 16;
    int r = idx & 65535;
    int n = r >> 8, k = r & 255;
    float v = W[(size_t)l * Hh * Hh + (size_t)k * Hh + n];
    __nv_bfloat16 h = __float2bfloat16(v);
    g_bthi[BT_CONV_OFF + idx] = h;
    g_btlo[BT_CONV_OFF + idx] = __float2bfloat16(v - __bfloat162float(h));
}

__global__ void k_split_x(const float* __restrict__ x)
{
    int idx = blockIdx.x * 256 + threadIdx.x;
    if (idx >= Nn * FIN) return;
    float v = x[idx];
    __nv_bfloat16 h = __float2bfloat16(v);
    g_xhi[idx] = h;
    g_xlo[idx] = __float2bfloat16(v - __bfloat162float(h));
}

// ---------------- setup kernels ----------------
__global__ void k_zero_deg() {
    int i = blockIdx.x * blockDim.x + threadIdx.x;
    if (i < Nn) { g_deg[i] = 0; g_cursor[i] = 0; }
}
__global__ void k_count(const int* __restrict__ ei) {
    int e = blockIdx.x * blockDim.x + threadIdx.x;
    if (e < Ee) atomicAdd(&g_deg[ei[Ee + e]], 1);
}
__global__ void k_dinv() {
    int i = blockIdx.x * blockDim.x + threadIdx.x;
    if (i < Nn) g_dinv[i] = rsqrtf((float)(g_deg[i] + 1));
}
__global__ void k_scan1() {
    __shared__ int s[512];
    int i = blockIdx.x * 512 + threadIdx.x;
    int v = (i < Nn) ? g_deg[i] : 0;
    s[threadIdx.x] = v;
    __syncthreads();
    int x = v;
#pragma unroll
    for (int off = 1; off < 512; off <<= 1) {
        int t = (threadIdx.x >= off) ? s[threadIdx.x - off] : 0;
        __syncthreads();
        x += t;
        s[threadIdx.x] = x;
        __syncthreads();
    }
    if (i < Nn) g_rowoff[i] = x - v;
    if (threadIdx.x == 511) g_bsums_scan[blockIdx.x] = x;
}
__global__ void k_scan2(int nb) {
    int acc = 0;
    for (int b = 0; b < nb; b++) { int t = g_bsums_scan[b]; g_bsums_scan[b] = acc; acc += t; }
    g_rowoff[Nn] = acc;
}
__global__ void k_scan3() {
    int i = blockIdx.x * 512 + threadIdx.x;
    if (i < Nn) g_rowoff[i] += g_bsums_scan[blockIdx.x];
}
__global__ void k_scatter(const int* __restrict__ ei) {
    int e = blockIdx.x * blockDim.x + threadIdx.x;
    if (e < Ee) {
        int s = ei[e];
        int d = ei[Ee + e];
        int pos = g_rowoff[d] + atomicAdd(&g_cursor[d], 1);
        g_csr_src[pos] = s;
        g_csr_nrm[pos] = g_dinv[s] * g_dinv[d];
    }
}
__global__ void k_softmax_w(const float* __restrict__ rw) {
    float mx = -1e30f;
    for (int l = 0; l < Ll; l++) mx = fmaxf(mx, rw[l]);
    float s = 0.f;
    float e[Ll];
    for (int l = 0; l < Ll; l++) { e[l] = expf(rw[l] - mx); s += e[l]; }
    for (int l = 0; l < Ll; l++) g_wsoft[l] = e[l] / s;
}

// ---------------- aggregation + fused BN stats + last-block finalize ----------------
__global__ void __launch_bounds__(256)
k_aggregate(const float* __restrict__ hw, const float* __restrict__ cb, int layer)
{
    __shared__ float ssum[Hh], ssq[Hh];
    ssum[threadIdx.x] = 0.f;
    ssq[threadIdx.x] = 0.f;
    __syncthreads();

    int warp = threadIdx.x >> 5, lane = threadIdx.x & 31;
    float tsum[8], tsq[8];
#pragma unroll
    for (int k = 0; k < 8; k++) { tsum[k] = 0.f; tsq[k] = 0.f; }

    int base = (blockIdx.x * 8 + warp) * 4;
    for (int n = 0; n < 4; n++) {
        int i = base + n;
        if (i >= Nn) break;
        float di = g_dinv[i];
        float wself = di * di;
        const float* hrow = hw + (size_t)i * Hh;
        float acc[8];
#pragma unroll
        for (int k = 0; k < 8; k++) acc[k] = wself * hrow[lane + 32 * k];
        int e0 = g_rowoff[i], e1 = g_rowoff[i + 1];
        for (int e = e0; e < e1; e++) {
            int s = g_csr_src[e];
            float nr = g_csr_nrm[e];
            const float* srow = hw + (size_t)s * Hh;
#pragma unroll
            for (int k = 0; k < 8; k++) acc[k] += nr * srow[lane + 32 * k];
        }
#pragma unroll
        for (int k = 0; k < 8; k++) {
            float v = acc[k] + cb[lane + 32 * k];
            g_agg[(size_t)i * Hh + lane + 32 * k] = v;
            tsum[k] += v;
            tsq[k] += v * v;
        }
    }
#pragma unroll
    for (int k = 0; k < 8; k++) {
        atomicAdd(&ssum[lane + 32 * k], tsum[k]);
        atomicAdd(&ssq[lane + 32 * k], tsq[k]);
    }
    __syncthreads();
    atomicAdd(&g_bsum[layer][threadIdx.x], (double)ssum[threadIdx.x]);
    atomicAdd(&g_bsq[layer][threadIdx.x], (double)ssq[threadIdx.x]);
    __threadfence();
    __syncthreads();

    __shared__ int isLast;
    if (threadIdx.x == 0)
        isLast = (atomicAdd(&g_aggdone[layer], 1) == (int)gridDim.x - 1);
    __syncthreads();
    if (isLast) {
        __threadfence();
        int c = threadIdx.x;
        double m = g_bsum[layer][c] / (double)Nn;
        double v = g_bsq[layer][c] / (double)Nn - m * m;
        g_mean[c] = (float)m;
        g_rstd[c] = (float)(1.0 / sqrt(v + (double)BN_EPS));
        g_bsum[layer][c] = 0.0;
        g_bsq[layer][c] = 0.0;
        if (c == 0) g_aggdone[layer] = 0;
    }
}

// ---------------- BN + ReLU + residual + mix ----------------
__global__ void __launch_bounds__(256)
k_bnapply(const float* __restrict__ gamma, const float* __restrict__ beta,
          int layer, float prevCoef)
{
    int idx = blockIdx.x * blockDim.x + threadIdx.x;
    if (idx >= Nn * (Hh / 4)) return;
    int c4 = (idx & 63);
    float4 a  = reinterpret_cast<const float4*>(g_agg)[idx];
    float4 mn = reinterpret_cast<const float4*>(g_mean)[c4];
    float4 rs = reinterpret_cast<const float4*>(g_rstd)[c4];
    float4 gm = reinterpret_cast<const float4*>(gamma)[c4];
    float4 bt = reinterpret_cast<const float4*>(beta)[c4];
    float4 xi = reinterpret_cast<const float4*>(g_xin)[idx];
    uint2 hpak = reinterpret_cast<const uint2*>(g_ahi)[idx];
    uint2 lpak = reinterpret_cast<const uint2*>(g_alo)[idx];
    float2 hp01 = unpack2(hpak.x, lpak.x);
    float2 hp23 = unpack2(hpak.y, lpak.y);
    float w = g_wsoft[layer];

    float4 hn;
    hn.x = fmaxf((a.x - mn.x) * rs.x * gm.x + bt.x, 0.f) + 0.2f * xi.x + prevCoef * hp01.x;
    hn.y = fmaxf((a.y - mn.y) * rs.y * gm.y + bt.y, 0.f) + 0.2f * xi.y + prevCoef * hp01.y;
    hn.z = fmaxf((a.z - mn.z) * rs.z * gm.z + bt.z, 0.f) + 0.2f * xi.z + prevCoef * hp23.x;
    hn.w = fmaxf((a.w - mn.w) * rs.w * gm.w + bt.w, 0.f) + 0.2f * xi.w + prevCoef * hp23.y;

    uint2 nh, nl;
    split_pair(hn.x, hn.y, nh.x, nl.x);
    split_pair(hn.z, hn.w, nh.y, nl.y);
    reinterpret_cast<uint2*>(g_ahi)[idx] = nh;
    reinterpret_cast<uint2*>(g_alo)[idx] = nl;

    float4 mx;
    if (layer == 0) {
        mx.x = w * hn.x; mx.y = w * hn.y; mx.z = w * hn.z; mx.w = w * hn.w;
    } else {
        mx = reinterpret_cast<const float4*>(g_mix)[idx];
        mx.x += w * hn.x; mx.y += w * hn.y; mx.z += w * hn.z; mx.w += w * hn.w;
    }
    reinterpret_cast<float4*>(g_mix)[idx] = mx;
}

// ---------------- output: logits + log_softmax ----------------
__global__ void __launch_bounds__(256)
k_output(const float* __restrict__ mix, const float* __restrict__ ow,
         const float* __restrict__ ob, float* __restrict__ out)
{
    __shared__ float sw[Hh * 41];
    __shared__ float sb2[Cc];
    __shared__ float srow[8][48];
    for (int t = threadIdx.x; t < Hh * Cc; t += 256) {
        int k = t / Cc, c = t % Cc;
        sw[k * 41 + c] = ow[t];
    }
    if (threadIdx.x < Cc) sb2[threadIdx.x] = ob[threadIdx.x];
    __syncthreads();

    int warp = threadIdx.x >> 5, lane = threadIdx.x & 31;
    for (int row = blockIdx.x * 8 + warp; row < Nn; row += gridDim.x * 8) {
        float m[8];
#pragma unroll
        for (int j = 0; j < 8; j++) m[j] = mix[(size_t)row * Hh + lane + 32 * j];
        for (int c = 0; c < Cc; c++) {
            float p = 0.f;
#pragma unroll
            for (int j = 0; j < 8; j++) p += m[j] * sw[(lane + 32 * j) * 41 + c];
#pragma unroll
            for (int off = 16; off > 0; off >>= 1) p += __shfl_xor_sync(0xffffffffu, p, off);
            if (lane == 0) srow[warp][c] = p + sb2[c];
        }
        __syncwarp();
        float v1 = srow[warp][lane];
        float v2 = (lane < 8) ? srow[warp][32 + lane] : -1e30f;
        float mx = fmaxf(v1, v2);
#pragma unroll
        for (int off = 16; off > 0; off >>= 1) mx = fmaxf(mx, __shfl_xor_sync(0xffffffffu, mx, off));
        float s = expf(v1 - mx) + ((lane < 8) ? expf(v2 - mx) : 0.f);
#pragma unroll
        for (int off = 16; off > 0; off >>= 1) s += __shfl_xor_sync(0xffffffffu, s, off);
        float lse = mx + logf(s);
        out[(size_t)row * Cc + lane] = v1 - lse;
        if (lane < 8) out[(size_t)row * Cc + 32 + lane] = v2 - lse;
        __syncwarp();
    }
}

// ---------------- launch ----------------
extern "C" void kernel_launch(void* const* d_in, const int* in_sizes, int n_in,
                              void* d_out, int out_size)
{
    const float* x      = (const float*)d_in[0];
    const int*   ei     = (const int*)d_in[1];
    const float* w_in   = (const float*)d_in[2];
    const float* b_in   = (const float*)d_in[3];
    const float* conv_w = (const float*)d_in[4];
    const float* conv_b = (const float*)d_in[5];
    const float* bn_g   = (const float*)d_in[6];
    const float* bn_b   = (const float*)d_in[7];
    const float* out_w  = (const float*)d_in[8];
    const float* out_b  = (const float*)d_in[9];
    const float* res_w  = (const float*)d_in[10];
    float* out = (float*)d_out;

    (void)in_sizes; (void)n_in; (void)out_size;

    static cudaStream_t s2 = nullptr;
    static cudaEvent_t evFork = nullptr, evJoin = nullptr;
    if (!s2) {
        cudaStreamCreate(&s2);
        cudaEventCreateWithFlags(&evFork, cudaEventDisableTiming);
        cudaEventCreateWithFlags(&evJoin, cudaEventDisableTiming);
        cudaFuncSetAttribute(k_gemm, cudaFuncAttributeMaxDynamicSharedMemorySize, SMEM_DYN);
    }

    float *p_hw, *p_xin, *p_mix;
    __nv_bfloat16 *p_ahi, *p_alo, *p_xhi, *p_xlo, *p_bthi, *p_btlo;
    cudaGetSymbolAddress((void**)&p_hw, g_hw);
    cudaGetSymbolAddress((void**)&p_xin, g_xin);
    cudaGetSymbolAddress((void**)&p_mix, g_mix);
    cudaGetSymbolAddress((void**)&p_ahi, g_ahi);
    cudaGetSymbolAddress((void**)&p_alo, g_alo);
    cudaGetSymbolAddress((void**)&p_xhi, g_xhi);
    cudaGetSymbolAddress((void**)&p_xlo, g_xlo);
    cudaGetSymbolAddress((void**)&p_bthi, g_bthi);
    cudaGetSymbolAddress((void**)&p_btlo, g_btlo);

    dim3 gg(4, (Nn + 127) / 128);   // 4 column blocks x 782 row blocks

    cudaEventRecord(evFork, 0);
    cudaStreamWaitEvent(s2, evFork, 0);

    k_split_x<<<(Nn * FIN + 255) / 256, 256>>>(x);
    k_split_w<<<(Hh * FIN + 255) / 256, 256>>>(w_in, p_bthi, p_btlo, FIN);
    k_split_wconv<<<(Ll * Hh * Hh + 255) / 256, 256>>>(conv_w);
    k_gemm<<<gg, 256, SMEM_DYN>>>(p_xhi, p_xlo, p_bthi + BT_IN_OFF, p_btlo + BT_IN_OFF,
                                  b_in, p_xin, p_ahi, p_alo, Nn, FIN);

    k_softmax_w<<<1, 1, 0, s2>>>(res_w);
    k_zero_deg<<<(Nn + 255) / 256, 256, 0, s2>>>();
    k_count<<<(Ee + 255) / 256, 256, 0, s2>>>(ei);
    k_dinv<<<(Nn + 255) / 256, 256, 0, s2>>>();
    int nsb = (Nn + 511) / 512;
    k_scan1<<<nsb, 512, 0, s2>>>();
    k_scan2<<<1, 1, 0, s2>>>(nsb);
    k_scan3<<<nsb, 512, 0, s2>>>();
    k_scatter<<<(Ee + 255) / 256, 256, 0, s2>>>(ei);
    cudaEventRecord(evJoin, s2);
    cudaStreamWaitEvent(0, evJoin, 0);

    for (int l = 0; l < Ll; l++) {
        k_gemm<<<gg, 256, SMEM_DYN>>>(p_ahi, p_alo,
                                      p_bthi + BT_CONV_OFF + (size_t)l * Hh * Hh,
                                      p_btlo + BT_CONV_OFF + (size_t)l * Hh * Hh,
                                      nullptr, p_hw, nullptr, nullptr, Nn, Hh);
        k_aggregate<<<(Nn + 31) / 32, 256>>>(p_hw, conv_b + (size_t)l * Hh, l);
        k_bnapply<<<(Nn * (Hh / 4) + 255) / 256, 256>>>(bn_g + (size_t)l * Hh, bn_b + (size_t)l * Hh,
                                                        l, (l == 0) ? 0.0f : 0.7f);
    }

    k_output<<<1563, 256>>>(p_mix, out_w, out_b, out);
}

// round 9
// speedup vs baseline: 1.6578x; 1.0550x over previous
#include <cuda_runtime.h>
#include <cuda_bf16.h>
#include <cuda_fp16.h>
#include <math.h>
#include <stdint.h>

#define Nn 100000
#define Ee 300000
#define Hh 256
#define Cc 40
#define Ll 6
#define FIN 128
#define BN_EPS 1e-5f

// ---------------- device scratch ----------------
__device__ float g_hw[Nn * Hh];
__device__ float g_agg[Nn * Hh];
__device__ float g_xin[Nn * Hh];
__device__ __half g_ap[Ll][Nn * Hh];       // a' = relu(bn) per layer, fp16
__device__ __nv_bfloat16 g_ahi[Nn * Hh];
__device__ __nv_bfloat16 g_alo[Nn * Hh];
__device__ __nv_bfloat16 g_xhi[Nn * FIN];
__device__ __nv_bfloat16 g_xlo[Nn * FIN];
#define BT_IN_OFF 0
#define BT_CONV_OFF (Hh * FIN)
__device__ __nv_bfloat16 g_bthi[Hh * FIN + Ll * Hh * Hh];
__device__ __nv_bfloat16 g_btlo[Hh * FIN + Ll * Hh * Hh];
__device__ float g_dinv[Nn];
__device__ int   g_deg[Nn];
__device__ int   g_cursor[Nn];
__device__ int   g_rowoff[Nn + 1];
__device__ int   g_csr_src[Ee];
__device__ float g_csr_nrm[Ee];
__device__ double g_bsum[Ll][Hh];
__device__ double g_bsq[Ll][Hh];
__device__ int    g_aggdone[Ll];
__device__ float g_mean[Hh];
__device__ float g_rstd[Hh];
__device__ float g_cm[Ll];                  // mix coefficients per layer
__device__ float g_xc;                      // coefficient on x in mix
__device__ int   g_bsums_scan[256];

// ---------------- helpers ----------------
__device__ __forceinline__ uint32_t smem_u32(const void* p) {
    uint32_t a;
    asm("{ .reg .u64 t; cvta.to.shared.u64 t, %1; cvt.u32.u64 %0, t; }" : "=r"(a) : "l"(p));
    return a;
}
__device__ __forceinline__ void cpasync16(uint32_t dst, const void* src, int szbytes) {
    asm volatile("cp.async.cg.shared.global [%0], [%1], 16, %2;"
                 :: "r"(dst), "l"(src), "r"(szbytes) : "memory");
}
#define CP_COMMIT() asm volatile("cp.async.commit_group;" ::: "memory")
#define CP_WAIT(n)  asm volatile("cp.async.wait_group %0;" :: "n"(n) : "memory")

__device__ __forceinline__ void ldsm4(uint32_t& r0, uint32_t& r1, uint32_t& r2, uint32_t& r3, uint32_t addr) {
    asm volatile("ldmatrix.sync.aligned.m8n8.x4.shared.b16 {%0,%1,%2,%3}, [%4];"
                 : "=r"(r0), "=r"(r1), "=r"(r2), "=r"(r3) : "r"(addr));
}
__device__ __forceinline__ void mma_bf16(float c[4], const uint32_t a[4], uint32_t b0, uint32_t b1) {
    asm volatile("mma.sync.aligned.m16n8k16.row.col.f32.bf16.bf16.f32 "
                 "{%0,%1,%2,%3}, {%4,%5,%6,%7}, {%8,%9}, {%0,%1,%2,%3};"
                 : "+f"(c[0]), "+f"(c[1]), "+f"(c[2]), "+f"(c[3])
                 : "r"(a[0]), "r"(a[1]), "r"(a[2]), "r"(a[3]), "r"(b0), "r"(b1));
}
__device__ __forceinline__ uint32_t bf2_pack(__nv_bfloat16 a, __nv_bfloat16 b) {
    __nv_bfloat162 t;
    t.x = a; t.y = b;
    return *reinterpret_cast<uint32_t*>(&t);
}
__device__ __forceinline__ void split_pair(float v0, float v1, uint32_t& hi, uint32_t& lo) {
    __nv_bfloat16 h0 = __float2bfloat16(v0), h1 = __float2bfloat16(v1);
    __nv_bfloat16 l0 = __float2bfloat16(v0 - __bfloat162float(h0));
    __nv_bfloat16 l1 = __float2bfloat16(v1 - __bfloat162float(h1));
    hi = bf2_pack(h0, h1);
    lo = bf2_pack(l0, l1);
}
__device__ __forceinline__ float2 unpack2(uint32_t hi, uint32_t lo) {
    __nv_bfloat162 H = *reinterpret_cast<__nv_bfloat162*>(&hi);
    __nv_bfloat162 L = *reinterpret_cast<__nv_bfloat162*>(&lo);
    return make_float2(__bfloat162float(H.x) + __bfloat162float(L.x),
                       __bfloat162float(H.y) + __bfloat162float(L.y));
}

// ---------------- bf16 split GEMM, 3 CTAs/SM (unchanged from round 8) ----------------
#define ST_SZ   24576
#define SM_ALO  8192
#define SM_BHI  16384
#define SMEM_DYN (3 * ST_SZ)

__global__ void __launch_bounds__(256, 3)
k_gemm(const __nv_bfloat16* __restrict__ Ahi, const __nv_bfloat16* __restrict__ Alo,
       const __nv_bfloat16* __restrict__ Bhi, const __nv_bfloat16* __restrict__ Blo,
       const float* __restrict__ bias, float* __restrict__ C,
       __nv_bfloat16* __restrict__ Chi, __nv_bfloat16* __restrict__ Clo,
       int M, int K)
{
    extern __shared__ char smem[];
    uint32_t sb = smem_u32(smem);
    int tid = threadIdx.x;
    int lane = tid & 31, wid = tid >> 5;
    int wm = wid >> 1, wn = wid & 1;
    int row0 = blockIdx.y * 128;
    int nb0 = blockIdx.x * 64;
    int nc = K >> 5;

    const char* AhiC = (const char*)Ahi;
    const char* AloC = (const char*)Alo;
    const char* BhiC = (const char*)Bhi;
    const char* BloC = (const char*)Blo;

    float c[2][4][4];
#pragma unroll
    for (int mt = 0; mt < 2; mt++)
#pragma unroll
        for (int nt = 0; nt < 4; nt++)
#pragma unroll
            for (int j = 0; j < 4; j++) c[mt][nt][j] = 0.f;

    auto stage_load = [&](int s, int kc) {
        uint32_t so = sb + s * ST_SZ;
#pragma unroll
        for (int j = 0; j < 2; j++) {
            int flat = tid + j * 256;
            int row = flat >> 2, cq = flat & 3;
            int grow = row0 + row;
            int sz = (grow < M) ? 16 : 0;
            int gc = (grow < M) ? grow : (M - 1);
            size_t srcoff = ((size_t)gc * K + kc * 32 + cq * 8) * 2;
            uint32_t dst = so + row * 64 + ((cq ^ ((row >> 1) & 3)) << 4);
            cpasync16(dst, AhiC + srcoff, sz);
            cpasync16(dst + SM_ALO, AloC + srcoff, sz);
        }
        {
            int n = tid >> 2, cq = tid & 3;
            size_t srcoff = ((size_t)(nb0 + n) * K + kc * 32 + cq * 8) * 2;
            uint32_t dst = so + SM_BHI + n * 64 + ((cq ^ ((n >> 1) & 3)) << 4);
            cpasync16(dst, BhiC + srcoff, 16);
            cpasync16(dst + 4096, BloC + srcoff, 16);
        }
    };

    stage_load(0, 0);
    CP_COMMIT();
    if (nc > 1) { stage_load(1, 1); CP_COMMIT(); }

    for (int kc = 0; kc < nc; kc++) {
        if (kc + 2 < nc) {
            stage_load((kc + 2) % 3, kc + 2);
            CP_COMMIT();
            CP_WAIT(2);
        } else {
            CP_WAIT(0);
        }
        __syncthreads();

        uint32_t so = sb + (kc % 3) * ST_SZ;
#pragma unroll
        for (int ks = 0; ks < 2; ks++) {
            uint32_t ah[2][4], al[2][4];
#pragma unroll
            for (int mt = 0; mt < 2; mt++) {
                int ml = wm * 32 + mt * 16 + (lane & 7) + ((lane >> 3) & 1) * 8;
                int ck = 2 * ks + (lane >> 4);
                uint32_t ab = so + ml * 64 + ((ck ^ ((ml >> 1) & 3)) << 4);
                ldsm4(ah[mt][0], ah[mt][1], ah[mt][2], ah[mt][3], ab);
                ldsm4(al[mt][0], al[mt][1], al[mt][2], al[mt][3], ab + SM_ALO);
            }
            uint32_t bh[2][4], bl[2][4];
#pragma unroll
            for (int j = 0; j < 2; j++) {
                int nl = wn * 32 + j * 16 + (lane & 7) + ((lane >> 4) << 3);
                int ck = 2 * ks + ((lane >> 3) & 1);
                uint32_t bb = so + SM_BHI + nl * 64 + ((ck ^ ((nl >> 1) & 3)) << 4);
                ldsm4(bh[j][0], bh[j][1], bh[j][2], bh[j][3], bb);
                ldsm4(bl[j][0], bl[j][1], bl[j][2], bl[j][3], bb + 4096);
            }
#pragma unroll
            for (int j = 0; j < 2; j++) {
                int nb = j * 2;
#pragma unroll
                for (int mt = 0; mt < 2; mt++) {
                    mma_bf16(c[mt][nb + 0], ah[mt], bh[j][0], bh[j][1]);
                    mma_bf16(c[mt][nb + 1], ah[mt], bh[j][2], bh[j][3]);
                }
            }
#pragma unroll
            for (int j = 0; j < 2; j++) {
                int nb = j * 2;
#pragma unroll
                for (int mt = 0; mt < 2; mt++) {
                    mma_bf16(c[mt][nb + 0], al[mt], bh[j][0], bh[j][1]);
                    mma_bf16(c[mt][nb + 1], al[mt], bh[j][2], bh[j][3]);
                }
            }
#pragma unroll
            for (int j = 0; j < 2; j++) {
                int nb = j * 2;
#pragma unroll
                for (int mt = 0; mt < 2; mt++) {
                    mma_bf16(c[mt][nb + 0], ah[mt], bl[j][0], bl[j][1]);
                    mma_bf16(c[mt][nb + 1], ah[mt], bl[j][2], bl[j][3]);
                }
            }
        }
        __syncthreads();
    }

#pragma unroll
    for (int mt = 0; mt < 2; mt++) {
        int r = row0 + wm * 32 + mt * 16 + (lane >> 2);
#pragma unroll
        for (int nt = 0; nt < 4; nt++) {
            int col = nb0 + wn * 32 + nt * 8 + ((lane & 3) << 1);
            float v0 = c[mt][nt][0], v1 = c[mt][nt][1];
            float v2 = c[mt][nt][2], v3 = c[mt][nt][3];
            if (bias) {
                float b0 = bias[col], b1 = bias[col + 1];
                v0 += b0; v1 += b1; v2 += b0; v3 += b1;
            }
            if (r < M) {
                size_t o = (size_t)r * Hh + col;
                *reinterpret_cast<float2*>(&C[o]) = make_float2(v0, v1);
                if (Chi) {
                    uint32_t hi, lo;
                    split_pair(v0, v1, hi, lo);
                    *reinterpret_cast<uint32_t*>(&Chi[o]) = hi;
                    *reinterpret_cast<uint32_t*>(&Clo[o]) = lo;
                }
            }
            if (r + 8 < M) {
                size_t o = (size_t)(r + 8) * Hh + col;
                *reinterpret_cast<float2*>(&C[o]) = make_float2(v2, v3);
                if (Chi) {
                    uint32_t hi, lo;
                    split_pair(v2, v3, hi, lo);
                    *reinterpret_cast<uint32_t*>(&Chi[o]) = hi;
                    *reinterpret_cast<uint32_t*>(&Clo[o]) = lo;
                }
            }
        }
    }
}

// ---------------- splits ----------------
__global__ void k_split_w(const float* __restrict__ W, __nv_bfloat16* __restrict__ hi,
                          __nv_bfloat16* __restrict__ lo, int K)
{
    int idx = blockIdx.x * 256 + threadIdx.x;
    if (idx >= Hh * K) return;
    int n = idx / K, k = idx - n * K;
    float v = W[(size_t)k * Hh + n];
    __nv_bfloat16 h = __float2bfloat16(v);
    hi[idx] = h;
    lo[idx] = __float2bfloat16(v - __bfloat162float(h));
}

__global__ void k_split_wconv(const float* __restrict__ W)
{
    int idx = blockIdx.x * 256 + threadIdx.x;
    if (idx >= Ll * Hh * Hh) return;
    int l = idx >> 16;
    int r = idx & 65535;
    int n = r >> 8, k = r & 255;
    float v = W[(size_t)l * Hh * Hh + (size_t)k * Hh + n];
    __nv_bfloat16 h = __float2bfloat16(v);
    g_bthi[BT_CONV_OFF + idx] = h;
    g_btlo[BT_CONV_OFF + idx] = __float2bfloat16(v - __bfloat162float(h));
}

__global__ void k_split_x(const float* __restrict__ x)
{
    int idx = blockIdx.x * 256 + threadIdx.x;
    if (idx >= Nn * FIN) return;
    float v = x[idx];
    __nv_bfloat16 h = __float2bfloat16(v);
    g_xhi[idx] = h;
    g_xlo[idx] = __float2bfloat16(v - __bfloat162float(h));
}

// ---------------- setup kernels ----------------
__global__ void k_zero_deg() {
    int i = blockIdx.x * blockDim.x + threadIdx.x;
    if (i < Nn) { g_deg[i] = 0; g_cursor[i] = 0; }
}
__global__ void k_count(const int* __restrict__ ei) {
    int e = blockIdx.x * blockDim.x + threadIdx.x;
    if (e < Ee) atomicAdd(&g_deg[ei[Ee + e]], 1);
}
__global__ void k_dinv() {
    int i = blockIdx.x * blockDim.x + threadIdx.x;
    if (i < Nn) g_dinv[i] = rsqrtf((float)(g_deg[i] + 1));
}
__global__ void k_scan1() {
    __shared__ int s[512];
    int i = blockIdx.x * 512 + threadIdx.x;
    int v = (i < Nn) ? g_deg[i] : 0;
    s[threadIdx.x] = v;
    __syncthreads();
    int x = v;
#pragma unroll
    for (int off = 1; off < 512; off <<= 1) {
        int t = (threadIdx.x >= off) ? s[threadIdx.x - off] : 0;
        __syncthreads();
        x += t;
        s[threadIdx.x] = x;
        __syncthreads();
    }
    if (i < Nn) g_rowoff[i] = x - v;
    if (threadIdx.x == 511) g_bsums_scan[blockIdx.x] = x;
}
__global__ void k_scan2(int nb) {
    int acc = 0;
    for (int b = 0; b < nb; b++) { int t = g_bsums_scan[b]; g_bsums_scan[b] = acc; acc += t; }
    g_rowoff[Nn] = acc;
}
__global__ void k_scan3() {
    int i = blockIdx.x * 512 + threadIdx.x;
    if (i < Nn) g_rowoff[i] += g_bsums_scan[blockIdx.x];
}
__global__ void k_scatter(const int* __restrict__ ei) {
    int e = blockIdx.x * blockDim.x + threadIdx.x;
    if (e < Ee) {
        int s = ei[e];
        int d = ei[Ee + e];
        int pos = g_rowoff[d] + atomicAdd(&g_cursor[d], 1);
        g_csr_src[pos] = s;
        g_csr_nrm[pos] = g_dinv[s] * g_dinv[d];
    }
}
__global__ void k_softmax_w(const float* __restrict__ rw) {
    float mx = -1e30f;
    for (int l = 0; l < Ll; l++) mx = fmaxf(mx, rw[l]);
    float s = 0.f;
    float w[Ll];
    for (int l = 0; l < Ll; l++) { w[l] = expf(rw[l] - mx); s += w[l]; }
    for (int l = 0; l < Ll; l++) w[l] /= s;
    // c_m = sum_{l>=m} w_l * 0.7^{l-m};  mix = sum_m c_m a'_m + 0.2*(sum_m c_m)*x
    float csum = 0.f;
    for (int m = 0; m < Ll; m++) {
        float c = 0.f, p = 1.f;
        for (int l = m; l < Ll; l++) { c += w[l] * p; p *= 0.7f; }
        g_cm[m] = c;
        csum += c;
    }
    g_xc = 0.2f * csum;
}

// ---------------- aggregation + fused BN stats + last-block finalize ----------------
__global__ void __launch_bounds__(256)
k_aggregate(const float* __restrict__ hw, const float* __restrict__ cb, int layer)
{
    __shared__ float ssum[Hh], ssq[Hh];
    ssum[threadIdx.x] = 0.f;
    ssq[threadIdx.x] = 0.f;
    __syncthreads();

    int warp = threadIdx.x >> 5, lane = threadIdx.x & 31;
    float tsum[8], tsq[8];
#pragma unroll
    for (int k = 0; k < 8; k++) { tsum[k] = 0.f; tsq[k] = 0.f; }

    int base = (blockIdx.x * 8 + warp) * 4;
    for (int n = 0; n < 4; n++) {
        int i = base + n;
        if (i >= Nn) break;
        float di = g_dinv[i];
        float wself = di * di;
        const float* hrow = hw + (size_t)i * Hh;
        float acc[8];
#pragma unroll
        for (int k = 0; k < 8; k++) acc[k] = wself * hrow[lane + 32 * k];
        int e0 = g_rowoff[i], e1 = g_rowoff[i + 1];
        for (int e = e0; e < e1; e++) {
            int s = g_csr_src[e];
            float nr = g_csr_nrm[e];
            const float* srow = hw + (size_t)s * Hh;
#pragma unroll
            for (int k = 0; k < 8; k++) acc[k] += nr * srow[lane + 32 * k];
        }
#pragma unroll
        for (int k = 0; k < 8; k++) {
            float v = acc[k] + cb[lane + 32 * k];
            g_agg[(size_t)i * Hh + lane + 32 * k] = v;
            tsum[k] += v;
            tsq[k] += v * v;
        }
    }
#pragma unroll
    for (int k = 0; k < 8; k++) {
        atomicAdd(&ssum[lane + 32 * k], tsum[k]);
        atomicAdd(&ssq[lane + 32 * k], tsq[k]);
    }
    __syncthreads();
    atomicAdd(&g_bsum[layer][threadIdx.x], (double)ssum[threadIdx.x]);
    atomicAdd(&g_bsq[layer][threadIdx.x], (double)ssq[threadIdx.x]);
    __threadfence();
    __syncthreads();

    __shared__ int isLast;
    if (threadIdx.x == 0)
        isLast = (atomicAdd(&g_aggdone[layer], 1) == (int)gridDim.x - 1);
    __syncthreads();
    if (isLast) {
        __threadfence();
        int c = threadIdx.x;
        double m = g_bsum[layer][c] / (double)Nn;
        double v = g_bsq[layer][c] / (double)Nn - m * m;
        g_mean[c] = (float)m;
        g_rstd[c] = (float)(1.0 / sqrt(v + (double)BN_EPS));
        g_bsum[layer][c] = 0.0;
        g_bsq[layer][c] = 0.0;
        if (c == 0) g_aggdone[layer] = 0;
    }
}

// ---------------- BN + ReLU + residual; a' stored fp16, mix handled at output ----------------
__global__ void __launch_bounds__(256)
k_bnapply(const float* __restrict__ gamma, const float* __restrict__ beta,
          int layer, float prevCoef, int writeH)
{
    int idx = blockIdx.x * blockDim.x + threadIdx.x;
    if (idx >= Nn * (Hh / 4)) return;
    int c4 = (idx & 63);
    float4 a  = reinterpret_cast<const float4*>(g_agg)[idx];
    float4 mn = reinterpret_cast<const float4*>(g_mean)[c4];
    float4 rs = reinterpret_cast<const float4*>(g_rstd)[c4];
    float4 gm = reinterpret_cast<const float4*>(gamma)[c4];
    float4 bt = reinterpret_cast<const float4*>(beta)[c4];

    float4 ap;
    ap.x = fmaxf((a.x - mn.x) * rs.x * gm.x + bt.x, 0.f);
    ap.y = fmaxf((a.y - mn.y) * rs.y * gm.y + bt.y, 0.f);
    ap.z = fmaxf((a.z - mn.z) * rs.z * gm.z + bt.z, 0.f);
    ap.w = fmaxf((a.w - mn.w) * rs.w * gm.w + bt.w, 0.f);

    // store a' as fp16 (feeds mix reconstruction at output)
    __half2* apst = reinterpret_cast<__half2*>(&g_ap[layer][0]);
    apst[idx * 2]     = __floats2half2_rn(ap.x, ap.y);
    apst[idx * 2 + 1] = __floats2half2_rn(ap.z, ap.w);

    if (writeH) {
        float4 xi = reinterpret_cast<const float4*>(g_xin)[idx];
        uint2 hpak = reinterpret_cast<const uint2*>(g_ahi)[idx];
        uint2 lpak = reinterpret_cast<const uint2*>(g_alo)[idx];
        float2 hp01 = unpack2(hpak.x, lpak.x);
        float2 hp23 = unpack2(hpak.y, lpak.y);

        float4 hn;
        hn.x = ap.x + 0.2f * xi.x + prevCoef * hp01.x;
        hn.y = ap.y + 0.2f * xi.y + prevCoef * hp01.y;
        hn.z = ap.z + 0.2f * xi.z + prevCoef * hp23.x;
        hn.w = ap.w + 0.2f * xi.w + prevCoef * hp23.y;

        uint2 nh, nl;
        split_pair(hn.x, hn.y, nh.x, nl.x);
        split_pair(hn.z, hn.w, nh.y, nl.y);
        reinterpret_cast<uint2*>(g_ahi)[idx] = nh;
        reinterpret_cast<uint2*>(g_alo)[idx] = nl;
    }
}

// ---------------- output: mix reconstruction + logits + log_softmax ----------------
__global__ void __launch_bounds__(256)
k_output(const float* __restrict__ ow, const float* __restrict__ ob, float* __restrict__ out)
{
    __shared__ float sw[Hh * 41];
    __shared__ float sb2[Cc];
    __shared__ float srow[8][48];
    for (int t = threadIdx.x; t < Hh * Cc; t += 256) {
        int k = t / Cc, c = t % Cc;
        sw[k * 41 + c] = ow[t];
    }
    if (threadIdx.x < Cc) sb2[threadIdx.x] = ob[threadIdx.x];
    __syncthreads();

    float cm[Ll], xc;
#pragma unroll
    for (int l = 0; l < Ll; l++) cm[l] = g_cm[l];
    xc = g_xc;

    int warp = threadIdx.x >> 5, lane = threadIdx.x & 31;
    for (int row = blockIdx.x * 8 + warp; row < Nn; row += gridDim.x * 8) {
        float m[8];
#pragma unroll
        for (int j = 0; j < 8; j++) {
            size_t o = (size_t)row * Hh + lane + 32 * j;
            float v = xc * g_xin[o];
#pragma unroll
            for (int l = 0; l < Ll; l++)
                v += cm[l] * __half2float(g_ap[l][o]);
            m[j] = v;
        }
        for (int c = 0; c < Cc; c++) {
            float p = 0.f;
#pragma unroll
            for (int j = 0; j < 8; j++) p += m[j] * sw[(lane + 32 * j) * 41 + c];
#pragma unroll
            for (int off = 16; off > 0; off >>= 1) p += __shfl_xor_sync(0xffffffffu, p, off);
            if (lane == 0) srow[warp][c] = p + sb2[c];
        }
        __syncwarp();
        float v1 = srow[warp][lane];
        float v2 = (lane < 8) ? srow[warp][32 + lane] : -1e30f;
        float mx = fmaxf(v1, v2);
#pragma unroll
        for (int off = 16; off > 0; off >>= 1) mx = fmaxf(mx, __shfl_xor_sync(0xffffffffu, mx, off));
        float s = expf(v1 - mx) + ((lane < 8) ? expf(v2 - mx) : 0.f);
#pragma unroll
        for (int off = 16; off > 0; off >>= 1) s += __shfl_xor_sync(0xffffffffu, s, off);
        float lse = mx + logf(s);
        out[(size_t)row * Cc + lane] = v1 - lse;
        if (lane < 8) out[(size_t)row * Cc + 32 + lane] = v2 - lse;
        __syncwarp();
    }
}

// ---------------- launch ----------------
extern "C" void kernel_launch(void* const* d_in, const int* in_sizes, int n_in,
                              void* d_out, int out_size)
{
    const float* x      = (const float*)d_in[0];
    const int*   ei     = (const int*)d_in[1];
    const float* w_in   = (const float*)d_in[2];
    const float* b_in   = (const float*)d_in[3];
    const float* conv_w = (const float*)d_in[4];
    const float* conv_b = (const float*)d_in[5];
    const float* bn_g   = (const float*)d_in[6];
    const float* bn_b   = (const float*)d_in[7];
    const float* out_w  = (const float*)d_in[8];
    const float* out_b  = (const float*)d_in[9];
    const float* res_w  = (const float*)d_in[10];
    float* out = (float*)d_out;

    (void)in_sizes; (void)n_in; (void)out_size;

    static cudaStream_t s2 = nullptr;
    static cudaEvent_t evFork = nullptr, evJoin = nullptr;
    if (!s2) {
        cudaStreamCreate(&s2);
        cudaEventCreateWithFlags(&evFork, cudaEventDisableTiming);
        cudaEventCreateWithFlags(&evJoin, cudaEventDisableTiming);
        cudaFuncSetAttribute(k_gemm, cudaFuncAttributeMaxDynamicSharedMemorySize, SMEM_DYN);
    }

    float *p_hw, *p_xin;
    __nv_bfloat16 *p_ahi, *p_alo, *p_xhi, *p_xlo, *p_bthi, *p_btlo;
    cudaGetSymbolAddress((void**)&p_hw, g_hw);
    cudaGetSymbolAddress((void**)&p_xin, g_xin);
    cudaGetSymbolAddress((void**)&p_ahi, g_ahi);
    cudaGetSymbolAddress((void**)&p_alo, g_alo);
    cudaGetSymbolAddress((void**)&p_xhi, g_xhi);
    cudaGetSymbolAddress((void**)&p_xlo, g_xlo);
    cudaGetSymbolAddress((void**)&p_bthi, g_bthi);
    cudaGetSymbolAddress((void**)&p_btlo, g_btlo);

    dim3 gg(4, (Nn + 127) / 128);

    cudaEventRecord(evFork, 0);
    cudaStreamWaitEvent(s2, evFork, 0);

    k_split_x<<<(Nn * FIN + 255) / 256, 256>>>(x);
    k_split_w<<<(Hh * FIN + 255) / 256, 256>>>(w_in, p_bthi, p_btlo, FIN);
    k_split_wconv<<<(Ll * Hh * Hh + 255) / 256, 256>>>(conv_w);
    k_gemm<<<gg, 256, SMEM_DYN>>>(p_xhi, p_xlo, p_bthi + BT_IN_OFF, p_btlo + BT_IN_OFF,
                                  b_in, p_xin, p_ahi, p_alo, Nn, FIN);

    k_softmax_w<<<1, 1, 0, s2>>>(res_w);
    k_zero_deg<<<(Nn + 255) / 256, 256, 0, s2>>>();
    k_count<<<(Ee + 255) / 256, 256, 0, s2>>>(ei);
    k_dinv<<<(Nn + 255) / 256, 256, 0, s2>>>();
    int nsb = (Nn + 511) / 512;
    k_scan1<<<nsb, 512, 0, s2>>>();
    k_scan2<<<1, 1, 0, s2>>>(nsb);
    k_scan3<<<nsb, 512, 0, s2>>>();
    k_scatter<<<(Ee + 255) / 256, 256, 0, s2>>>(ei);
    cudaEventRecord(evJoin, s2);
    cudaStreamWaitEvent(0, evJoin, 0);

    for (int l = 0; l < Ll; l++) {
        k_gemm<<<gg, 256, SMEM_DYN>>>(p_ahi, p_alo,
                                      p_bthi + BT_CONV_OFF + (size_t)l * Hh * Hh,
                                      p_btlo + BT_CONV_OFF + (size_t)l * Hh * Hh,
                                      nullptr, p_hw, nullptr, nullptr, Nn, Hh);
        k_aggregate<<<(Nn + 31) / 32, 256>>>(p_hw, conv_b + (size_t)l * Hh, l);
        k_bnapply<<<(Nn * (Hh / 4) + 255) / 256, 256>>>(bn_g + (size_t)l * Hh, bn_b + (size_t)l * Hh,
                                                        l, (l == 0) ? 0.0f : 0.7f,
                                                        (l < Ll - 1) ? 1 : 0);
    }

    k_output<<<1563, 256>>>(out_w, out_b, out);
}

// round 10
// speedup vs baseline: 1.7996x; 1.0856x over previous
#include <cuda_runtime.h>
#include <cuda_bf16.h>
#include <cuda_fp16.h>
#include <math.h>
#include <stdint.h>

#define Nn 100000
#define Ee 300000
#define Hh 256
#define Cc 40
#define Ll 6
#define FIN 128
#define BN_EPS 1e-5f

// ---------------- device scratch ----------------
__device__ __half g_hw[Nn * Hh];           // h @ W (fp16)
__device__ __half g_agg[Nn * Hh];          // aggregated messages (fp16)
__device__ __half g_xin[Nn * Hh];          // x_input (fp16)
__device__ __half g_ap[Ll][Nn * Hh];       // a' = relu(bn) per layer (fp16)
__device__ __nv_bfloat16 g_ahi[Nn * Hh];
__device__ __nv_bfloat16 g_alo[Nn * Hh];
__device__ __nv_bfloat16 g_xhi[Nn * FIN];
__device__ __nv_bfloat16 g_xlo[Nn * FIN];
#define BT_IN_OFF 0
#define BT_CONV_OFF (Hh * FIN)
__device__ __nv_bfloat16 g_bthi[Hh * FIN + Ll * Hh * Hh];
__device__ __nv_bfloat16 g_btlo[Hh * FIN + Ll * Hh * Hh];
__device__ float g_dinv[Nn];
__device__ int   g_deg[Nn];
__device__ int   g_cursor[Nn];
__device__ int   g_rowoff[Nn + 1];
__device__ int   g_csr_src[Ee];
__device__ float g_csr_nrm[Ee];
__device__ double g_bsum[Ll][Hh];
__device__ double g_bsq[Ll][Hh];
__device__ int    g_aggdone[Ll];
__device__ float g_mean[Hh];
__device__ float g_rstd[Hh];
__device__ float g_cm[Ll];
__device__ float g_xc;
__device__ int   g_bsums_scan[256];

// ---------------- helpers ----------------
__device__ __forceinline__ uint32_t smem_u32(const void* p) {
    uint32_t a;
    asm("{ .reg .u64 t; cvta.to.shared.u64 t, %1; cvt.u32.u64 %0, t; }" : "=r"(a) : "l"(p));
    return a;
}
__device__ __forceinline__ void cpasync16(uint32_t dst, const void* src, int szbytes) {
    asm volatile("cp.async.cg.shared.global [%0], [%1], 16, %2;"
                 :: "r"(dst), "l"(src), "r"(szbytes) : "memory");
}
#define CP_COMMIT() asm volatile("cp.async.commit_group;" ::: "memory")
#define CP_WAIT(n)  asm volatile("cp.async.wait_group %0;" :: "n"(n) : "memory")

__device__ __forceinline__ void ldsm4(uint32_t& r0, uint32_t& r1, uint32_t& r2, uint32_t& r3, uint32_t addr) {
    asm volatile("ldmatrix.sync.aligned.m8n8.x4.shared.b16 {%0,%1,%2,%3}, [%4];"
                 : "=r"(r0), "=r"(r1), "=r"(r2), "=r"(r3) : "r"(addr));
}
__device__ __forceinline__ void mma_bf16(float c[4], const uint32_t a[4], uint32_t b0, uint32_t b1) {
    asm volatile("mma.sync.aligned.m16n8k16.row.col.f32.bf16.bf16.f32 "
                 "{%0,%1,%2,%3}, {%4,%5,%6,%7}, {%8,%9}, {%0,%1,%2,%3};"
                 : "+f"(c[0]), "+f"(c[1]), "+f"(c[2]), "+f"(c[3])
                 : "r"(a[0]), "r"(a[1]), "r"(a[2]), "r"(a[3]), "r"(b0), "r"(b1));
}
__device__ __forceinline__ uint32_t bf2_pack(__nv_bfloat16 a, __nv_bfloat16 b) {
    __nv_bfloat162 t;
    t.x = a; t.y = b;
    return *reinterpret_cast<uint32_t*>(&t);
}
__device__ __forceinline__ void split_pair(float v0, float v1, uint32_t& hi, uint32_t& lo) {
    __nv_bfloat16 h0 = __float2bfloat16(v0), h1 = __float2bfloat16(v1);
    __nv_bfloat16 l0 = __float2bfloat16(v0 - __bfloat162float(h0));
    __nv_bfloat16 l1 = __float2bfloat16(v1 - __bfloat162float(h1));
    hi = bf2_pack(h0, h1);
    lo = bf2_pack(l0, l1);
}
__device__ __forceinline__ float2 unpack2(uint32_t hi, uint32_t lo) {
    __nv_bfloat162 H = *reinterpret_cast<__nv_bfloat162*>(&hi);
    __nv_bfloat162 L = *reinterpret_cast<__nv_bfloat162*>(&lo);
    return make_float2(__bfloat162float(H.x) + __bfloat162float(L.x),
                       __bfloat162float(H.y) + __bfloat162float(L.y));
}

// ---------------- bf16 split GEMM, 3 CTAs/SM (core unchanged; C now fp16) ----------------
#define ST_SZ   24576
#define SM_ALO  8192
#define SM_BHI  16384
#define SMEM_DYN (3 * ST_SZ)

__global__ void __launch_bounds__(256, 3)
k_gemm(const __nv_bfloat16* __restrict__ Ahi, const __nv_bfloat16* __restrict__ Alo,
       const __nv_bfloat16* __restrict__ Bhi, const __nv_bfloat16* __restrict__ Blo,
       const float* __restrict__ bias, __half* __restrict__ C,
       __nv_bfloat16* __restrict__ Chi, __nv_bfloat16* __restrict__ Clo,
       int M, int K)
{
    extern __shared__ char smem[];
    uint32_t sb = smem_u32(smem);
    int tid = threadIdx.x;
    int lane = tid & 31, wid = tid >> 5;
    int wm = wid >> 1, wn = wid & 1;
    int row0 = blockIdx.y * 128;
    int nb0 = blockIdx.x * 64;
    int nc = K >> 5;

    const char* AhiC = (const char*)Ahi;
    const char* AloC = (const char*)Alo;
    const char* BhiC = (const char*)Bhi;
    const char* BloC = (const char*)Blo;

    float c[2][4][4];
#pragma unroll
    for (int mt = 0; mt < 2; mt++)
#pragma unroll
        for (int nt = 0; nt < 4; nt++)
#pragma unroll
            for (int j = 0; j < 4; j++) c[mt][nt][j] = 0.f;

    auto stage_load = [&](int s, int kc) {
        uint32_t so = sb + s * ST_SZ;
#pragma unroll
        for (int j = 0; j < 2; j++) {
            int flat = tid + j * 256;
            int row = flat >> 2, cq = flat & 3;
            int grow = row0 + row;
            int sz = (grow < M) ? 16 : 0;
            int gc = (grow < M) ? grow : (M - 1);
            size_t srcoff = ((size_t)gc * K + kc * 32 + cq * 8) * 2;
            uint32_t dst = so + row * 64 + ((cq ^ ((row >> 1) & 3)) << 4);
            cpasync16(dst, AhiC + srcoff, sz);
            cpasync16(dst + SM_ALO, AloC + srcoff, sz);
        }
        {
            int n = tid >> 2, cq = tid & 3;
            size_t srcoff = ((size_t)(nb0 + n) * K + kc * 32 + cq * 8) * 2;
            uint32_t dst = so + SM_BHI + n * 64 + ((cq ^ ((n >> 1) & 3)) << 4);
            cpasync16(dst, BhiC + srcoff, 16);
            cpasync16(dst + 4096, BloC + srcoff, 16);
        }
    };

    stage_load(0, 0);
    CP_COMMIT();
    if (nc > 1) { stage_load(1, 1); CP_COMMIT(); }

    for (int kc = 0; kc < nc; kc++) {
        if (kc + 2 < nc) {
            stage_load((kc + 2) % 3, kc + 2);
            CP_COMMIT();
            CP_WAIT(2);
        } else {
            CP_WAIT(0);
        }
        __syncthreads();

        uint32_t so = sb + (kc % 3) * ST_SZ;
#pragma unroll
        for (int ks = 0; ks < 2; ks++) {
            uint32_t ah[2][4], al[2][4];
#pragma unroll
            for (int mt = 0; mt < 2; mt++) {
                int ml = wm * 32 + mt * 16 + (lane & 7) + ((lane >> 3) & 1) * 8;
                int ck = 2 * ks + (lane >> 4);
                uint32_t ab = so + ml * 64 + ((ck ^ ((ml >> 1) & 3)) << 4);
                ldsm4(ah[mt][0], ah[mt][1], ah[mt][2], ah[mt][3], ab);
                ldsm4(al[mt][0], al[mt][1], al[mt][2], al[mt][3], ab + SM_ALO);
            }
            uint32_t bh[2][4], bl[2][4];
#pragma unroll
            for (int j = 0; j < 2; j++) {
                int nl = wn * 32 + j * 16 + (lane & 7) + ((lane >> 4) << 3);
                int ck = 2 * ks + ((lane >> 3) & 1);
                uint32_t bb = so + SM_BHI + nl * 64 + ((ck ^ ((nl >> 1) & 3)) << 4);
                ldsm4(bh[j][0], bh[j][1], bh[j][2], bh[j][3], bb);
                ldsm4(bl[j][0], bl[j][1], bl[j][2], bl[j][3], bb + 4096);
            }
#pragma unroll
            for (int j = 0; j < 2; j++) {
                int nb = j * 2;
#pragma unroll
                for (int mt = 0; mt < 2; mt++) {
                    mma_bf16(c[mt][nb + 0], ah[mt], bh[j][0], bh[j][1]);
                    mma_bf16(c[mt][nb + 1], ah[mt], bh[j][2], bh[j][3]);
                }
            }
#pragma unroll
            for (int j = 0; j < 2; j++) {
                int nb = j * 2;
#pragma unroll
                for (int mt = 0; mt < 2; mt++) {
                    mma_bf16(c[mt][nb + 0], al[mt], bh[j][0], bh[j][1]);
                    mma_bf16(c[mt][nb + 1], al[mt], bh[j][2], bh[j][3]);
                }
            }
#pragma unroll
            for (int j = 0; j < 2; j++) {
                int nb = j * 2;
#pragma unroll
                for (int mt = 0; mt < 2; mt++) {
                    mma_bf16(c[mt][nb + 0], ah[mt], bl[j][0], bl[j][1]);
                    mma_bf16(c[mt][nb + 1], ah[mt], bl[j][2], bl[j][3]);
                }
            }
        }
        __syncthreads();
    }

#pragma unroll
    for (int mt = 0; mt < 2; mt++) {
        int r = row0 + wm * 32 + mt * 16 + (lane >> 2);
#pragma unroll
        for (int nt = 0; nt < 4; nt++) {
            int col = nb0 + wn * 32 + nt * 8 + ((lane & 3) << 1);
            float v0 = c[mt][nt][0], v1 = c[mt][nt][1];
            float v2 = c[mt][nt][2], v3 = c[mt][nt][3];
            if (bias) {
                float b0 = bias[col], b1 = bias[col + 1];
                v0 += b0; v1 += b1; v2 += b0; v3 += b1;
            }
            if (r < M) {
                size_t o = (size_t)r * Hh + col;
                *reinterpret_cast<__half2*>(&C[o]) = __floats2half2_rn(v0, v1);
                if (Chi) {
                    uint32_t hi, lo;
                    split_pair(v0, v1, hi, lo);
                    *reinterpret_cast<uint32_t*>(&Chi[o]) = hi;
                    *reinterpret_cast<uint32_t*>(&Clo[o]) = lo;
                }
            }
            if (r + 8 < M) {
                size_t o = (size_t)(r + 8) * Hh + col;
                *reinterpret_cast<__half2*>(&C[o]) = __floats2half2_rn(v2, v3);
                if (Chi) {
                    uint32_t hi, lo;
                    split_pair(v2, v3, hi, lo);
                    *reinterpret_cast<uint32_t*>(&Chi[o]) = hi;
                    *reinterpret_cast<uint32_t*>(&Clo[o]) = lo;
                }
            }
        }
    }
}

// ---------------- splits ----------------
__global__ void k_split_w(const float* __restrict__ W, __nv_bfloat16* __restrict__ hi,
                          __nv_bfloat16* __restrict__ lo, int K)
{
    int idx = blockIdx.x * 256 + threadIdx.x;
    if (idx >= Hh * K) return;
    int n = idx / K, k = idx - n * K;
    float v = W[(size_t)k * Hh + n];
    __nv_bfloat16 h = __float2bfloat16(v);
    hi[idx] = h;
    lo[idx] = __float2bfloat16(v - __bfloat162float(h));
}

__global__ void k_split_wconv(const float* __restrict__ W)
{
    int idx = blockIdx.x * 256 + threadIdx.x;
    if (idx >= Ll * Hh * Hh) return;
    int l = idx >> 16;
    int r = idx & 65535;
    int n = r >> 8, k = r & 255;
    float v = W[(size_t)l * Hh * Hh + (size_t)k * Hh + n];
    __nv_bfloat16 h = __float2bfloat16(v);
    g_bthi[BT_CONV_OFF + idx] = h;
    g_btlo[BT_CONV_OFF + idx] = __float2bfloat16(v - __bfloat162float(h));
}

__global__ void k_split_x(const float* __restrict__ x)
{
    int idx = blockIdx.x * 256 + threadIdx.x;
    if (idx >= Nn * FIN) return;
    float v = x[idx];
    __nv_bfloat16 h = __float2bfloat16(v);
    g_xhi[idx] = h;
    g_xlo[idx] = __float2bfloat16(v - __bfloat162float(h));
}

// ---------------- setup kernels ----------------
__global__ void k_zero_deg() {
    int i = blockIdx.x * blockDim.x + threadIdx.x;
    if (i < Nn) { g_deg[i] = 0; g_cursor[i] = 0; }
}
__global__ void k_count(const int* __restrict__ ei) {
    int e = blockIdx.x * blockDim.x + threadIdx.x;
    if (e < Ee) atomicAdd(&g_deg[ei[Ee + e]], 1);
}
__global__ void k_dinv() {
    int i = blockIdx.x * blockDim.x + threadIdx.x;
    if (i < Nn) g_dinv[i] = rsqrtf((float)(g_deg[i] + 1));
}
__global__ void k_scan1() {
    __shared__ int s[512];
    int i = blockIdx.x * 512 + threadIdx.x;
    int v = (i < Nn) ? g_deg[i] : 0;
    s[threadIdx.x] = v;
    __syncthreads();
    int x = v;
#pragma unroll
    for (int off = 1; off < 512; off <<= 1) {
        int t = (threadIdx.x >= off) ? s[threadIdx.x - off] : 0;
        __syncthreads();
        x += t;
        s[threadIdx.x] = x;
        __syncthreads();
    }
    if (i < Nn) g_rowoff[i] = x - v;
    if (threadIdx.x == 511) g_bsums_scan[blockIdx.x] = x;
}
__global__ void k_scan2(int nb) {
    int acc = 0;
    for (int b = 0; b < nb; b++) { int t = g_bsums_scan[b]; g_bsums_scan[b] = acc; acc += t; }
    g_rowoff[Nn] = acc;
}
__global__ void k_scan3() {
    int i = blockIdx.x * 512 + threadIdx.x;
    if (i < Nn) g_rowoff[i] += g_bsums_scan[blockIdx.x];
}
__global__ void k_scatter(const int* __restrict__ ei) {
    int e = blockIdx.x * blockDim.x + threadIdx.x;
    if (e < Ee) {
        int s = ei[e];
        int d = ei[Ee + e];
        int pos = g_rowoff[d] + atomicAdd(&g_cursor[d], 1);
        g_csr_src[pos] = s;
        g_csr_nrm[pos] = g_dinv[s] * g_dinv[d];
    }
}
__global__ void k_softmax_w(const float* __restrict__ rw) {
    float mx = -1e30f;
    for (int l = 0; l < Ll; l++) mx = fmaxf(mx, rw[l]);
    float s = 0.f;
    float w[Ll];
    for (int l = 0; l < Ll; l++) { w[l] = expf(rw[l] - mx); s += w[l]; }
    for (int l = 0; l < Ll; l++) w[l] /= s;
    float csum = 0.f;
    for (int m = 0; m < Ll; m++) {
        float c = 0.f, p = 1.f;
        for (int l = m; l < Ll; l++) { c += w[l] * p; p *= 0.7f; }
        g_cm[m] = c;
        csum += c;
    }
    g_xc = 0.2f * csum;
}

// ---------------- aggregation (fp16 hw) + fused BN stats + last-block finalize ----------------
__global__ void __launch_bounds__(256)
k_aggregate(const __half* __restrict__ hw, const float* __restrict__ cb, int layer)
{
    __shared__ float ssum[Hh], ssq[Hh];
    ssum[threadIdx.x] = 0.f;
    ssq[threadIdx.x] = 0.f;
    __syncthreads();

    int warp = threadIdx.x >> 5, lane = threadIdx.x & 31;
    float tsum[8], tsq[8];
#pragma unroll
    for (int k = 0; k < 8; k++) { tsum[k] = 0.f; tsq[k] = 0.f; }

    float cbv[8];
#pragma unroll
    for (int j = 0; j < 4; j++) {
        int col = 2 * (lane + 32 * j);
        cbv[2 * j] = cb[col];
        cbv[2 * j + 1] = cb[col + 1];
    }

    int base = (blockIdx.x * 8 + warp) * 4;
    for (int n = 0; n < 4; n++) {
        int i = base + n;
        if (i >= Nn) break;
        float di = g_dinv[i];
        float wself = di * di;
        const __half2* hrow = reinterpret_cast<const __half2*>(hw + (size_t)i * Hh);
        float acc[8];
#pragma unroll
        for (int j = 0; j < 4; j++) {
            float2 f = __half22float2(hrow[lane + 32 * j]);
            acc[2 * j] = wself * f.x;
            acc[2 * j + 1] = wself * f.y;
        }
        int e0 = g_rowoff[i], e1 = g_rowoff[i + 1];
        for (int e = e0; e < e1; e++) {
            int s = g_csr_src[e];
            float nr = g_csr_nrm[e];
            const __half2* srow = reinterpret_cast<const __half2*>(hw + (size_t)s * Hh);
#pragma unroll
            for (int j = 0; j < 4; j++) {
                float2 f = __half22float2(srow[lane + 32 * j]);
                acc[2 * j] += nr * f.x;
                acc[2 * j + 1] += nr * f.y;
            }
        }
        __half2* arow = reinterpret_cast<__half2*>(g_agg + (size_t)i * Hh);
#pragma unroll
        for (int j = 0; j < 4; j++) {
            float v0 = acc[2 * j] + cbv[2 * j];
            float v1 = acc[2 * j + 1] + cbv[2 * j + 1];
            arow[lane + 32 * j] = __floats2half2_rn(v0, v1);
            tsum[2 * j] += v0;  tsq[2 * j] += v0 * v0;
            tsum[2 * j + 1] += v1;  tsq[2 * j + 1] += v1 * v1;
        }
    }
#pragma unroll
    for (int j = 0; j < 4; j++) {
        int col = 2 * (lane + 32 * j);
        atomicAdd(&ssum[col], tsum[2 * j]);
        atomicAdd(&ssq[col], tsq[2 * j]);
        atomicAdd(&ssum[col + 1], tsum[2 * j + 1]);
        atomicAdd(&ssq[col + 1], tsq[2 * j + 1]);
    }
    __syncthreads();
    atomicAdd(&g_bsum[layer][threadIdx.x], (double)ssum[threadIdx.x]);
    atomicAdd(&g_bsq[layer][threadIdx.x], (double)ssq[threadIdx.x]);
    __threadfence();
    __syncthreads();

    __shared__ int isLast;
    if (threadIdx.x == 0)
        isLast = (atomicAdd(&g_aggdone[layer], 1) == (int)gridDim.x - 1);
    __syncthreads();
    if (isLast) {
        __threadfence();
        int c = threadIdx.x;
        double m = g_bsum[layer][c] / (double)Nn;
        double v = g_bsq[layer][c] / (double)Nn - m * m;
        g_mean[c] = (float)m;
        g_rstd[c] = (float)(1.0 / sqrt(v + (double)BN_EPS));
        g_bsum[layer][c] = 0.0;
        g_bsq[layer][c] = 0.0;
        if (c == 0) g_aggdone[layer] = 0;
    }
}

// ---------------- BN + ReLU + residual; fp16 agg/xin; a' fp16; mix at output ----------------
__global__ void __launch_bounds__(256)
k_bnapply(const float* __restrict__ gamma, const float* __restrict__ beta,
          int layer, float prevCoef, int writeH)
{
    int idx = blockIdx.x * blockDim.x + threadIdx.x;
    if (idx >= Nn * (Hh / 4)) return;
    int c4 = (idx & 63);
    uint2 araw = reinterpret_cast<const uint2*>(g_agg)[idx];
    float2 a01 = __half22float2(*reinterpret_cast<__half2*>(&araw.x));
    float2 a23 = __half22float2(*reinterpret_cast<__half2*>(&araw.y));
    float4 mn = reinterpret_cast<const float4*>(g_mean)[c4];
    float4 rs = reinterpret_cast<const float4*>(g_rstd)[c4];
    float4 gm = reinterpret_cast<const float4*>(gamma)[c4];
    float4 bt = reinterpret_cast<const float4*>(beta)[c4];

    float4 ap;
    ap.x = fmaxf((a01.x - mn.x) * rs.x * gm.x + bt.x, 0.f);
    ap.y = fmaxf((a01.y - mn.y) * rs.y * gm.y + bt.y, 0.f);
    ap.z = fmaxf((a23.x - mn.z) * rs.z * gm.z + bt.z, 0.f);
    ap.w = fmaxf((a23.y - mn.w) * rs.w * gm.w + bt.w, 0.f);

    __half2* apst = reinterpret_cast<__half2*>(&g_ap[layer][0]);
    apst[idx * 2]     = __floats2half2_rn(ap.x, ap.y);
    apst[idx * 2 + 1] = __floats2half2_rn(ap.z, ap.w);

    if (writeH) {
        uint2 xraw = reinterpret_cast<const uint2*>(g_xin)[idx];
        float2 x01 = __half22float2(*reinterpret_cast<__half2*>(&xraw.x));
        float2 x23 = __half22float2(*reinterpret_cast<__half2*>(&xraw.y));
        uint2 hpak = reinterpret_cast<const uint2*>(g_ahi)[idx];
        uint2 lpak = reinterpret_cast<const uint2*>(g_alo)[idx];
        float2 hp01 = unpack2(hpak.x, lpak.x);
        float2 hp23 = unpack2(hpak.y, lpak.y);

        float4 hn;
        hn.x = ap.x + 0.2f * x01.x + prevCoef * hp01.x;
        hn.y = ap.y + 0.2f * x01.y + prevCoef * hp01.y;
        hn.z = ap.z + 0.2f * x23.x + prevCoef * hp23.x;
        hn.w = ap.w + 0.2f * x23.y + prevCoef * hp23.y;

        uint2 nh, nl;
        split_pair(hn.x, hn.y, nh.x, nl.x);
        split_pair(hn.z, hn.w, nh.y, nl.y);
        reinterpret_cast<uint2*>(g_ahi)[idx] = nh;
        reinterpret_cast<uint2*>(g_alo)[idx] = nl;
    }
}

// ---------------- output: mix reconstruction + logits + log_softmax ----------------
__global__ void __launch_bounds__(256)
k_output(const float* __restrict__ ow, const float* __restrict__ ob, float* __restrict__ out)
{
    __shared__ float sw[Hh * 41];
    __shared__ float sb2[Cc];
    __shared__ float srow[8][48];
    for (int t = threadIdx.x; t < Hh * Cc; t += 256) {
        int k = t / Cc, c = t % Cc;
        sw[k * 41 + c] = ow[t];
    }
    if (threadIdx.x < Cc) sb2[threadIdx.x] = ob[threadIdx.x];
    __syncthreads();

    float cm[Ll], xc;
#pragma unroll
    for (int l = 0; l < Ll; l++) cm[l] = g_cm[l];
    xc = g_xc;

    int warp = threadIdx.x >> 5, lane = threadIdx.x & 31;
    for (int row = blockIdx.x * 8 + warp; row < Nn; row += gridDim.x * 8) {
        float m[8];
#pragma unroll
        for (int j = 0; j < 8; j++) {
            size_t o = (size_t)row * Hh + lane + 32 * j;
            float v = xc * __half2float(g_xin[o]);
#pragma unroll
            for (int l = 0; l < Ll; l++)
                v += cm[l] * __half2float(g_ap[l][o]);
            m[j] = v;
        }
        for (int c = 0; c < Cc; c++) {
            float p = 0.f;
#pragma unroll
            for (int j = 0; j < 8; j++) p += m[j] * sw[(lane + 32 * j) * 41 + c];
#pragma unroll
            for (int off = 16; off > 0; off >>= 1) p += __shfl_xor_sync(0xffffffffu, p, off);
            if (lane == 0) srow[warp][c] = p + sb2[c];
        }
        __syncwarp();
        float v1 = srow[warp][lane];
        float v2 = (lane < 8) ? srow[warp][32 + lane] : -1e30f;
        float mx = fmaxf(v1, v2);
#pragma unroll
        for (int off = 16; off > 0; off >>= 1) mx = fmaxf(mx, __shfl_xor_sync(0xffffffffu, mx, off));
        float s = expf(v1 - mx) + ((lane < 8) ? expf(v2 - mx) : 0.f);
#pragma unroll
        for (int off = 16; off > 0; off >>= 1) s += __shfl_xor_sync(0xffffffffu, s, off);
        float lse = mx + logf(s);
        out[(size_t)row * Cc + lane] = v1 - lse;
        if (lane < 8) out[(size_t)row * Cc + 32 + lane] = v2 - lse;
        __syncwarp();
    }
}

// ---------------- launch ----------------
extern "C" void kernel_launch(void* const* d_in, const int* in_sizes, int n_in,
                              void* d_out, int out_size)
{
    const float* x      = (const float*)d_in[0];
    const int*   ei     = (const int*)d_in[1];
    const float* w_in   = (const float*)d_in[2];
    const float* b_in   = (const float*)d_in[3];
    const float* conv_w = (const float*)d_in[4];
    const float* conv_b = (const float*)d_in[5];
    const float* bn_g   = (const float*)d_in[6];
    const float* bn_b   = (const float*)d_in[7];
    const float* out_w  = (const float*)d_in[8];
    const float* out_b  = (const float*)d_in[9];
    const float* res_w  = (const float*)d_in[10];
    float* out = (float*)d_out;

    (void)in_sizes; (void)n_in; (void)out_size;

    static cudaStream_t s2 = nullptr;
    static cudaEvent_t evFork = nullptr, evJoin = nullptr;
    if (!s2) {
        cudaStreamCreate(&s2);
        cudaEventCreateWithFlags(&evFork, cudaEventDisableTiming);
        cudaEventCreateWithFlags(&evJoin, cudaEventDisableTiming);
        cudaFuncSetAttribute(k_gemm, cudaFuncAttributeMaxDynamicSharedMemorySize, SMEM_DYN);
    }

    __half *p_hw, *p_xin;
    __nv_bfloat16 *p_ahi, *p_alo, *p_xhi, *p_xlo, *p_bthi, *p_btlo;
    cudaGetSymbolAddress((void**)&p_hw, g_hw);
    cudaGetSymbolAddress((void**)&p_xin, g_xin);
    cudaGetSymbolAddress((void**)&p_ahi, g_ahi);
    cudaGetSymbolAddress((void**)&p_alo, g_alo);
    cudaGetSymbolAddress((void**)&p_xhi, g_xhi);
    cudaGetSymbolAddress((void**)&p_xlo, g_xlo);
    cudaGetSymbolAddress((void**)&p_bthi, g_bthi);
    cudaGetSymbolAddress((void**)&p_btlo, g_btlo);

    dim3 gg(4, (Nn + 127) / 128);

    cudaEventRecord(evFork, 0);
    cudaStreamWaitEvent(s2, evFork, 0);

    k_split_x<<<(Nn * FIN + 255) / 256, 256>>>(x);
    k_split_w<<<(Hh * FIN + 255) / 256, 256>>>(w_in, p_bthi, p_btlo, FIN);
    k_split_wconv<<<(Ll * Hh * Hh + 255) / 256, 256>>>(conv_w);
    k_gemm<<<gg, 256, SMEM_DYN>>>(p_xhi, p_xlo, p_bthi + BT_IN_OFF, p_btlo + BT_IN_OFF,
                                  b_in, p_xin, p_ahi, p_alo, Nn, FIN);

    k_softmax_w<<<1, 1, 0, s2>>>(res_w);
    k_zero_deg<<<(Nn + 255) / 256, 256, 0, s2>>>();
    k_count<<<(Ee + 255) / 256, 256, 0, s2>>>(ei);
    k_dinv<<<(Nn + 255) / 256, 256, 0, s2>>>();
    int nsb = (Nn + 511) / 512;
    k_scan1<<<nsb, 512, 0, s2>>>();
    k_scan2<<<1, 1, 0, s2>>>(nsb);
    k_scan3<<<nsb, 512, 0, s2>>>();
    k_scatter<<<(Ee + 255) / 256, 256, 0, s2>>>(ei);
    cudaEventRecord(evJoin, s2);
    cudaStreamWaitEvent(0, evJoin, 0);

    for (int l = 0; l < Ll; l++) {
        k_gemm<<<gg, 256, SMEM_DYN>>>(p_ahi, p_alo,
                                      p_bthi + BT_CONV_OFF + (size_t)l * Hh * Hh,
                                      p_btlo + BT_CONV_OFF + (size_t)l * Hh * Hh,
                                      nullptr, p_hw, nullptr, nullptr, Nn, Hh);
        k_aggregate<<<(Nn + 31) / 32, 256>>>(p_hw, conv_b + (size_t)l * Hh, l);
        k_bnapply<<<(Nn * (Hh / 4) + 255) / 256, 256>>>(bn_g + (size_t)l * Hh, bn_b + (size_t)l * Hh,
                                                        l, (l == 0) ? 0.0f : 0.7f,
                                                        (l < Ll - 1) ? 1 : 0);
    }

    k_output<<<1563, 256>>>(out_w, out_b, out);
}

// round 11
// speedup vs baseline: 2.3515x; 1.3067x over previous
#include <cuda_runtime.h>
#include <cuda_bf16.h>
#include <cuda_fp16.h>
#include <math.h>
#include <stdint.h>

#define Nn 100000
#define Ee 300000
#define Hh 256
#define Cc 40
#define Ll 6
#define FIN 128
#define BN_EPS 1e-5f

// ---------------- device scratch ----------------
__device__ __half g_hw[Nn * Hh];           // h @ W (fp16)
__device__ __half g_agg[Nn * Hh];          // aggregated messages (fp16)
__device__ __half g_xin[Nn * Hh];          // x_input (fp16)
__device__ __half g_ap[Ll][Nn * Hh];       // a' = relu(bn) per layer (fp16)
__device__ __half g_a[Nn * Hh];            // current h (fp16) — GEMM A + residual state
__device__ __half g_xq[Nn * FIN];          // fp16 x (input GEMM A)
#define BT_IN_OFF 0
#define BT_CONV_OFF (Hh * FIN)
__device__ __half g_bt[Hh * FIN + Ll * Hh * Hh];   // transposed fp16 weights
__device__ float g_dinv[Nn];
__device__ int   g_deg[Nn];
__device__ int   g_cursor[Nn];
__device__ int   g_rowoff[Nn + 1];
__device__ int   g_csr_src[Ee];
__device__ float g_csr_nrm[Ee];
__device__ double g_bsum[Ll][Hh];
__device__ double g_bsq[Ll][Hh];
__device__ int    g_aggdone[Ll];
__device__ float g_mean[Hh];
__device__ float g_rstd[Hh];
__device__ float g_cm[Ll];
__device__ float g_xc;
__device__ int   g_bsums_scan[256];

// ---------------- helpers ----------------
__device__ __forceinline__ uint32_t smem_u32(const void* p) {
    uint32_t a;
    asm("{ .reg .u64 t; cvta.to.shared.u64 t, %1; cvt.u32.u64 %0, t; }" : "=r"(a) : "l"(p));
    return a;
}
__device__ __forceinline__ void cpasync16(uint32_t dst, const void* src, int szbytes) {
    asm volatile("cp.async.cg.shared.global [%0], [%1], 16, %2;"
                 :: "r"(dst), "l"(src), "r"(szbytes) : "memory");
}
#define CP_COMMIT() asm volatile("cp.async.commit_group;" ::: "memory")
#define CP_WAIT(n)  asm volatile("cp.async.wait_group %0;" :: "n"(n) : "memory")

__device__ __forceinline__ void ldsm4(uint32_t& r0, uint32_t& r1, uint32_t& r2, uint32_t& r3, uint32_t addr) {
    asm volatile("ldmatrix.sync.aligned.m8n8.x4.shared.b16 {%0,%1,%2,%3}, [%4];"
                 : "=r"(r0), "=r"(r1), "=r"(r2), "=r"(r3) : "r"(addr));
}
__device__ __forceinline__ void mma_f16(float c[4], const uint32_t a[4], uint32_t b0, uint32_t b1) {
    asm volatile("mma.sync.aligned.m16n8k16.row.col.f32.f16.f16.f32 "
                 "{%0,%1,%2,%3}, {%4,%5,%6,%7}, {%8,%9}, {%0,%1,%2,%3};"
                 : "+f"(c[0]), "+f"(c[1]), "+f"(c[2]), "+f"(c[3])
                 : "r"(a[0]), "r"(a[1]), "r"(a[2]), "r"(a[3]), "r"(b0), "r"(b1));
}

// ---------------- fp16 GEMM, 3 CTAs/SM ----------------
// CTA: BM=128, BN=64 (gridDim.x = 4 column blocks), BK=32, 256 threads (8 warps 4m x 2n),
// warp tile 32x32. 3-stage cp.async pipeline; stage = A 8K | B 4K = 12KB.
#define ST_SZ   12288
#define SM_B    8192
#define SMEM_DYN (3 * ST_SZ)

__global__ void __launch_bounds__(256, 3)
k_gemm(const __half* __restrict__ A, const __half* __restrict__ B,
       const float* __restrict__ bias, __half* __restrict__ C,
       __half* __restrict__ C2, int M, int K)
{
    extern __shared__ char smem[];
    uint32_t sb = smem_u32(smem);
    int tid = threadIdx.x;
    int lane = tid & 31, wid = tid >> 5;
    int wm = wid >> 1, wn = wid & 1;
    int row0 = blockIdx.y * 128;
    int nb0 = blockIdx.x * 64;
    int nc = K >> 5;

    const char* AC = (const char*)A;
    const char* BC = (const char*)B;

    float c[2][4][4];
#pragma unroll
    for (int mt = 0; mt < 2; mt++)
#pragma unroll
        for (int nt = 0; nt < 4; nt++)
#pragma unroll
            for (int j = 0; j < 4; j++) c[mt][nt][j] = 0.f;

    auto stage_load = [&](int s, int kc) {
        uint32_t so = sb + s * ST_SZ;
        // A: 128 rows x 32 k (64B rows, 4 x 16B chunks)
#pragma unroll
        for (int j = 0; j < 2; j++) {
            int flat = tid + j * 256;
            int row = flat >> 2, cq = flat & 3;
            int grow = row0 + row;
            int sz = (grow < M) ? 16 : 0;
            int gc = (grow < M) ? grow : (M - 1);
            size_t srcoff = ((size_t)gc * K + kc * 32 + cq * 8) * 2;
            uint32_t dst = so + row * 64 + ((cq ^ ((row >> 1) & 3)) << 4);
            cpasync16(dst, AC + srcoff, sz);
        }
        // B: 64 n-rows x 32 k
        {
            int n = tid >> 2, cq = tid & 3;
            size_t srcoff = ((size_t)(nb0 + n) * K + kc * 32 + cq * 8) * 2;
            uint32_t dst = so + SM_B + n * 64 + ((cq ^ ((n >> 1) & 3)) << 4);
            cpasync16(dst, BC + srcoff, 16);
        }
    };

    stage_load(0, 0);
    CP_COMMIT();
    if (nc > 1) { stage_load(1, 1); CP_COMMIT(); }

    for (int kc = 0; kc < nc; kc++) {
        if (kc + 2 < nc) {
            stage_load((kc + 2) % 3, kc + 2);
            CP_COMMIT();
            CP_WAIT(2);
        } else {
            CP_WAIT(0);
        }
        __syncthreads();

        uint32_t so = sb + (kc % 3) * ST_SZ;
#pragma unroll
        for (int ks = 0; ks < 2; ks++) {
            uint32_t ah[2][4];
#pragma unroll
            for (int mt = 0; mt < 2; mt++) {
                int ml = wm * 32 + mt * 16 + (lane & 7) + ((lane >> 3) & 1) * 8;
                int ck = 2 * ks + (lane >> 4);
                uint32_t ab = so + ml * 64 + ((ck ^ ((ml >> 1) & 3)) << 4);
                ldsm4(ah[mt][0], ah[mt][1], ah[mt][2], ah[mt][3], ab);
            }
            uint32_t bh[2][4];
#pragma unroll
            for (int j = 0; j < 2; j++) {
                int nl = wn * 32 + j * 16 + (lane & 7) + ((lane >> 4) << 3);
                int ck = 2 * ks + ((lane >> 3) & 1);
                uint32_t bb = so + SM_B + nl * 64 + ((ck ^ ((nl >> 1) & 3)) << 4);
                ldsm4(bh[j][0], bh[j][1], bh[j][2], bh[j][3], bb);
            }
#pragma unroll
            for (int j = 0; j < 2; j++) {
                int nb = j * 2;
#pragma unroll
                for (int mt = 0; mt < 2; mt++) {
                    mma_f16(c[mt][nb + 0], ah[mt], bh[j][0], bh[j][1]);
                    mma_f16(c[mt][nb + 1], ah[mt], bh[j][2], bh[j][3]);
                }
            }
        }
        __syncthreads();
    }

#pragma unroll
    for (int mt = 0; mt < 2; mt++) {
        int r = row0 + wm * 32 + mt * 16 + (lane >> 2);
#pragma unroll
        for (int nt = 0; nt < 4; nt++) {
            int col = nb0 + wn * 32 + nt * 8 + ((lane & 3) << 1);
            float v0 = c[mt][nt][0], v1 = c[mt][nt][1];
            float v2 = c[mt][nt][2], v3 = c[mt][nt][3];
            if (bias) {
                float b0 = bias[col], b1 = bias[col + 1];
                v0 += b0; v1 += b1; v2 += b0; v3 += b1;
            }
            if (r < M) {
                size_t o = (size_t)r * Hh + col;
                __half2 hv = __floats2half2_rn(v0, v1);
                *reinterpret_cast<__half2*>(&C[o]) = hv;
                if (C2) *reinterpret_cast<__half2*>(&C2[o]) = hv;
            }
            if (r + 8 < M) {
                size_t o = (size_t)(r + 8) * Hh + col;
                __half2 hv = __floats2half2_rn(v2, v3);
                *reinterpret_cast<__half2*>(&C[o]) = hv;
                if (C2) *reinterpret_cast<__half2*>(&C2[o]) = hv;
            }
        }
    }
}

// ---------------- splits (fp16 quantization) ----------------
__global__ void k_split_w(const float* __restrict__ W, __half* __restrict__ dst, int K)
{
    int idx = blockIdx.x * 256 + threadIdx.x;
    if (idx >= Hh * K) return;
    int n = idx / K, k = idx - n * K;
    dst[idx] = __float2half(W[(size_t)k * Hh + n]);
}

__global__ void k_split_wconv(const float* __restrict__ W)
{
    int idx = blockIdx.x * 256 + threadIdx.x;
    if (idx >= Ll * Hh * Hh) return;
    int l = idx >> 16;
    int r = idx & 65535;
    int n = r >> 8, k = r & 255;
    g_bt[BT_CONV_OFF + idx] = __float2half(W[(size_t)l * Hh * Hh + (size_t)k * Hh + n]);
}

__global__ void k_split_x(const float* __restrict__ x)
{
    int idx = blockIdx.x * 256 + threadIdx.x;
    if (idx >= Nn * FIN) return;
    g_xq[idx] = __float2half(x[idx]);
}

// ---------------- setup kernels ----------------
__global__ void k_zero_deg() {
    int i = blockIdx.x * blockDim.x + threadIdx.x;
    if (i < Nn) { g_deg[i] = 0; g_cursor[i] = 0; }
}
__global__ void k_count(const int* __restrict__ ei) {
    int e = blockIdx.x * blockDim.x + threadIdx.x;
    if (e < Ee) atomicAdd(&g_deg[ei[Ee + e]], 1);
}
__global__ void k_dinv() {
    int i = blockIdx.x * blockDim.x + threadIdx.x;
    if (i < Nn) g_dinv[i] = rsqrtf((float)(g_deg[i] + 1));
}
__global__ void k_scan1() {
    __shared__ int s[512];
    int i = blockIdx.x * 512 + threadIdx.x;
    int v = (i < Nn) ? g_deg[i] : 0;
    s[threadIdx.x] = v;
    __syncthreads();
    int x = v;
#pragma unroll
    for (int off = 1; off < 512; off <<= 1) {
        int t = (threadIdx.x >= off) ? s[threadIdx.x - off] : 0;
        __syncthreads();
        x += t;
        s[threadIdx.x] = x;
        __syncthreads();
    }
    if (i < Nn) g_rowoff[i] = x - v;
    if (threadIdx.x == 511) g_bsums_scan[blockIdx.x] = x;
}
__global__ void k_scan2(int nb) {
    int acc = 0;
    for (int b = 0; b < nb; b++) { int t = g_bsums_scan[b]; g_bsums_scan[b] = acc; acc += t; }
    g_rowoff[Nn] = acc;
}
__global__ void k_scan3() {
    int i = blockIdx.x * 512 + threadIdx.x;
    if (i < Nn) g_rowoff[i] += g_bsums_scan[blockIdx.x];
}
__global__ void k_scatter(const int* __restrict__ ei) {
    int e = blockIdx.x * blockDim.x + threadIdx.x;
    if (e < Ee) {
        int s = ei[e];
        int d = ei[Ee + e];
        int pos = g_rowoff[d] + atomicAdd(&g_cursor[d], 1);
        g_csr_src[pos] = s;
        g_csr_nrm[pos] = g_dinv[s] * g_dinv[d];
    }
}
__global__ void k_softmax_w(const float* __restrict__ rw) {
    float mx = -1e30f;
    for (int l = 0; l < Ll; l++) mx = fmaxf(mx, rw[l]);
    float s = 0.f;
    float w[Ll];
    for (int l = 0; l < Ll; l++) { w[l] = expf(rw[l] - mx); s += w[l]; }
    for (int l = 0; l < Ll; l++) w[l] /= s;
    float csum = 0.f;
    for (int m = 0; m < Ll; m++) {
        float c = 0.f, p = 1.f;
        for (int l = m; l < Ll; l++) { c += w[l] * p; p *= 0.7f; }
        g_cm[m] = c;
        csum += c;
    }
    g_xc = 0.2f * csum;
}

// ---------------- aggregation (fp16 hw) + fused BN stats + last-block finalize ----------------
__global__ void __launch_bounds__(256)
k_aggregate(const __half* __restrict__ hw, const float* __restrict__ cb, int layer)
{
    __shared__ float ssum[Hh], ssq[Hh];
    ssum[threadIdx.x] = 0.f;
    ssq[threadIdx.x] = 0.f;
    __syncthreads();

    int warp = threadIdx.x >> 5, lane = threadIdx.x & 31;
    float tsum[8], tsq[8];
#pragma unroll
    for (int k = 0; k < 8; k++) { tsum[k] = 0.f; tsq[k] = 0.f; }

    float cbv[8];
#pragma unroll
    for (int j = 0; j < 4; j++) {
        int col = 2 * (lane + 32 * j);
        cbv[2 * j] = cb[col];
        cbv[2 * j + 1] = cb[col + 1];
    }

    int base = (blockIdx.x * 8 + warp) * 4;
    for (int n = 0; n < 4; n++) {
        int i = base + n;
        if (i >= Nn) break;
        float di = g_dinv[i];
        float wself = di * di;
        const __half2* hrow = reinterpret_cast<const __half2*>(hw + (size_t)i * Hh);
        float acc[8];
#pragma unroll
        for (int j = 0; j < 4; j++) {
            float2 f = __half22float2(hrow[lane + 32 * j]);
            acc[2 * j] = wself * f.x;
            acc[2 * j + 1] = wself * f.y;
        }
        int e0 = g_rowoff[i], e1 = g_rowoff[i + 1];
        for (int e = e0; e < e1; e++) {
            int s = g_csr_src[e];
            float nr = g_csr_nrm[e];
            const __half2* srow = reinterpret_cast<const __half2*>(hw + (size_t)s * Hh);
#pragma unroll
            for (int j = 0; j < 4; j++) {
                float2 f = __half22float2(srow[lane + 32 * j]);
                acc[2 * j] += nr * f.x;
                acc[2 * j + 1] += nr * f.y;
            }
        }
        __half2* arow = reinterpret_cast<__half2*>(g_agg + (size_t)i * Hh);
#pragma unroll
        for (int j = 0; j < 4; j++) {
            float v0 = acc[2 * j] + cbv[2 * j];
            float v1 = acc[2 * j + 1] + cbv[2 * j + 1];
            arow[lane + 32 * j] = __floats2half2_rn(v0, v1);
            tsum[2 * j] += v0;  tsq[2 * j] += v0 * v0;
            tsum[2 * j + 1] += v1;  tsq[2 * j + 1] += v1 * v1;
        }
    }
#pragma unroll
    for (int j = 0; j < 4; j++) {
        int col = 2 * (lane + 32 * j);
        atomicAdd(&ssum[col], tsum[2 * j]);
        atomicAdd(&ssq[col], tsq[2 * j]);
        atomicAdd(&ssum[col + 1], tsum[2 * j + 1]);
        atomicAdd(&ssq[col + 1], tsq[2 * j + 1]);
    }
    __syncthreads();
    atomicAdd(&g_bsum[layer][threadIdx.x], (double)ssum[threadIdx.x]);
    atomicAdd(&g_bsq[layer][threadIdx.x], (double)ssq[threadIdx.x]);
    __threadfence();
    __syncthreads();

    __shared__ int isLast;
    if (threadIdx.x == 0)
        isLast = (atomicAdd(&g_aggdone[layer], 1) == (int)gridDim.x - 1);
    __syncthreads();
    if (isLast) {
        __threadfence();
        int c = threadIdx.x;
        double m = g_bsum[layer][c] / (double)Nn;
        double v = g_bsq[layer][c] / (double)Nn - m * m;
        g_mean[c] = (float)m;
        g_rstd[c] = (float)(1.0 / sqrt(v + (double)BN_EPS));
        g_bsum[layer][c] = 0.0;
        g_bsq[layer][c] = 0.0;
        if (c == 0) g_aggdone[layer] = 0;
    }
}

// ---------------- BN + ReLU + residual; all fp16 state ----------------
__global__ void __launch_bounds__(256)
k_bnapply(const float* __restrict__ gamma, const float* __restrict__ beta,
          int layer, float prevCoef, int writeH)
{
    int idx = blockIdx.x * blockDim.x + threadIdx.x;
    if (idx >= Nn * (Hh / 4)) return;
    int c4 = (idx & 63);
    uint2 araw = reinterpret_cast<const uint2*>(g_agg)[idx];
    float2 a01 = __half22float2(*reinterpret_cast<__half2*>(&araw.x));
    float2 a23 = __half22float2(*reinterpret_cast<__half2*>(&araw.y));
    float4 mn = reinterpret_cast<const float4*>(g_mean)[c4];
    float4 rs = reinterpret_cast<const float4*>(g_rstd)[c4];
    float4 gm = reinterpret_cast<const float4*>(gamma)[c4];
    float4 bt = reinterpret_cast<const float4*>(beta)[c4];

    float4 ap;
    ap.x = fmaxf((a01.x - mn.x) * rs.x * gm.x + bt.x, 0.f);
    ap.y = fmaxf((a01.y - mn.y) * rs.y * gm.y + bt.y, 0.f);
    ap.z = fmaxf((a23.x - mn.z) * rs.z * gm.z + bt.z, 0.f);
    ap.w = fmaxf((a23.y - mn.w) * rs.w * gm.w + bt.w, 0.f);

    __half2* apst = reinterpret_cast<__half2*>(&g_ap[layer][0]);
    apst[idx * 2]     = __floats2half2_rn(ap.x, ap.y);
    apst[idx * 2 + 1] = __floats2half2_rn(ap.z, ap.w);

    if (writeH) {
        uint2 xraw = reinterpret_cast<const uint2*>(g_xin)[idx];
        float2 x01 = __half22float2(*reinterpret_cast<__half2*>(&xraw.x));
        float2 x23 = __half22float2(*reinterpret_cast<__half2*>(&xraw.y));
        uint2 hraw = reinterpret_cast<const uint2*>(g_a)[idx];
        float2 h01 = __half22float2(*reinterpret_cast<__half2*>(&hraw.x));
        float2 h23 = __half22float2(*reinterpret_cast<__half2*>(&hraw.y));

        float4 hn;
        hn.x = ap.x + 0.2f * x01.x + prevCoef * h01.x;
        hn.y = ap.y + 0.2f * x01.y + prevCoef * h01.y;
        hn.z = ap.z + 0.2f * x23.x + prevCoef * h23.x;
        hn.w = ap.w + 0.2f * x23.y + prevCoef * h23.y;

        uint2 nh;
        *reinterpret_cast<__half2*>(&nh.x) = __floats2half2_rn(hn.x, hn.y);
        *reinterpret_cast<__half2*>(&nh.y) = __floats2half2_rn(hn.z, hn.w);
        reinterpret_cast<uint2*>(g_a)[idx] = nh;
    }
}

// ---------------- output: mix reconstruction + logits + log_softmax ----------------
__global__ void __launch_bounds__(256)
k_output(const float* __restrict__ ow, const float* __restrict__ ob, float* __restrict__ out)
{
    __shared__ float sw[Hh * 41];
    __shared__ float sb2[Cc];
    __shared__ float srow[8][48];
    for (int t = threadIdx.x; t < Hh * Cc; t += 256) {
        int k = t / Cc, c = t % Cc;
        sw[k * 41 + c] = ow[t];
    }
    if (threadIdx.x < Cc) sb2[threadIdx.x] = ob[threadIdx.x];
    __syncthreads();

    float cm[Ll], xc;
#pragma unroll
    for (int l = 0; l < Ll; l++) cm[l] = g_cm[l];
    xc = g_xc;

    int warp = threadIdx.x >> 5, lane = threadIdx.x & 31;
    for (int row = blockIdx.x * 8 + warp; row < Nn; row += gridDim.x * 8) {
        float m[8];
#pragma unroll
        for (int j = 0; j < 8; j++) {
            size_t o = (size_t)row * Hh + lane + 32 * j;
            float v = xc * __half2float(g_xin[o]);
#pragma unroll
            for (int l = 0; l < Ll; l++)
                v += cm[l] * __half2float(g_ap[l][o]);
            m[j] = v;
        }
        for (int c = 0; c < Cc; c++) {
            float p = 0.f;
#pragma unroll
            for (int j = 0; j < 8; j++) p += m[j] * sw[(lane + 32 * j) * 41 + c];
#pragma unroll
            for (int off = 16; off > 0; off >>= 1) p += __shfl_xor_sync(0xffffffffu, p, off);
            if (lane == 0) srow[warp][c] = p + sb2[c];
        }
        __syncwarp();
        float v1 = srow[warp][lane];
        float v2 = (lane < 8) ? srow[warp][32 + lane] : -1e30f;
        float mx = fmaxf(v1, v2);
#pragma unroll
        for (int off = 16; off > 0; off >>= 1) mx = fmaxf(mx, __shfl_xor_sync(0xffffffffu, mx, off));
        float s = expf(v1 - mx) + ((lane < 8) ? expf(v2 - mx) : 0.f);
#pragma unroll
        for (int off = 16; off > 0; off >>= 1) s += __shfl_xor_sync(0xffffffffu, s, off);
        float lse = mx + logf(s);
        out[(size_t)row * Cc + lane] = v1 - lse;
        if (lane < 8) out[(size_t)row * Cc + 32 + lane] = v2 - lse;
        __syncwarp();
    }
}

// ---------------- launch ----------------
extern "C" void kernel_launch(void* const* d_in, const int* in_sizes, int n_in,
                              void* d_out, int out_size)
{
    const float* x      = (const float*)d_in[0];
    const int*   ei     = (const int*)d_in[1];
    const float* w_in   = (const float*)d_in[2];
    const float* b_in   = (const float*)d_in[3];
    const float* conv_w = (const float*)d_in[4];
    const float* conv_b = (const float*)d_in[5];
    const float* bn_g   = (const float*)d_in[6];
    const float* bn_b   = (const float*)d_in[7];
    const float* out_w  = (const float*)d_in[8];
    const float* out_b  = (const float*)d_in[9];
    const float* res_w  = (const float*)d_in[10];
    float* out = (float*)d_out;

    (void)in_sizes; (void)n_in; (void)out_size;

    static cudaStream_t s2 = nullptr;
    static cudaEvent_t evFork = nullptr, evJoin = nullptr;
    if (!s2) {
        cudaStreamCreate(&s2);
        cudaEventCreateWithFlags(&evFork, cudaEventDisableTiming);
        cudaEventCreateWithFlags(&evJoin, cudaEventDisableTiming);
        cudaFuncSetAttribute(k_gemm, cudaFuncAttributeMaxDynamicSharedMemorySize, SMEM_DYN);
    }

    __half *p_hw, *p_xin, *p_a, *p_xq, *p_bt;
    cudaGetSymbolAddress((void**)&p_hw, g_hw);
    cudaGetSymbolAddress((void**)&p_xin, g_xin);
    cudaGetSymbolAddress((void**)&p_a, g_a);
    cudaGetSymbolAddress((void**)&p_xq, g_xq);
    cudaGetSymbolAddress((void**)&p_bt, g_bt);

    dim3 gg(4, (Nn + 127) / 128);

    cudaEventRecord(evFork, 0);
    cudaStreamWaitEvent(s2, evFork, 0);

    k_split_x<<<(Nn * FIN + 255) / 256, 256>>>(x);
    k_split_w<<<(Hh * FIN + 255) / 256, 256>>>(w_in, p_bt + BT_IN_OFF, FIN);
    k_split_wconv<<<(Ll * Hh * Hh + 255) / 256, 256>>>(conv_w);
    k_gemm<<<gg, 256, SMEM_DYN>>>(p_xq, p_bt + BT_IN_OFF, b_in, p_xin, p_a, Nn, FIN);

    k_softmax_w<<<1, 1, 0, s2>>>(res_w);
    k_zero_deg<<<(Nn + 255) / 256, 256, 0, s2>>>();
    k_count<<<(Ee + 255) / 256, 256, 0, s2>>>(ei);
    k_dinv<<<(Nn + 255) / 256, 256, 0, s2>>>();
    int nsb = (Nn + 511) / 512;
    k_scan1<<<nsb, 512, 0, s2>>>();
    k_scan2<<<1, 1, 0, s2>>>(nsb);
    k_scan3<<<nsb, 512, 0, s2>>>();
    k_scatter<<<(Ee + 255) / 256, 256, 0, s2>>>(ei);
    cudaEventRecord(evJoin, s2);
    cudaStreamWaitEvent(0, evJoin, 0);

    for (int l = 0; l < Ll; l++) {
        k_gemm<<<gg, 256, SMEM_DYN>>>(p_a, p_bt + BT_CONV_OFF + (size_t)l * Hh * Hh,
                                      nullptr, p_hw, nullptr, Nn, Hh);
        k_aggregate<<<(Nn + 31) / 32, 256>>>(p_hw, conv_b + (size_t)l * Hh, l);
        k_bnapply<<<(Nn * (Hh / 4) + 255) / 256, 256>>>(bn_g + (size_t)l * Hh, bn_b + (size_t)l * Hh,
                                                        l, (l == 0) ? 0.0f : 0.7f,
                                                        (l < Ll - 1) ? 1 : 0);
    }

    k_output<<<1563, 256>>>(out_w, out_b, out);
}